// round 1
// baseline (speedup 1.0000x reference)
#include <cuda_runtime.h>
#include <math.h>

#define Nn   8192
#define Din  512
#define Dout 256
#define Ne   131072
#define AH   16

// ---------------- scratch (static device allocations; no cudaMalloc) ----------------
static __device__ float g_Y[Nn*Din];       // xW buffer
static __device__ float g_P[Nn*Din];       // scatter accumulator
static __device__ float g_H1[Nn*Din];      // relu(layer1)
static __device__ float g_Hadj[Nn*Dout];
static __device__ float g_Hx[Nn*Dout];
static __device__ float g_Hf[Nn*Dout];
static __device__ float g_Za[Nn*Dout];
static __device__ float g_Zx[Nn*Dout];
static __device__ float g_Zf[Nn*Dout];
static __device__ float g_deg[4*Nn];       // outA,inA,outX,inX
static __device__ float g_nrm[4*Nn];       // nsA,ndA,nsX,ndX
static __device__ float g_dcraw[Din*Dout];
static __device__ float g_Cn[Din*Dout];
static __device__ float g_colsum[Din];
static __device__ float g_sum[4*Nn];
static __device__ float g_pos[4*Nn];
static __device__ float g_loss[4];

// ---------------- small kernels ----------------
__global__ void k_degree(const int* __restrict__ src, const int* __restrict__ dst,
                         float* degO, float* degI) {
    int t = blockIdx.x * 256 + threadIdx.x;
    if (t < Ne) { atomicAdd(degO + src[t], 1.f); atomicAdd(degI + dst[t], 1.f); }
}

__global__ void k_norm() {
    int t = blockIdx.x * 256 + threadIdx.x;
    if (t < 4 * Nn) { float d = g_deg[t]; g_nrm[t] = (d > 0.f) ? rsqrtf(d) : 0.f; }
}

// scatter: P[dst] += Y[src] * ns[src], vectorized over feature dim (C4 = C/4)
__global__ void k_scatter(const int* __restrict__ src, const int* __restrict__ dst,
                          const float* __restrict__ Y, const float* __restrict__ ns,
                          float* __restrict__ P, int C4) {
    int idx = blockIdx.x * 256 + threadIdx.x;
    if (idx >= Ne * C4) return;
    int e = idx / C4, c = idx % C4;
    int s = src[e], d = dst[e];
    float4 v = ((const float4*)Y)[(size_t)s * C4 + c];
    float sc = ns[s];
    float* p = P + ((size_t)d * C4 + c) * 4;
    atomicAdd(p + 0, v.x * sc); atomicAdd(p + 1, v.y * sc);
    atomicAdd(p + 2, v.z * sc); atomicAdd(p + 3, v.w * sc);
}

// H = (relu?)(P * nd[row] + bias[col])
__global__ void k_post(const float* __restrict__ P, const float* __restrict__ nd,
                       const float* __restrict__ bias, float* __restrict__ H,
                       int C, int relu) {
    int idx = blockIdx.x * 256 + threadIdx.x;
    int i = idx / C, c = idx % C;
    float v = P[idx] * nd[i] + bias[c];
    if (relu) v = fmaxf(v, 0.f);
    H[idx] = v;
}

// ---------------- generic fp32 GEMM: C = A[MxK] @ B[KxN], all row-major ----------------
__global__ __launch_bounds__(256, 2)
void k_gemm_nn(const float* __restrict__ A, const float* __restrict__ B,
               float* __restrict__ C, int M, int Nc, int K) {
    __shared__ float As[32][132];
    __shared__ float Bs[32][132];
    int tid = threadIdx.x, tx = tid & 15, ty = tid >> 4;
    int r0 = blockIdx.x * 128, c0 = blockIdx.y * 128;
    int ty8 = ty * 8, tx8 = tx * 8;
    float acc[8][8] = {};
    for (int k0 = 0; k0 < K; k0 += 32) {
        for (int t = tid; t < 4096; t += 256) {
            int k = t & 31, m = t >> 5;
            As[k][m] = A[(size_t)(r0 + m) * K + k0 + k];
        }
        for (int t = tid; t < 4096; t += 256) {
            int n = t & 127, k = t >> 7;
            Bs[k][n] = B[(size_t)(k0 + k) * Nc + c0 + n];
        }
        __syncthreads();
        #pragma unroll 8
        for (int k = 0; k < 32; k++) {
            float a[8], b[8];
            #pragma unroll
            for (int i = 0; i < 8; i++) a[i] = As[k][ty8 + i];
            #pragma unroll
            for (int j = 0; j < 8; j++) b[j] = Bs[k][tx8 + j];
            #pragma unroll
            for (int i = 0; i < 8; i++)
                #pragma unroll
                for (int j = 0; j < 8; j++) acc[i][j] = fmaf(a[i], b[j], acc[i][j]);
        }
        __syncthreads();
    }
    for (int i = 0; i < 8; i++) {
        size_t r = (size_t)(r0 + ty8 + i) * Nc + c0 + tx8;
        #pragma unroll
        for (int j = 0; j < 8; j++) C[r + j] = acc[i][j];
    }
}

// C[MxN] += A^T@B over a K-slice: A is [K x M] row-major (lda=M), B is [K x N]
__global__ __launch_bounds__(256, 2)
void k_atb(const float* __restrict__ A, const float* __restrict__ B,
           float* __restrict__ C, int M, int Nc, int kPerSlice) {
    __shared__ float As[32][132];
    __shared__ float Bs[32][132];
    int tid = threadIdx.x, tx = tid & 15, ty = tid >> 4;
    int r0 = blockIdx.x * 128, c0 = blockIdx.y * 128;
    int kb = blockIdx.z * kPerSlice;
    int ty8 = ty * 8, tx8 = tx * 8;
    float acc[8][8] = {};
    for (int k0 = kb; k0 < kb + kPerSlice; k0 += 32) {
        for (int t = tid; t < 4096; t += 256) {
            int m = t & 127, k = t >> 7;
            As[k][m] = A[(size_t)(k0 + k) * M + r0 + m];
        }
        for (int t = tid; t < 4096; t += 256) {
            int n = t & 127, k = t >> 7;
            Bs[k][n] = B[(size_t)(k0 + k) * Nc + c0 + n];
        }
        __syncthreads();
        #pragma unroll 8
        for (int k = 0; k < 32; k++) {
            float a[8], b[8];
            #pragma unroll
            for (int i = 0; i < 8; i++) a[i] = As[k][ty8 + i];
            #pragma unroll
            for (int j = 0; j < 8; j++) b[j] = Bs[k][tx8 + j];
            #pragma unroll
            for (int i = 0; i < 8; i++)
                #pragma unroll
                for (int j = 0; j < 8; j++) acc[i][j] = fmaf(a[i], b[j], acc[i][j]);
        }
        __syncthreads();
    }
    for (int i = 0; i < 8; i++) {
        size_t r = (size_t)(r0 + ty8 + i) * Nc + c0 + tx8;
        #pragma unroll
        for (int j = 0; j < 8; j++) atomicAdd(&C[r + j], acc[i][j]);
    }
}

// ---------------- fused contrastive loss: per-row sum(exp(sim)) and sum(adj*exp(sim)) ----------------
__global__ __launch_bounds__(256, 2)
void k_loss_adj(const float* __restrict__ Z, const float* __restrict__ adj,
                float* __restrict__ sumG, float* __restrict__ posG) {
    __shared__ float As[32][132];
    __shared__ float Bs[32][132];
    int tid = threadIdx.x, tx = tid & 15, ty = tid >> 4;
    int r0 = blockIdx.x * 128;
    int jBeg = blockIdx.y * 2048, jEnd = jBeg + 2048;
    int ty8 = ty * 8, tx8 = tx * 8;
    float sumAcc[8] = {}, posAcc[8] = {};
    for (int c0 = jBeg; c0 < jEnd; c0 += 128) {
        float acc[8][8] = {};
        for (int k0 = 0; k0 < Dout; k0 += 32) {
            for (int t = tid; t < 4096; t += 256) {
                int k = t & 31, m = t >> 5;
                As[k][m] = Z[(size_t)(r0 + m) * Dout + k0 + k];
            }
            for (int t = tid; t < 4096; t += 256) {
                int k = t & 31, m = t >> 5;
                Bs[k][m] = Z[(size_t)(c0 + m) * Dout + k0 + k];
            }
            __syncthreads();
            #pragma unroll 8
            for (int k = 0; k < 32; k++) {
                float a[8], b[8];
                #pragma unroll
                for (int i = 0; i < 8; i++) a[i] = As[k][ty8 + i];
                #pragma unroll
                for (int j = 0; j < 8; j++) b[j] = Bs[k][tx8 + j];
                #pragma unroll
                for (int i = 0; i < 8; i++)
                    #pragma unroll
                    for (int j = 0; j < 8; j++) acc[i][j] = fmaf(a[i], b[j], acc[i][j]);
            }
            __syncthreads();
        }
        #pragma unroll
        for (int i = 0; i < 8; i++) {
            const float* arow = adj + (size_t)(r0 + ty8 + i) * Nn + c0 + tx8;
            #pragma unroll
            for (int j = 0; j < 8; j++) {
                float e = __expf(acc[i][j]);
                sumAcc[i] += e;
                posAcc[i] += arow[j] * e;
            }
        }
    }
    for (int i = 0; i < 8; i++) {
        int r = r0 + ty8 + i;
        atomicAdd(&sumG[r], sumAcc[i]);
        atomicAdd(&posG[r], posAcc[i]);
    }
}

// fused dim-label loss: refl = exp(Zf_n @ Cn^T) [Nn x Din], pos masked by feat>0
__global__ __launch_bounds__(256, 2)
void k_loss_dim(const float* __restrict__ Z, const float* __restrict__ Cn,
                const float* __restrict__ feat,
                float* __restrict__ sumG, float* __restrict__ posG) {
    __shared__ float As[32][132];
    __shared__ float Bs[32][132];
    int tid = threadIdx.x, tx = tid & 15, ty = tid >> 4;
    int r0 = blockIdx.x * 128;
    int c0 = blockIdx.y * 128;     // 4 tiles cover 512 cols
    int ty8 = ty * 8, tx8 = tx * 8;
    float acc[8][8] = {};
    for (int k0 = 0; k0 < Dout; k0 += 32) {
        for (int t = tid; t < 4096; t += 256) {
            int k = t & 31, m = t >> 5;
            As[k][m] = Z[(size_t)(r0 + m) * Dout + k0 + k];
        }
        for (int t = tid; t < 4096; t += 256) {
            int k = t & 31, m = t >> 5;
            Bs[k][m] = Cn[(size_t)(c0 + m) * Dout + k0 + k];
        }
        __syncthreads();
        #pragma unroll 8
        for (int k = 0; k < 32; k++) {
            float a[8], b[8];
            #pragma unroll
            for (int i = 0; i < 8; i++) a[i] = As[k][ty8 + i];
            #pragma unroll
            for (int j = 0; j < 8; j++) b[j] = Bs[k][tx8 + j];
            #pragma unroll
            for (int i = 0; i < 8; i++)
                #pragma unroll
                for (int j = 0; j < 8; j++) acc[i][j] = fmaf(a[i], b[j], acc[i][j]);
        }
        __syncthreads();
    }
    for (int i = 0; i < 8; i++) {
        int r = r0 + ty8 + i;
        const float* frow = feat + (size_t)r * Din + c0 + tx8;
        float sA = 0.f, pA = 0.f;
        #pragma unroll
        for (int j = 0; j < 8; j++) {
            float e = __expf(acc[i][j]);
            sA += e;
            if (frow[j] > 0.f) pA += e;
        }
        atomicAdd(&sumG[r], sA);
        atomicAdd(&posG[r], pA);
    }
}

__global__ void k_rowloss(const float* __restrict__ sumG, const float* __restrict__ posG,
                          float* loss, int mode) {
    __shared__ float red[256];
    int t = blockIdx.x * 256 + threadIdx.x;
    float term = 0.f;
    if (t < Nn) {
        float pos = posG[t], tot = sumG[t];
        float neg = tot - pos;
        if (mode == 0) term = -logf((pos + 1e-10f) / (neg + 1e-10f));
        else           term = -logf((pos + 1e-10f) / neg + 1e-5f);
    }
    red[threadIdx.x] = term;
    __syncthreads();
    for (int s = 128; s; s >>= 1) {
        if (threadIdx.x < s) red[threadIdx.x] += red[threadIdx.x + s];
        __syncthreads();
    }
    if (threadIdx.x == 0) atomicAdd(loss, red[0]);
}

// ---------------- attention fuse + norms + centers ----------------
__global__ void k_attention(const float* __restrict__ Wp1, const float* __restrict__ bp1,
                            const float* __restrict__ wp2) {
    int nid = blockIdx.x * 256 + threadIdx.x;
    if (nid >= Nn) return;
    const float* hx = g_Hx + (size_t)nid * Dout;
    const float* ha = g_Hadj + (size_t)nid * Dout;
    float accx[AH], acca[AH];
    #pragma unroll
    for (int h = 0; h < AH; h++) { accx[h] = bp1[h]; acca[h] = bp1[h]; }
    for (int d = 0; d < Dout; d++) {
        float vx = hx[d], va = ha[d];
        #pragma unroll
        for (int h = 0; h < AH; h++) {
            float w = Wp1[d * AH + h];
            accx[h] += vx * w; acca[h] += va * w;
        }
    }
    float wx = 0.f, wa = 0.f;
    #pragma unroll
    for (int h = 0; h < AH; h++) {
        wx += tanhf(accx[h]) * wp2[h];
        wa += tanhf(acca[h]) * wp2[h];
    }
    float m = fmaxf(wx, wa);
    float ex = __expf(wx - m), ea = __expf(wa - m);
    float inv = 1.f / (ex + ea);
    float bx = ex * inv, ba = ea * inv;
    float* out = g_Hf + (size_t)nid * Dout;
    for (int d = 0; d < Dout; d++) out[d] = bx * hx[d] + ba * ha[d];
}

__global__ void k_l2norm(const float* __restrict__ in, float* __restrict__ out,
                         int rows, int cols) {
    int w = (blockIdx.x * blockDim.x + threadIdx.x) >> 5;
    int lane = threadIdx.x & 31;
    if (w >= rows) return;
    const float* r = in + (size_t)w * cols;
    float ss = 0.f;
    for (int c = lane; c < cols; c += 32) { float v = r[c]; ss += v * v; }
    for (int o = 16; o; o >>= 1) ss += __shfl_xor_sync(0xffffffffu, ss, o);
    float inv = 1.f / fmaxf(sqrtf(ss), 1e-12f);
    float* wo = out + (size_t)w * cols;
    for (int c = lane; c < cols; c += 32) wo[c] = r[c] * inv;
}

__global__ void k_colsum(const float* __restrict__ feat) {
    int c = blockIdx.x * 256 + threadIdx.x;     // gridDim.x = 2
    int rbeg = blockIdx.y * 128;                // gridDim.y = 64
    float s = 0.f;
    for (int i = rbeg; i < rbeg + 128; i++) s += feat[(size_t)i * Din + c];
    atomicAdd(&g_colsum[c], s);
}

__global__ void k_center() {
    int w = (blockIdx.x * blockDim.x + threadIdx.x) >> 5;
    int lane = threadIdx.x & 31;
    if (w >= Din) return;
    float s = g_colsum[w] + 1e-5f;
    float inv_s = 1.f / s;
    float v[8]; float ss = 0.f;
    #pragma unroll
    for (int i = 0; i < 8; i++) {
        v[i] = g_dcraw[(size_t)w * Dout + lane + 32 * i] * inv_s;
        ss += v[i] * v[i];
    }
    for (int o = 16; o; o >>= 1) ss += __shfl_xor_sync(0xffffffffu, ss, o);
    float inv = 1.f / fmaxf(sqrtf(ss), 1e-12f);
    #pragma unroll
    for (int i = 0; i < 8; i++) g_Cn[(size_t)w * Dout + lane + 32 * i] = v[i] * inv;
}

__global__ void k_final(float* out) {
    out[0] = (0.5f * (g_loss[0] + g_loss[1]) + 0.1f * g_loss[2] + g_loss[3]) * (1.0f / Nn);
}

// ---------------- host ----------------
extern "C" void kernel_launch(void* const* d_in, const int* in_sizes, int n_in,
                              void* d_out, int out_size) {
    const float* feat = (const float*)d_in[0];
    const float* adjL = (const float*)d_in[1];
    const float* adjX = (const float*)d_in[2];
    const float* adjR = (const float*)d_in[3];

    // Disambiguate input ordering: dict order puts edge_index at 4/5 (both 262144);
    // signature order puts W0a at 4 (262144) and b0a at 5 (512).
    const int *eA, *eX; int pb;
    if (in_sizes[5] == 262144) { eA = (const int*)d_in[4]; eX = (const int*)d_in[5]; pb = 6; }
    else                       { pb = 4; eA = (const int*)d_in[15]; eX = (const int*)d_in[16]; }

    const float* W0a = (const float*)d_in[pb + 0];
    const float* b0a = (const float*)d_in[pb + 1];
    const float* W1a = (const float*)d_in[pb + 2];
    const float* b1a = (const float*)d_in[pb + 3];
    const float* W0x = (const float*)d_in[pb + 4];
    const float* b0x = (const float*)d_in[pb + 5];
    const float* W1x = (const float*)d_in[pb + 6];
    const float* b1x = (const float*)d_in[pb + 7];
    const float* Wp1 = (const float*)d_in[pb + 8];
    const float* bp1 = (const float*)d_in[pb + 9];
    const float* wp2 = (const float*)d_in[pb + 10];

    void *pY, *pP, *pH1, *pHadj, *pHx, *pHf, *pZa, *pZx, *pZf;
    void *pDeg, *pNrm, *pDc, *pCn, *pCs, *pSum, *pPos, *pLoss;
    cudaGetSymbolAddress(&pY, g_Y);       cudaGetSymbolAddress(&pP, g_P);
    cudaGetSymbolAddress(&pH1, g_H1);     cudaGetSymbolAddress(&pHadj, g_Hadj);
    cudaGetSymbolAddress(&pHx, g_Hx);     cudaGetSymbolAddress(&pHf, g_Hf);
    cudaGetSymbolAddress(&pZa, g_Za);     cudaGetSymbolAddress(&pZx, g_Zx);
    cudaGetSymbolAddress(&pZf, g_Zf);     cudaGetSymbolAddress(&pDeg, g_deg);
    cudaGetSymbolAddress(&pNrm, g_nrm);   cudaGetSymbolAddress(&pDc, g_dcraw);
    cudaGetSymbolAddress(&pCn, g_Cn);     cudaGetSymbolAddress(&pCs, g_colsum);
    cudaGetSymbolAddress(&pSum, g_sum);   cudaGetSymbolAddress(&pPos, g_pos);
    cudaGetSymbolAddress(&pLoss, g_loss);

    float* nrm = (float*)pNrm;
    float* nsA = nrm;           float* ndA = nrm + Nn;
    float* nsX = nrm + 2 * Nn;  float* ndX = nrm + 3 * Nn;
    float* sum = (float*)pSum;  float* pos = (float*)pPos;
    float* loss = (float*)pLoss;

    // degrees + norm factors
    cudaMemsetAsync(pDeg, 0, 4 * Nn * sizeof(float));
    k_degree<<<(Ne + 255) / 256, 256>>>(eA, eA + Ne, (float*)pDeg, (float*)pDeg + Nn);
    k_degree<<<(Ne + 255) / 256, 256>>>(eX, eX + Ne, (float*)pDeg + 2 * Nn, (float*)pDeg + 3 * Nn);
    k_norm<<<(4 * Nn) / 256, 256>>>();

    // ---- GCN over graph A ----
    k_gemm_nn<<<dim3(Nn / 128, Din / 128), 256>>>(feat, W0a, (float*)pY, Nn, Din, Din);
    cudaMemsetAsync(pP, 0, (size_t)Nn * Din * sizeof(float));
    k_scatter<<<(Ne * (Din / 4) + 255) / 256, 256>>>(eA, eA + Ne, (float*)pY, nsA, (float*)pP, Din / 4);
    k_post<<<Nn * Din / 256, 256>>>((float*)pP, ndA, b0a, (float*)pH1, Din, 1);
    k_gemm_nn<<<dim3(Nn / 128, Dout / 128), 256>>>((float*)pH1, W1a, (float*)pY, Nn, Dout, Din);
    cudaMemsetAsync(pP, 0, (size_t)Nn * Dout * sizeof(float));
    k_scatter<<<(Ne * (Dout / 4) + 255) / 256, 256>>>(eA, eA + Ne, (float*)pY, nsA, (float*)pP, Dout / 4);
    k_post<<<Nn * Dout / 256, 256>>>((float*)pP, ndA, b1a, (float*)pHadj, Dout, 0);

    // ---- GCN over graph X ----
    k_gemm_nn<<<dim3(Nn / 128, Din / 128), 256>>>(feat, W0x, (float*)pY, Nn, Din, Din);
    cudaMemsetAsync(pP, 0, (size_t)Nn * Din * sizeof(float));
    k_scatter<<<(Ne * (Din / 4) + 255) / 256, 256>>>(eX, eX + Ne, (float*)pY, nsX, (float*)pP, Din / 4);
    k_post<<<Nn * Din / 256, 256>>>((float*)pP, ndX, b0x, (float*)pH1, Din, 1);
    k_gemm_nn<<<dim3(Nn / 128, Dout / 128), 256>>>((float*)pH1, W1x, (float*)pY, Nn, Dout, Din);
    cudaMemsetAsync(pP, 0, (size_t)Nn * Dout * sizeof(float));
    k_scatter<<<(Ne * (Dout / 4) + 255) / 256, 256>>>(eX, eX + Ne, (float*)pY, nsX, (float*)pP, Dout / 4);
    k_post<<<Nn * Dout / 256, 256>>>((float*)pP, ndX, b1x, (float*)pHx, Dout, 0);

    // ---- attention fusion + normalization ----
    k_attention<<<Nn / 256, 256>>>(Wp1, bp1, wp2);
    k_l2norm<<<Nn / 8, 256>>>((float*)pHadj, (float*)pZa, Nn, Dout);
    k_l2norm<<<Nn / 8, 256>>>((float*)pHx,   (float*)pZx, Nn, Dout);
    k_l2norm<<<Nn / 8, 256>>>((float*)pHf,   (float*)pZf, Nn, Dout);

    // ---- dim_center ----
    cudaMemsetAsync(pCs, 0, Din * sizeof(float));
    k_colsum<<<dim3(2, 64), 256>>>(feat);
    cudaMemsetAsync(pDc, 0, (size_t)Din * Dout * sizeof(float));
    k_atb<<<dim3(Din / 128, Dout / 128, 32), 256>>>(feat, (float*)pHf, (float*)pDc, Din, Dout, Nn / 32);
    k_center<<<Din / 8, 256>>>();

    // ---- losses ----
    cudaMemsetAsync(pSum, 0, 4 * Nn * sizeof(float));
    cudaMemsetAsync(pPos, 0, 4 * Nn * sizeof(float));
    cudaMemsetAsync(pLoss, 0, 4 * sizeof(float));
    k_loss_adj<<<dim3(Nn / 128, 4), 256>>>((float*)pZa, adjL, sum,           pos);
    k_loss_adj<<<dim3(Nn / 128, 4), 256>>>((float*)pZx, adjX, sum + Nn,      pos + Nn);
    k_loss_dim<<<dim3(Nn / 128, Din / 128), 256>>>((float*)pZf, (float*)pCn, feat,
                                                   sum + 2 * Nn, pos + 2 * Nn);
    k_loss_adj<<<dim3(Nn / 128, 4), 256>>>((float*)pZf, adjR, sum + 3 * Nn,  pos + 3 * Nn);

    k_rowloss<<<Nn / 256, 256>>>(sum,          pos,          loss + 0, 0);
    k_rowloss<<<Nn / 256, 256>>>(sum + Nn,     pos + Nn,     loss + 1, 0);
    k_rowloss<<<Nn / 256, 256>>>(sum + 2 * Nn, pos + 2 * Nn, loss + 2, 1);
    k_rowloss<<<Nn / 256, 256>>>(sum + 3 * Nn, pos + 3 * Nn, loss + 3, 0);

    k_final<<<1, 1>>>((float*)d_out);
}

// round 3
// speedup vs baseline: 2.1909x; 2.1909x over previous
#include <cuda_runtime.h>
#include <cuda_fp16.h>
#include <cstdint>
#include <math.h>

#define Nn   8192
#define Din  512
#define Dout 256
#define Ne   131072
#define AH   16
#define LDH  264   // padded row stride (halves) for smem tiles: 528B -> conflict-free ldmatrix

// ---------------- scratch (static device allocations; no cudaMalloc) ----------------
static __device__ float g_Y[Nn*Din];
static __device__ float g_P[Nn*Din];
static __device__ float g_H1[Nn*Din];
static __device__ float g_Hadj[Nn*Dout];
static __device__ float g_Hx[Nn*Dout];
static __device__ float g_Hf[Nn*Dout];
static __device__ float g_Zf[Nn*Dout];          // fp32 (dim loss)
static __device__ __half g_Zah[Nn*Dout];        // fp16 l2-normalized embeddings
static __device__ __half g_Zxh[Nn*Dout];
static __device__ __half g_Zfh[Nn*Dout];
static __device__ float g_deg[4*Nn];
static __device__ float g_nrm[4*Nn];
static __device__ float g_dcraw[Din*Dout];
static __device__ float g_Cn[Din*Dout];
static __device__ float g_colsum[Din];
static __device__ float g_sum[4*Nn];
static __device__ float g_pos[4*Nn];
static __device__ float g_loss[4];

// ---------------- small kernels ----------------
__global__ void k_degree(const int* __restrict__ src, const int* __restrict__ dst,
                         float* degO, float* degI) {
    int t = blockIdx.x * 256 + threadIdx.x;
    if (t < Ne) { atomicAdd(degO + src[t], 1.f); atomicAdd(degI + dst[t], 1.f); }
}

__global__ void k_norm() {
    int t = blockIdx.x * 256 + threadIdx.x;
    if (t < 4 * Nn) { float d = g_deg[t]; g_nrm[t] = (d > 0.f) ? rsqrtf(d) : 0.f; }
}

__global__ void k_scatter(const int* __restrict__ src, const int* __restrict__ dst,
                          const float* __restrict__ Y, const float* __restrict__ ns,
                          float* __restrict__ P, int C4) {
    int idx = blockIdx.x * 256 + threadIdx.x;
    if (idx >= Ne * C4) return;
    int e = idx / C4, c = idx % C4;
    int s = src[e], d = dst[e];
    float4 v = ((const float4*)Y)[(size_t)s * C4 + c];
    float sc = ns[s];
    float* p = P + ((size_t)d * C4 + c) * 4;
    atomicAdd(p + 0, v.x * sc); atomicAdd(p + 1, v.y * sc);
    atomicAdd(p + 2, v.z * sc); atomicAdd(p + 3, v.w * sc);
}

__global__ void k_post(const float* __restrict__ P, const float* __restrict__ nd,
                       const float* __restrict__ bias, float* __restrict__ H,
                       int C, int relu) {
    int idx = blockIdx.x * 256 + threadIdx.x;
    int i = idx / C, c = idx % C;
    float v = P[idx] * nd[i] + bias[c];
    if (relu) v = fmaxf(v, 0.f);
    H[idx] = v;
}

// ---------------- generic fp32 GEMM: C = A[MxK] @ B[KxN] ----------------
__global__ __launch_bounds__(256, 2)
void k_gemm_nn(const float* __restrict__ A, const float* __restrict__ B,
               float* __restrict__ C, int M, int Nc, int K) {
    __shared__ float As[32][132];
    __shared__ float Bs[32][132];
    int tid = threadIdx.x, tx = tid & 15, ty = tid >> 4;
    int r0 = blockIdx.x * 128, c0 = blockIdx.y * 128;
    int ty8 = ty * 8, tx8 = tx * 8;
    float acc[8][8] = {};
    for (int k0 = 0; k0 < K; k0 += 32) {
        for (int t = tid; t < 4096; t += 256) {
            int k = t & 31, m = t >> 5;
            As[k][m] = A[(size_t)(r0 + m) * K + k0 + k];
        }
        for (int t = tid; t < 4096; t += 256) {
            int n = t & 127, k = t >> 7;
            Bs[k][n] = B[(size_t)(k0 + k) * Nc + c0 + n];
        }
        __syncthreads();
        #pragma unroll 8
        for (int k = 0; k < 32; k++) {
            float a[8], b[8];
            #pragma unroll
            for (int i = 0; i < 8; i++) a[i] = As[k][ty8 + i];
            #pragma unroll
            for (int j = 0; j < 8; j++) b[j] = Bs[k][tx8 + j];
            #pragma unroll
            for (int i = 0; i < 8; i++)
                #pragma unroll
                for (int j = 0; j < 8; j++) acc[i][j] = fmaf(a[i], b[j], acc[i][j]);
        }
        __syncthreads();
    }
    for (int i = 0; i < 8; i++) {
        size_t r = (size_t)(r0 + ty8 + i) * Nc + c0 + tx8;
        #pragma unroll
        for (int j = 0; j < 8; j++) C[r + j] = acc[i][j];
    }
}

// C[MxN] += A^T@B over K-slice: A is [K x M] row-major, B is [K x N]
__global__ __launch_bounds__(256, 2)
void k_atb(const float* __restrict__ A, const float* __restrict__ B,
           float* __restrict__ C, int M, int Nc, int kPerSlice) {
    __shared__ float As[32][132];
    __shared__ float Bs[32][132];
    int tid = threadIdx.x, tx = tid & 15, ty = tid >> 4;
    int r0 = blockIdx.x * 128, c0 = blockIdx.y * 128;
    int kb = blockIdx.z * kPerSlice;
    int ty8 = ty * 8, tx8 = tx * 8;
    float acc[8][8] = {};
    for (int k0 = kb; k0 < kb + kPerSlice; k0 += 32) {
        for (int t = tid; t < 4096; t += 256) {
            int m = t & 127, k = t >> 7;
            As[k][m] = A[(size_t)(k0 + k) * M + r0 + m];
        }
        for (int t = tid; t < 4096; t += 256) {
            int n = t & 127, k = t >> 7;
            Bs[k][n] = B[(size_t)(k0 + k) * Nc + c0 + n];
        }
        __syncthreads();
        #pragma unroll 8
        for (int k = 0; k < 32; k++) {
            float a[8], b[8];
            #pragma unroll
            for (int i = 0; i < 8; i++) a[i] = As[k][ty8 + i];
            #pragma unroll
            for (int j = 0; j < 8; j++) b[j] = Bs[k][tx8 + j];
            #pragma unroll
            for (int i = 0; i < 8; i++)
                #pragma unroll
                for (int j = 0; j < 8; j++) acc[i][j] = fmaf(a[i], b[j], acc[i][j]);
        }
        __syncthreads();
    }
    for (int i = 0; i < 8; i++) {
        size_t r = (size_t)(r0 + ty8 + i) * Nc + c0 + tx8;
        #pragma unroll
        for (int j = 0; j < 8; j++) atomicAdd(&C[r + j], acc[i][j]);
    }
}

// ---------------- tensor-core fused contrastive loss ----------------
__device__ __forceinline__ unsigned int saddr(const void* p) {
    return (unsigned int)__cvta_generic_to_shared(p);
}

__global__ __launch_bounds__(256)
void k_loss_adj_h(const __half* __restrict__ Zh, const float* __restrict__ adj,
                  float* __restrict__ sumG, float* __restrict__ posG) {
    extern __shared__ __half sh[];
    __half* As = sh;                  // [128][LDH]
    __half* Bs = sh + 128 * LDH;      // [128][LDH]
    const int tid = threadIdx.x;
    const int lane = tid & 31, warp = tid >> 5;
    const int wm = warp >> 1, wn = warp & 1;
    const int r0 = blockIdx.x * 128;
    const int jBeg = blockIdx.y * 4096, jEnd = jBeg + 4096;

    // stage A tile (rows r0..r0+127, all 256 k) once
    for (int t = tid; t < 4096; t += 256) {
        int row = t >> 5, c8 = (t & 31) * 8;
        *(float4*)&As[row * LDH + c8] =
            *(const float4*)&Zh[(size_t)(r0 + row) * Dout + c8];
    }

    // per-lane ldmatrix base addresses (k0 = 0)
    const int mat = lane >> 3, r = lane & 7;
    unsigned int aBase[2], bBase[4];
    #pragma unroll
    for (int am = 0; am < 2; am++) {
        int row = wm * 32 + am * 16 + (mat & 1) * 8 + r;
        aBase[am] = saddr(&As[row * LDH + (mat >> 1) * 8]);
    }
    #pragma unroll
    for (int p = 0; p < 4; p++) {
        int row = wn * 64 + p * 16 + (mat >> 1) * 8 + r;
        bBase[p] = saddr(&Bs[row * LDH + (mat & 1) * 8]);
    }

    float rs[4] = {}, rp[4] = {};

    for (int c0 = jBeg; c0 < jEnd; c0 += 128) {
        __syncthreads();
        for (int t = tid; t < 4096; t += 256) {
            int row = t >> 5, c8 = (t & 31) * 8;
            *(float4*)&Bs[row * LDH + c8] =
                *(const float4*)&Zh[(size_t)(c0 + row) * Dout + c8];
        }
        __syncthreads();

        float acc[2][8][4] = {};
        #pragma unroll
        for (int k0 = 0; k0 < Dout; k0 += 16) {
            unsigned int a[2][4], b[4][4];
            #pragma unroll
            for (int am = 0; am < 2; am++)
                asm volatile("ldmatrix.sync.aligned.m8n8.x4.shared.b16 {%0,%1,%2,%3}, [%4];"
                    : "=r"(a[am][0]), "=r"(a[am][1]), "=r"(a[am][2]), "=r"(a[am][3])
                    : "r"(aBase[am] + k0 * 2));
            #pragma unroll
            for (int p = 0; p < 4; p++)
                asm volatile("ldmatrix.sync.aligned.m8n8.x4.shared.b16 {%0,%1,%2,%3}, [%4];"
                    : "=r"(b[p][0]), "=r"(b[p][1]), "=r"(b[p][2]), "=r"(b[p][3])
                    : "r"(bBase[p] + k0 * 2));
            #pragma unroll
            for (int am = 0; am < 2; am++)
                #pragma unroll
                for (int an = 0; an < 8; an++) {
                    int p = an >> 1, q = (an & 1) * 2;
                    asm volatile(
                        "mma.sync.aligned.m16n8k16.row.col.f32.f16.f16.f32 "
                        "{%0,%1,%2,%3}, {%4,%5,%6,%7}, {%8,%9}, {%0,%1,%2,%3};"
                        : "+f"(acc[am][an][0]), "+f"(acc[am][an][1]),
                          "+f"(acc[am][an][2]), "+f"(acc[am][an][3])
                        : "r"(a[am][0]), "r"(a[am][1]), "r"(a[am][2]), "r"(a[am][3]),
                          "r"(b[p][q]), "r"(b[p][q + 1]));
                }
        }

        // fused epilogue: exp + masked row sums
        #pragma unroll
        for (int am = 0; am < 2; am++) {
            int row0 = r0 + wm * 32 + am * 16 + (lane >> 2);
            #pragma unroll
            for (int an = 0; an < 8; an++) {
                int col = c0 + wn * 64 + an * 8 + (lane & 3) * 2;
                float2 m0 = *(const float2*)&adj[(size_t)row0 * Nn + col];
                float2 m1 = *(const float2*)&adj[(size_t)(row0 + 8) * Nn + col];
                float e0 = __expf(acc[am][an][0]);
                float e1 = __expf(acc[am][an][1]);
                float e2 = __expf(acc[am][an][2]);
                float e3 = __expf(acc[am][an][3]);
                rs[am * 2 + 0] += e0 + e1;
                rp[am * 2 + 0] += m0.x * e0 + m0.y * e1;
                rs[am * 2 + 1] += e2 + e3;
                rp[am * 2 + 1] += m1.x * e2 + m1.y * e3;
            }
        }
    }

    // quad reduce (lanes sharing a row) then merge
    #pragma unroll
    for (int s = 0; s < 4; s++) {
        float v = rs[s], p = rp[s];
        v += __shfl_xor_sync(0xffffffffu, v, 1);
        v += __shfl_xor_sync(0xffffffffu, v, 2);
        p += __shfl_xor_sync(0xffffffffu, p, 1);
        p += __shfl_xor_sync(0xffffffffu, p, 2);
        if ((lane & 3) == 0) {
            int row = r0 + wm * 32 + (s >> 1) * 16 + (s & 1) * 8 + (lane >> 2);
            atomicAdd(&sumG[row], v);
            atomicAdd(&posG[row], p);
        }
    }
}

// fused dim-label loss (fp32: Nn x Din x Dout)
__global__ __launch_bounds__(256, 2)
void k_loss_dim(const float* __restrict__ Z, const float* __restrict__ Cn,
                const float* __restrict__ feat,
                float* __restrict__ sumG, float* __restrict__ posG) {
    __shared__ float As[32][132];
    __shared__ float Bs[32][132];
    int tid = threadIdx.x, tx = tid & 15, ty = tid >> 4;
    int r0 = blockIdx.x * 128;
    int c0 = blockIdx.y * 128;
    int ty8 = ty * 8, tx8 = tx * 8;
    float acc[8][8] = {};
    for (int k0 = 0; k0 < Dout; k0 += 32) {
        for (int t = tid; t < 4096; t += 256) {
            int k = t & 31, m = t >> 5;
            As[k][m] = Z[(size_t)(r0 + m) * Dout + k0 + k];
        }
        for (int t = tid; t < 4096; t += 256) {
            int k = t & 31, m = t >> 5;
            Bs[k][m] = Cn[(size_t)(c0 + m) * Dout + k0 + k];
        }
        __syncthreads();
        #pragma unroll 8
        for (int k = 0; k < 32; k++) {
            float a[8], b[8];
            #pragma unroll
            for (int i = 0; i < 8; i++) a[i] = As[k][ty8 + i];
            #pragma unroll
            for (int j = 0; j < 8; j++) b[j] = Bs[k][tx8 + j];
            #pragma unroll
            for (int i = 0; i < 8; i++)
                #pragma unroll
                for (int j = 0; j < 8; j++) acc[i][j] = fmaf(a[i], b[j], acc[i][j]);
        }
        __syncthreads();
    }
    for (int i = 0; i < 8; i++) {
        int rr = r0 + ty8 + i;
        const float* frow = feat + (size_t)rr * Din + c0 + tx8;
        float sA = 0.f, pA = 0.f;
        #pragma unroll
        for (int j = 0; j < 8; j++) {
            float e = __expf(acc[i][j]);
            sA += e;
            if (frow[j] > 0.f) pA += e;
        }
        atomicAdd(&sumG[rr], sA);
        atomicAdd(&posG[rr], pA);
    }
}

__global__ void k_rowloss(const float* __restrict__ sumG, const float* __restrict__ posG,
                          float* loss, int mode) {
    __shared__ float red[256];
    int t = blockIdx.x * 256 + threadIdx.x;
    float term = 0.f;
    if (t < Nn) {
        float pos = posG[t], tot = sumG[t];
        float neg = tot - pos;
        if (mode == 0) term = -logf((pos + 1e-10f) / (neg + 1e-10f));
        else           term = -logf((pos + 1e-10f) / neg + 1e-5f);
    }
    red[threadIdx.x] = term;
    __syncthreads();
    for (int s = 128; s; s >>= 1) {
        if (threadIdx.x < s) red[threadIdx.x] += red[threadIdx.x + s];
        __syncthreads();
    }
    if (threadIdx.x == 0) atomicAdd(loss, red[0]);
}

// ---------------- attention fuse + norms + centers ----------------
__global__ void k_attention(const float* __restrict__ Wp1, const float* __restrict__ bp1,
                            const float* __restrict__ wp2) {
    int nid = blockIdx.x * 256 + threadIdx.x;
    if (nid >= Nn) return;
    const float* hx = g_Hx + (size_t)nid * Dout;
    const float* ha = g_Hadj + (size_t)nid * Dout;
    float accx[AH], acca[AH];
    #pragma unroll
    for (int h = 0; h < AH; h++) { accx[h] = bp1[h]; acca[h] = bp1[h]; }
    for (int d = 0; d < Dout; d++) {
        float vx = hx[d], va = ha[d];
        #pragma unroll
        for (int h = 0; h < AH; h++) {
            float w = Wp1[d * AH + h];
            accx[h] += vx * w; acca[h] += va * w;
        }
    }
    float wx = 0.f, wa = 0.f;
    #pragma unroll
    for (int h = 0; h < AH; h++) {
        wx += tanhf(accx[h]) * wp2[h];
        wa += tanhf(acca[h]) * wp2[h];
    }
    float m = fmaxf(wx, wa);
    float ex = __expf(wx - m), ea = __expf(wa - m);
    float inv = 1.f / (ex + ea);
    float bx = ex * inv, ba = ea * inv;
    float* out = g_Hf + (size_t)nid * Dout;
    for (int d = 0; d < Dout; d++) out[d] = bx * hx[d] + ba * ha[d];
}

// l2norm writing fp16 (and optionally fp32)
__global__ void k_l2norm(const float* __restrict__ in, __half* __restrict__ outH,
                         float* __restrict__ outF, int rows, int cols) {
    int w = (blockIdx.x * blockDim.x + threadIdx.x) >> 5;
    int lane = threadIdx.x & 31;
    if (w >= rows) return;
    const float* r = in + (size_t)w * cols;
    float ss = 0.f;
    for (int c = lane; c < cols; c += 32) { float v = r[c]; ss += v * v; }
    for (int o = 16; o; o >>= 1) ss += __shfl_xor_sync(0xffffffffu, ss, o);
    float inv = 1.f / fmaxf(sqrtf(ss), 1e-12f);
    __half* wh = outH + (size_t)w * cols;
    for (int c = lane; c < cols; c += 32) {
        float v = r[c] * inv;
        wh[c] = __float2half(v);
        if (outF) outF[(size_t)w * cols + c] = v;
    }
}

__global__ void k_colsum(const float* __restrict__ feat) {
    int c = blockIdx.x * 256 + threadIdx.x;
    int rbeg = blockIdx.y * 128;
    float s = 0.f;
    for (int i = rbeg; i < rbeg + 128; i++) s += feat[(size_t)i * Din + c];
    atomicAdd(&g_colsum[c], s);
}

__global__ void k_center() {
    int w = (blockIdx.x * blockDim.x + threadIdx.x) >> 5;
    int lane = threadIdx.x & 31;
    if (w >= Din) return;
    float s = g_colsum[w] + 1e-5f;
    float inv_s = 1.f / s;
    float v[8]; float ss = 0.f;
    #pragma unroll
    for (int i = 0; i < 8; i++) {
        v[i] = g_dcraw[(size_t)w * Dout + lane + 32 * i] * inv_s;
        ss += v[i] * v[i];
    }
    for (int o = 16; o; o >>= 1) ss += __shfl_xor_sync(0xffffffffu, ss, o);
    float inv = 1.f / fmaxf(sqrtf(ss), 1e-12f);
    #pragma unroll
    for (int i = 0; i < 8; i++) g_Cn[(size_t)w * Dout + lane + 32 * i] = v[i] * inv;
}

__global__ void k_final(float* out) {
    out[0] = (0.5f * (g_loss[0] + g_loss[1]) + 0.1f * g_loss[2] + g_loss[3]) * (1.0f / Nn);
}

// ---------------- host ----------------
extern "C" void kernel_launch(void* const* d_in, const int* in_sizes, int n_in,
                              void* d_out, int out_size) {
    const float* feat = (const float*)d_in[0];
    const float* adjL = (const float*)d_in[1];
    const float* adjX = (const float*)d_in[2];
    const float* adjR = (const float*)d_in[3];

    const int *eA, *eX; int pb;
    if (in_sizes[5] == 262144) { eA = (const int*)d_in[4]; eX = (const int*)d_in[5]; pb = 6; }
    else                       { pb = 4; eA = (const int*)d_in[15]; eX = (const int*)d_in[16]; }

    const float* W0a = (const float*)d_in[pb + 0];
    const float* b0a = (const float*)d_in[pb + 1];
    const float* W1a = (const float*)d_in[pb + 2];
    const float* b1a = (const float*)d_in[pb + 3];
    const float* W0x = (const float*)d_in[pb + 4];
    const float* b0x = (const float*)d_in[pb + 5];
    const float* W1x = (const float*)d_in[pb + 6];
    const float* b1x = (const float*)d_in[pb + 7];
    const float* Wp1 = (const float*)d_in[pb + 8];
    const float* bp1 = (const float*)d_in[pb + 9];
    const float* wp2 = (const float*)d_in[pb + 10];

    static int smemSet = 0;
    const int LOSS_SMEM = 2 * 128 * LDH * (int)sizeof(__half);   // 135168
    if (!smemSet) {
        cudaFuncSetAttribute(k_loss_adj_h, cudaFuncAttributeMaxDynamicSharedMemorySize, LOSS_SMEM);
        smemSet = 1;
    }

    void *pY, *pP, *pH1, *pHadj, *pHx, *pHf, *pZf, *pZah, *pZxh, *pZfh;
    void *pDeg, *pNrm, *pDc, *pCn, *pCs, *pSum, *pPos, *pLoss;
    cudaGetSymbolAddress(&pY, g_Y);       cudaGetSymbolAddress(&pP, g_P);
    cudaGetSymbolAddress(&pH1, g_H1);     cudaGetSymbolAddress(&pHadj, g_Hadj);
    cudaGetSymbolAddress(&pHx, g_Hx);     cudaGetSymbolAddress(&pHf, g_Hf);
    cudaGetSymbolAddress(&pZf, g_Zf);     cudaGetSymbolAddress(&pZah, g_Zah);
    cudaGetSymbolAddress(&pZxh, g_Zxh);   cudaGetSymbolAddress(&pZfh, g_Zfh);
    cudaGetSymbolAddress(&pDeg, g_deg);   cudaGetSymbolAddress(&pNrm, g_nrm);
    cudaGetSymbolAddress(&pDc, g_dcraw);  cudaGetSymbolAddress(&pCn, g_Cn);
    cudaGetSymbolAddress(&pCs, g_colsum); cudaGetSymbolAddress(&pSum, g_sum);
    cudaGetSymbolAddress(&pPos, g_pos);   cudaGetSymbolAddress(&pLoss, g_loss);

    float* nrm = (float*)pNrm;
    float* nsA = nrm;           float* ndA = nrm + Nn;
    float* nsX = nrm + 2 * Nn;  float* ndX = nrm + 3 * Nn;
    float* sum = (float*)pSum;  float* pos = (float*)pPos;
    float* loss = (float*)pLoss;

    cudaMemsetAsync(pDeg, 0, 4 * Nn * sizeof(float));
    k_degree<<<(Ne + 255) / 256, 256>>>(eA, eA + Ne, (float*)pDeg, (float*)pDeg + Nn);
    k_degree<<<(Ne + 255) / 256, 256>>>(eX, eX + Ne, (float*)pDeg + 2 * Nn, (float*)pDeg + 3 * Nn);
    k_norm<<<(4 * Nn) / 256, 256>>>();

    // ---- GCN over graph A ----
    k_gemm_nn<<<dim3(Nn / 128, Din / 128), 256>>>(feat, W0a, (float*)pY, Nn, Din, Din);
    cudaMemsetAsync(pP, 0, (size_t)Nn * Din * sizeof(float));
    k_scatter<<<(Ne * (Din / 4) + 255) / 256, 256>>>(eA, eA + Ne, (float*)pY, nsA, (float*)pP, Din / 4);
    k_post<<<Nn * Din / 256, 256>>>((float*)pP, ndA, b0a, (float*)pH1, Din, 1);
    k_gemm_nn<<<dim3(Nn / 128, Dout / 128), 256>>>((float*)pH1, W1a, (float*)pY, Nn, Dout, Din);
    cudaMemsetAsync(pP, 0, (size_t)Nn * Dout * sizeof(float));
    k_scatter<<<(Ne * (Dout / 4) + 255) / 256, 256>>>(eA, eA + Ne, (float*)pY, nsA, (float*)pP, Dout / 4);
    k_post<<<Nn * Dout / 256, 256>>>((float*)pP, ndA, b1a, (float*)pHadj, Dout, 0);

    // ---- GCN over graph X ----
    k_gemm_nn<<<dim3(Nn / 128, Din / 128), 256>>>(feat, W0x, (float*)pY, Nn, Din, Din);
    cudaMemsetAsync(pP, 0, (size_t)Nn * Din * sizeof(float));
    k_scatter<<<(Ne * (Din / 4) + 255) / 256, 256>>>(eX, eX + Ne, (float*)pY, nsX, (float*)pP, Din / 4);
    k_post<<<Nn * Din / 256, 256>>>((float*)pP, ndX, b0x, (float*)pH1, Din, 1);
    k_gemm_nn<<<dim3(Nn / 128, Dout / 128), 256>>>((float*)pH1, W1x, (float*)pY, Nn, Dout, Din);
    cudaMemsetAsync(pP, 0, (size_t)Nn * Dout * sizeof(float));
    k_scatter<<<(Ne * (Dout / 4) + 255) / 256, 256>>>(eX, eX + Ne, (float*)pY, nsX, (float*)pP, Dout / 4);
    k_post<<<Nn * Dout / 256, 256>>>((float*)pP, ndX, b1x, (float*)pHx, Dout, 0);

    // ---- attention fusion + normalization ----
    k_attention<<<Nn / 256, 256>>>(Wp1, bp1, wp2);
    k_l2norm<<<Nn / 8, 256>>>((float*)pHadj, (__half*)pZah, nullptr, Nn, Dout);
    k_l2norm<<<Nn / 8, 256>>>((float*)pHx,   (__half*)pZxh, nullptr, Nn, Dout);
    k_l2norm<<<Nn / 8, 256>>>((float*)pHf,   (__half*)pZfh, (float*)pZf, Nn, Dout);

    // ---- dim_center ----
    cudaMemsetAsync(pCs, 0, Din * sizeof(float));
    k_colsum<<<dim3(2, 64), 256>>>(feat);
    cudaMemsetAsync(pDc, 0, (size_t)Din * Dout * sizeof(float));
    k_atb<<<dim3(Din / 128, Dout / 128, 32), 256>>>(feat, (float*)pHf, (float*)pDc, Din, Dout, Nn / 32);
    k_center<<<Din / 8, 256>>>();

    // ---- losses ----
    cudaMemsetAsync(pSum, 0, 4 * Nn * sizeof(float));
    cudaMemsetAsync(pPos, 0, 4 * Nn * sizeof(float));
    cudaMemsetAsync(pLoss, 0, 4 * sizeof(float));
    k_loss_adj_h<<<dim3(Nn / 128, 2), 256, LOSS_SMEM>>>((const __half*)pZah, adjL, sum,          pos);
    k_loss_adj_h<<<dim3(Nn / 128, 2), 256, LOSS_SMEM>>>((const __half*)pZxh, adjX, sum + Nn,     pos + Nn);
    k_loss_dim<<<dim3(Nn / 128, Din / 128), 256>>>((float*)pZf, (float*)pCn, feat,
                                                   sum + 2 * Nn, pos + 2 * Nn);
    k_loss_adj_h<<<dim3(Nn / 128, 2), 256, LOSS_SMEM>>>((const __half*)pZfh, adjR, sum + 3 * Nn, pos + 3 * Nn);

    k_rowloss<<<Nn / 256, 256>>>(sum,          pos,          loss + 0, 0);
    k_rowloss<<<Nn / 256, 256>>>(sum + Nn,     pos + Nn,     loss + 1, 0);
    k_rowloss<<<Nn / 256, 256>>>(sum + 2 * Nn, pos + 2 * Nn, loss + 2, 1);
    k_rowloss<<<Nn / 256, 256>>>(sum + 3 * Nn, pos + 3 * Nn, loss + 3, 0);

    k_final<<<1, 1>>>((float*)d_out);
}

// round 4
// speedup vs baseline: 2.4249x; 1.1068x over previous
#include <cuda_runtime.h>
#include <cuda_fp16.h>
#include <cstdint>
#include <math.h>

#define Nn   8192
#define Din  512
#define Dout 256
#define Ne   131072
#define AH   16
#define LDH  264   // padded smem row stride (halves): conflict-free ldmatrix
#define NW   256   // bitmask words per row (8192/32)

// ---------------- static scratch ----------------
static __device__ float g_Y[Nn*Din];
static __device__ float g_H1[Nn*Din];
static __device__ float g_Hadj[Nn*Dout];
static __device__ float g_Hx[Nn*Dout];
static __device__ float g_Hf[Nn*Dout];
static __device__ float g_Zf[Nn*Dout];
static __device__ __half g_Zah[Nn*Dout];
static __device__ __half g_Zxh[Nn*Dout];
static __device__ __half g_Zfh[Nn*Dout];
static __device__ float g_deg[4*Nn];            // outA,inA,outX,inX
static __device__ float g_nrm[4*Nn];
static __device__ int   g_off[2*(Nn+1)];
static __device__ int   g_cursor[2*Nn];
static __device__ int   g_eidx[2*Ne];
static __device__ unsigned g_bits[3u*Nn*NW];    // packed adjacencies
static __device__ float g_dcraw[Din*Dout];
static __device__ float g_Cn[Din*Dout];
static __device__ float g_colsum[Din];
static __device__ float g_sum[4*Nn];
static __device__ float g_pos[4*Nn];
static __device__ float g_loss[4];

// ---------------- graph preprocessing ----------------
__global__ void k_degree(const int* __restrict__ src, const int* __restrict__ dst,
                         float* degO, float* degI) {
    int t = blockIdx.x * 256 + threadIdx.x;
    if (t < Ne) { atomicAdd(degO + src[t], 1.f); atomicAdd(degI + dst[t], 1.f); }
}

__global__ void k_norm() {
    int t = blockIdx.x * 256 + threadIdx.x;
    if (t < 4 * Nn) { float d = g_deg[t]; g_nrm[t] = (d > 0.f) ? rsqrtf(d) : 0.f; }
}

// exclusive prefix sum of in-degrees (one block, 1024 thr x 8 elems)
__global__ void k_scan(const float* __restrict__ degIn, int* __restrict__ off) {
    __shared__ int part[1024];
    int t = threadIdx.x;
    int v[8]; int s = 0;
    #pragma unroll
    for (int i = 0; i < 8; i++) { v[i] = s; s += (int)degIn[t * 8 + i]; }
    part[t] = s;
    __syncthreads();
    for (int d = 1; d < 1024; d <<= 1) {
        int x = (t >= d) ? part[t - d] : 0;
        __syncthreads();
        part[t] += x;
        __syncthreads();
    }
    int base = (t > 0) ? part[t - 1] : 0;
    #pragma unroll
    for (int i = 0; i < 8; i++) off[t * 8 + i] = base + v[i];
    if (t == 1023) off[Nn] = part[1023];
}

__global__ void k_bucket(const int* __restrict__ src, const int* __restrict__ dst,
                         const int* __restrict__ off, int* __restrict__ cursor,
                         int* __restrict__ eidx) {
    int t = blockIdx.x * 256 + threadIdx.x;
    if (t >= Ne) return;
    int d = dst[t];
    int p = atomicAdd(&cursor[d], 1);
    eidx[off[d] + p] = src[t];
}

// CSR gather with fused ns-scale, nd-scale, bias, relu.  block = C4 threads, grid = Nn
__global__ void k_gather(const int* __restrict__ off, const int* __restrict__ eidx,
                         const float* __restrict__ Y, const float* __restrict__ ns,
                         const float* __restrict__ nd, const float* __restrict__ bias,
                         float* __restrict__ H, int C4, int relu) {
    int n = blockIdx.x, c = threadIdx.x;
    int s0 = off[n], s1 = off[n + 1];
    float4 acc = {0.f, 0.f, 0.f, 0.f};
    for (int i = s0; i < s1; i++) {
        int s = eidx[i];
        float w = ns[s];
        float4 v = ((const float4*)Y)[(size_t)s * C4 + c];
        acc.x += v.x * w; acc.y += v.y * w; acc.z += v.z * w; acc.w += v.w * w;
    }
    float sc = nd[n];
    float4 b = ((const float4*)bias)[c];
    float4 o;
    o.x = acc.x * sc + b.x; o.y = acc.y * sc + b.y;
    o.z = acc.z * sc + b.z; o.w = acc.w * sc + b.w;
    if (relu) {
        o.x = fmaxf(o.x, 0.f); o.y = fmaxf(o.y, 0.f);
        o.z = fmaxf(o.z, 0.f); o.w = fmaxf(o.w, 0.f);
    }
    ((float4*)H)[(size_t)n * C4 + c] = o;
}

// pack adjacency floats (0/1) into bitmask: warp per 32 cols
__global__ void k_pack(const float* __restrict__ a, unsigned* __restrict__ bits) {
    size_t w = (size_t)blockIdx.x * 8 + (threadIdx.x >> 5);
    int lane = threadIdx.x & 31;
    float v = a[w * 32 + lane];
    unsigned m = __ballot_sync(0xffffffffu, v != 0.f);
    if (lane == 0) bits[w] = m;
}

// ---------------- generic fp32 GEMM: C = A[MxK] @ B[KxN] ----------------
__global__ __launch_bounds__(256, 2)
void k_gemm_nn(const float* __restrict__ A, const float* __restrict__ B,
               float* __restrict__ C, int M, int Nc, int K) {
    __shared__ float As[32][132];
    __shared__ float Bs[32][132];
    int tid = threadIdx.x, tx = tid & 15, ty = tid >> 4;
    int r0 = blockIdx.x * 128, c0 = blockIdx.y * 128;
    int ty8 = ty * 8, tx8 = tx * 8;
    float acc[8][8] = {};
    for (int k0 = 0; k0 < K; k0 += 32) {
        for (int t = tid; t < 4096; t += 256) {
            int k = t & 31, m = t >> 5;
            As[k][m] = A[(size_t)(r0 + m) * K + k0 + k];
        }
        for (int t = tid; t < 4096; t += 256) {
            int n = t & 127, k = t >> 7;
            Bs[k][n] = B[(size_t)(k0 + k) * Nc + c0 + n];
        }
        __syncthreads();
        #pragma unroll 8
        for (int k = 0; k < 32; k++) {
            float a[8], b[8];
            #pragma unroll
            for (int i = 0; i < 8; i++) a[i] = As[k][ty8 + i];
            #pragma unroll
            for (int j = 0; j < 8; j++) b[j] = Bs[k][tx8 + j];
            #pragma unroll
            for (int i = 0; i < 8; i++)
                #pragma unroll
                for (int j = 0; j < 8; j++) acc[i][j] = fmaf(a[i], b[j], acc[i][j]);
        }
        __syncthreads();
    }
    for (int i = 0; i < 8; i++) {
        size_t r = (size_t)(r0 + ty8 + i) * Nc + c0 + tx8;
        #pragma unroll
        for (int j = 0; j < 8; j++) C[r + j] = acc[i][j];
    }
}

// C[MxN] += A^T@B over K-slice: A is [K x M] row-major, B is [K x N]
__global__ __launch_bounds__(256, 2)
void k_atb(const float* __restrict__ A, const float* __restrict__ B,
           float* __restrict__ C, int M, int Nc, int kPerSlice) {
    __shared__ float As[32][132];
    __shared__ float Bs[32][132];
    int tid = threadIdx.x, tx = tid & 15, ty = tid >> 4;
    int r0 = blockIdx.x * 128, c0 = blockIdx.y * 128;
    int kb = blockIdx.z * kPerSlice;
    int ty8 = ty * 8, tx8 = tx * 8;
    float acc[8][8] = {};
    for (int k0 = kb; k0 < kb + kPerSlice; k0 += 32) {
        for (int t = tid; t < 4096; t += 256) {
            int m = t & 127, k = t >> 7;
            As[k][m] = A[(size_t)(k0 + k) * M + r0 + m];
        }
        for (int t = tid; t < 4096; t += 256) {
            int n = t & 127, k = t >> 7;
            Bs[k][n] = B[(size_t)(k0 + k) * Nc + c0 + n];
        }
        __syncthreads();
        #pragma unroll 8
        for (int k = 0; k < 32; k++) {
            float a[8], b[8];
            #pragma unroll
            for (int i = 0; i < 8; i++) a[i] = As[k][ty8 + i];
            #pragma unroll
            for (int j = 0; j < 8; j++) b[j] = Bs[k][tx8 + j];
            #pragma unroll
            for (int i = 0; i < 8; i++)
                #pragma unroll
                for (int j = 0; j < 8; j++) acc[i][j] = fmaf(a[i], b[j], acc[i][j]);
        }
        __syncthreads();
    }
    for (int i = 0; i < 8; i++) {
        size_t r = (size_t)(r0 + ty8 + i) * Nc + c0 + tx8;
        #pragma unroll
        for (int j = 0; j < 8; j++) atomicAdd(&C[r + j], acc[i][j]);
    }
}

// ---------------- tensor-core fused contrastive loss (bitmask adjacency) ----------------
__device__ __forceinline__ unsigned int saddr(const void* p) {
    return (unsigned int)__cvta_generic_to_shared(p);
}

__global__ __launch_bounds__(256)
void k_loss_adj_h(const __half* __restrict__ Zh, const unsigned* __restrict__ bits,
                  float* __restrict__ sumG, float* __restrict__ posG) {
    extern __shared__ __half sh[];
    __half* As = sh;                  // [128][LDH]
    __half* Bs = sh + 128 * LDH;      // [128][LDH]
    const int tid = threadIdx.x;
    const int lane = tid & 31, warp = tid >> 5;
    const int wm = warp >> 1, wn = warp & 1;
    const int r0 = blockIdx.x * 128;
    const int jBeg = blockIdx.y * 4096, jEnd = jBeg + 4096;

    for (int t = tid; t < 4096; t += 256) {
        int row = t >> 5, c8 = (t & 31) * 8;
        *(float4*)&As[row * LDH + c8] =
            *(const float4*)&Zh[(size_t)(r0 + row) * Dout + c8];
    }

    const int mat = lane >> 3, r = lane & 7;
    unsigned int aBase[2], bBase[4];
    #pragma unroll
    for (int am = 0; am < 2; am++) {
        int row = wm * 32 + am * 16 + (mat & 1) * 8 + r;
        aBase[am] = saddr(&As[row * LDH + (mat >> 1) * 8]);
    }
    #pragma unroll
    for (int p = 0; p < 4; p++) {
        int row = wn * 64 + p * 16 + (mat >> 1) * 8 + r;
        bBase[p] = saddr(&Bs[row * LDH + (mat & 1) * 8]);
    }

    float rs[4] = {}, rp[4] = {};
    const int bitPos = (lane & 3) * 2;

    for (int c0 = jBeg; c0 < jEnd; c0 += 128) {
        __syncthreads();
        for (int t = tid; t < 4096; t += 256) {
            int row = t >> 5, c8 = (t & 31) * 8;
            *(float4*)&Bs[row * LDH + c8] =
                *(const float4*)&Zh[(size_t)(c0 + row) * Dout + c8];
        }
        __syncthreads();

        float acc[2][8][4] = {};
        #pragma unroll
        for (int k0 = 0; k0 < Dout; k0 += 16) {
            unsigned int a[2][4], b[4][4];
            #pragma unroll
            for (int am = 0; am < 2; am++)
                asm volatile("ldmatrix.sync.aligned.m8n8.x4.shared.b16 {%0,%1,%2,%3}, [%4];"
                    : "=r"(a[am][0]), "=r"(a[am][1]), "=r"(a[am][2]), "=r"(a[am][3])
                    : "r"(aBase[am] + k0 * 2));
            #pragma unroll
            for (int p = 0; p < 4; p++)
                asm volatile("ldmatrix.sync.aligned.m8n8.x4.shared.b16 {%0,%1,%2,%3}, [%4];"
                    : "=r"(b[p][0]), "=r"(b[p][1]), "=r"(b[p][2]), "=r"(b[p][3])
                    : "r"(bBase[p] + k0 * 2));
            #pragma unroll
            for (int am = 0; am < 2; am++)
                #pragma unroll
                for (int an = 0; an < 8; an++) {
                    int p = an >> 1, q = (an & 1) * 2;
                    asm volatile(
                        "mma.sync.aligned.m16n8k16.row.col.f32.f16.f16.f32 "
                        "{%0,%1,%2,%3}, {%4,%5,%6,%7}, {%8,%9}, {%0,%1,%2,%3};"
                        : "+f"(acc[am][an][0]), "+f"(acc[am][an][1]),
                          "+f"(acc[am][an][2]), "+f"(acc[am][an][3])
                        : "r"(a[am][0]), "r"(a[am][1]), "r"(a[am][2]), "r"(a[am][3]),
                          "r"(b[p][q]), "r"(b[p][q + 1]));
                }
        }

        // epilogue: exp + bitmask-masked row sums
        const int wbase = (c0 >> 5) + wn * 2;
        #pragma unroll
        for (int am = 0; am < 2; am++) {
            int row0 = r0 + wm * 32 + am * 16 + (lane >> 2);
            uint2 wA = *(const uint2*)&bits[(size_t)row0 * NW + wbase];
            uint2 wB = *(const uint2*)&bits[(size_t)(row0 + 8) * NW + wbase];
            #pragma unroll
            for (int an = 0; an < 8; an++) {
                unsigned ma = (an < 4) ? wA.x : wA.y;
                unsigned mb = (an < 4) ? wB.x : wB.y;
                int pos = (an & 3) * 8 + bitPos;
                float e0 = __expf(acc[am][an][0]);
                float e1 = __expf(acc[am][an][1]);
                float e2 = __expf(acc[am][an][2]);
                float e3 = __expf(acc[am][an][3]);
                rs[am * 2 + 0] += e0 + e1;
                rs[am * 2 + 1] += e2 + e3;
                if ((ma >> pos) & 1u)       rp[am * 2 + 0] += e0;
                if ((ma >> (pos + 1)) & 1u) rp[am * 2 + 0] += e1;
                if ((mb >> pos) & 1u)       rp[am * 2 + 1] += e2;
                if ((mb >> (pos + 1)) & 1u) rp[am * 2 + 1] += e3;
            }
        }
    }

    #pragma unroll
    for (int s = 0; s < 4; s++) {
        float v = rs[s], p = rp[s];
        v += __shfl_xor_sync(0xffffffffu, v, 1);
        v += __shfl_xor_sync(0xffffffffu, v, 2);
        p += __shfl_xor_sync(0xffffffffu, p, 1);
        p += __shfl_xor_sync(0xffffffffu, p, 2);
        if ((lane & 3) == 0) {
            int row = r0 + wm * 32 + (s >> 1) * 16 + (s & 1) * 8 + (lane >> 2);
            atomicAdd(&sumG[row], v);
            atomicAdd(&posG[row], p);
        }
    }
}

// fused dim-label loss (fp32: Nn x Din x Dout)
__global__ __launch_bounds__(256, 2)
void k_loss_dim(const float* __restrict__ Z, const float* __restrict__ Cn,
                const float* __restrict__ feat,
                float* __restrict__ sumG, float* __restrict__ posG) {
    __shared__ float As[32][132];
    __shared__ float Bs[32][132];
    int tid = threadIdx.x, tx = tid & 15, ty = tid >> 4;
    int r0 = blockIdx.x * 128;
    int c0 = blockIdx.y * 128;
    int ty8 = ty * 8, tx8 = tx * 8;
    float acc[8][8] = {};
    for (int k0 = 0; k0 < Dout; k0 += 32) {
        for (int t = tid; t < 4096; t += 256) {
            int k = t & 31, m = t >> 5;
            As[k][m] = Z[(size_t)(r0 + m) * Dout + k0 + k];
        }
        for (int t = tid; t < 4096; t += 256) {
            int k = t & 31, m = t >> 5;
            Bs[k][m] = Cn[(size_t)(c0 + m) * Dout + k0 + k];
        }
        __syncthreads();
        #pragma unroll 8
        for (int k = 0; k < 32; k++) {
            float a[8], b[8];
            #pragma unroll
            for (int i = 0; i < 8; i++) a[i] = As[k][ty8 + i];
            #pragma unroll
            for (int j = 0; j < 8; j++) b[j] = Bs[k][tx8 + j];
            #pragma unroll
            for (int i = 0; i < 8; i++)
                #pragma unroll
                for (int j = 0; j < 8; j++) acc[i][j] = fmaf(a[i], b[j], acc[i][j]);
        }
        __syncthreads();
    }
    for (int i = 0; i < 8; i++) {
        int rr = r0 + ty8 + i;
        const float* frow = feat + (size_t)rr * Din + c0 + tx8;
        float sA = 0.f, pA = 0.f;
        #pragma unroll
        for (int j = 0; j < 8; j++) {
            float e = __expf(acc[i][j]);
            sA += e;
            if (frow[j] > 0.f) pA += e;
        }
        atomicAdd(&sumG[rr], sA);
        atomicAdd(&posG[rr], pA);
    }
}

__global__ void k_rowloss(const float* __restrict__ sumG, const float* __restrict__ posG,
                          float* loss, int mode) {
    __shared__ float red[256];
    int t = blockIdx.x * 256 + threadIdx.x;
    float term = 0.f;
    if (t < Nn) {
        float pos = posG[t], tot = sumG[t];
        float neg = tot - pos;
        if (mode == 0) term = -logf((pos + 1e-10f) / (neg + 1e-10f));
        else           term = -logf((pos + 1e-10f) / neg + 1e-5f);
    }
    red[threadIdx.x] = term;
    __syncthreads();
    for (int s = 128; s; s >>= 1) {
        if (threadIdx.x < s) red[threadIdx.x] += red[threadIdx.x + s];
        __syncthreads();
    }
    if (threadIdx.x == 0) atomicAdd(loss, red[0]);
}

// ---------------- attention fuse + norms + centers ----------------
__global__ void k_attention(const float* __restrict__ Wp1, const float* __restrict__ bp1,
                            const float* __restrict__ wp2) {
    int nid = blockIdx.x * 256 + threadIdx.x;
    if (nid >= Nn) return;
    const float* hx = g_Hx + (size_t)nid * Dout;
    const float* ha = g_Hadj + (size_t)nid * Dout;
    float accx[AH], acca[AH];
    #pragma unroll
    for (int h = 0; h < AH; h++) { accx[h] = bp1[h]; acca[h] = bp1[h]; }
    for (int d = 0; d < Dout; d++) {
        float vx = hx[d], va = ha[d];
        #pragma unroll
        for (int h = 0; h < AH; h++) {
            float w = Wp1[d * AH + h];
            accx[h] += vx * w; acca[h] += va * w;
        }
    }
    float wx = 0.f, wa = 0.f;
    #pragma unroll
    for (int h = 0; h < AH; h++) {
        wx += tanhf(accx[h]) * wp2[h];
        wa += tanhf(acca[h]) * wp2[h];
    }
    float m = fmaxf(wx, wa);
    float ex = __expf(wx - m), ea = __expf(wa - m);
    float inv = 1.f / (ex + ea);
    float bx = ex * inv, ba = ea * inv;
    float* out = g_Hf + (size_t)nid * Dout;
    for (int d = 0; d < Dout; d++) out[d] = bx * hx[d] + ba * ha[d];
}

__global__ void k_l2norm(const float* __restrict__ in, __half* __restrict__ outH,
                         float* __restrict__ outF, int rows, int cols) {
    int w = (blockIdx.x * blockDim.x + threadIdx.x) >> 5;
    int lane = threadIdx.x & 31;
    if (w >= rows) return;
    const float* r = in + (size_t)w * cols;
    float ss = 0.f;
    for (int c = lane; c < cols; c += 32) { float v = r[c]; ss += v * v; }
    for (int o = 16; o; o >>= 1) ss += __shfl_xor_sync(0xffffffffu, ss, o);
    float inv = 1.f / fmaxf(sqrtf(ss), 1e-12f);
    __half* wh = outH + (size_t)w * cols;
    for (int c = lane; c < cols; c += 32) {
        float v = r[c] * inv;
        wh[c] = __float2half(v);
        if (outF) outF[(size_t)w * cols + c] = v;
    }
}

__global__ void k_colsum(const float* __restrict__ feat) {
    int c = blockIdx.x * 256 + threadIdx.x;
    int rbeg = blockIdx.y * 128;
    float s = 0.f;
    for (int i = rbeg; i < rbeg + 128; i++) s += feat[(size_t)i * Din + c];
    atomicAdd(&g_colsum[c], s);
}

__global__ void k_center() {
    int w = (blockIdx.x * blockDim.x + threadIdx.x) >> 5;
    int lane = threadIdx.x & 31;
    if (w >= Din) return;
    float s = g_colsum[w] + 1e-5f;
    float inv_s = 1.f / s;
    float v[8]; float ss = 0.f;
    #pragma unroll
    for (int i = 0; i < 8; i++) {
        v[i] = g_dcraw[(size_t)w * Dout + lane + 32 * i] * inv_s;
        ss += v[i] * v[i];
    }
    for (int o = 16; o; o >>= 1) ss += __shfl_xor_sync(0xffffffffu, ss, o);
    float inv = 1.f / fmaxf(sqrtf(ss), 1e-12f);
    #pragma unroll
    for (int i = 0; i < 8; i++) g_Cn[(size_t)w * Dout + lane + 32 * i] = v[i] * inv;
}

__global__ void k_final(float* out) {
    out[0] = (0.5f * (g_loss[0] + g_loss[1]) + 0.1f * g_loss[2] + g_loss[3]) * (1.0f / Nn);
}

// ---------------- host ----------------
extern "C" void kernel_launch(void* const* d_in, const int* in_sizes, int n_in,
                              void* d_out, int out_size) {
    const float* feat = (const float*)d_in[0];
    const float* adjL = (const float*)d_in[1];
    const float* adjX = (const float*)d_in[2];
    const float* adjR = (const float*)d_in[3];

    const int *eA, *eX; int pb;
    if (in_sizes[5] == 262144) { eA = (const int*)d_in[4]; eX = (const int*)d_in[5]; pb = 6; }
    else                       { pb = 4; eA = (const int*)d_in[15]; eX = (const int*)d_in[16]; }

    const float* W0a = (const float*)d_in[pb + 0];
    const float* b0a = (const float*)d_in[pb + 1];
    const float* W1a = (const float*)d_in[pb + 2];
    const float* b1a = (const float*)d_in[pb + 3];
    const float* W0x = (const float*)d_in[pb + 4];
    const float* b0x = (const float*)d_in[pb + 5];
    const float* W1x = (const float*)d_in[pb + 6];
    const float* b1x = (const float*)d_in[pb + 7];
    const float* Wp1 = (const float*)d_in[pb + 8];
    const float* bp1 = (const float*)d_in[pb + 9];
    const float* wp2 = (const float*)d_in[pb + 10];

    static int smemSet = 0;
    const int LOSS_SMEM = 2 * 128 * LDH * (int)sizeof(__half);
    if (!smemSet) {
        cudaFuncSetAttribute(k_loss_adj_h, cudaFuncAttributeMaxDynamicSharedMemorySize, LOSS_SMEM);
        smemSet = 1;
    }

    void *pY, *pH1, *pHadj, *pHx, *pHf, *pZf, *pZah, *pZxh, *pZfh;
    void *pDeg, *pNrm, *pOff, *pCur, *pEidx, *pBits;
    void *pDc, *pCn, *pCs, *pSum, *pPos, *pLoss;
    cudaGetSymbolAddress(&pY, g_Y);       cudaGetSymbolAddress(&pH1, g_H1);
    cudaGetSymbolAddress(&pHadj, g_Hadj); cudaGetSymbolAddress(&pHx, g_Hx);
    cudaGetSymbolAddress(&pHf, g_Hf);     cudaGetSymbolAddress(&pZf, g_Zf);
    cudaGetSymbolAddress(&pZah, g_Zah);   cudaGetSymbolAddress(&pZxh, g_Zxh);
    cudaGetSymbolAddress(&pZfh, g_Zfh);   cudaGetSymbolAddress(&pDeg, g_deg);
    cudaGetSymbolAddress(&pNrm, g_nrm);   cudaGetSymbolAddress(&pOff, g_off);
    cudaGetSymbolAddress(&pCur, g_cursor);cudaGetSymbolAddress(&pEidx, g_eidx);
    cudaGetSymbolAddress(&pBits, g_bits); cudaGetSymbolAddress(&pDc, g_dcraw);
    cudaGetSymbolAddress(&pCn, g_Cn);     cudaGetSymbolAddress(&pCs, g_colsum);
    cudaGetSymbolAddress(&pSum, g_sum);   cudaGetSymbolAddress(&pPos, g_pos);
    cudaGetSymbolAddress(&pLoss, g_loss);

    float* deg = (float*)pDeg;
    float* nrm = (float*)pNrm;
    float* nsA = nrm;           float* ndA = nrm + Nn;
    float* nsX = nrm + 2 * Nn;  float* ndX = nrm + 3 * Nn;
    int* offA = (int*)pOff;     int* offX = offA + (Nn + 1);
    int* eidxA = (int*)pEidx;   int* eidxX = eidxA + Ne;
    unsigned* bitsL = (unsigned*)pBits;
    unsigned* bitsX = bitsL + (size_t)Nn * NW;
    unsigned* bitsR = bitsX + (size_t)Nn * NW;
    float* sum = (float*)pSum;  float* pos = (float*)pPos;
    float* loss = (float*)pLoss;

    // ---- graph preprocessing ----
    cudaMemsetAsync(pDeg, 0, 4 * Nn * sizeof(float));
    cudaMemsetAsync(pCur, 0, 2 * Nn * sizeof(int));
    k_degree<<<(Ne + 255) / 256, 256>>>(eA, eA + Ne, deg, deg + Nn);
    k_degree<<<(Ne + 255) / 256, 256>>>(eX, eX + Ne, deg + 2 * Nn, deg + 3 * Nn);
    k_norm<<<(4 * Nn) / 256, 256>>>();
    k_scan<<<1, 1024>>>(deg + Nn, offA);
    k_scan<<<1, 1024>>>(deg + 3 * Nn, offX);
    k_bucket<<<(Ne + 255) / 256, 256>>>(eA, eA + Ne, offA, (int*)pCur, eidxA);
    k_bucket<<<(Ne + 255) / 256, 256>>>(eX, eX + Ne, offX, (int*)pCur + Nn, eidxX);

    // ---- pack adjacencies into bitmasks ----
    const int packBlocks = (Nn * NW) / 8;   // warps total / 8 per block
    k_pack<<<packBlocks, 256>>>(adjL, bitsL);
    k_pack<<<packBlocks, 256>>>(adjX, bitsX);
    k_pack<<<packBlocks, 256>>>(adjR, bitsR);

    // ---- GCN over graph A ----
    k_gemm_nn<<<dim3(Nn / 128, Din / 128), 256>>>(feat, W0a, (float*)pY, Nn, Din, Din);
    k_gather<<<Nn, Din / 4>>>(offA, eidxA, (float*)pY, nsA, ndA, b0a, (float*)pH1, Din / 4, 1);
    k_gemm_nn<<<dim3(Nn / 128, Dout / 128), 256>>>((float*)pH1, W1a, (float*)pY, Nn, Dout, Din);
    k_gather<<<Nn, Dout / 4>>>(offA, eidxA, (float*)pY, nsA, ndA, b1a, (float*)pHadj, Dout / 4, 0);

    // ---- GCN over graph X ----
    k_gemm_nn<<<dim3(Nn / 128, Din / 128), 256>>>(feat, W0x, (float*)pY, Nn, Din, Din);
    k_gather<<<Nn, Din / 4>>>(offX, eidxX, (float*)pY, nsX, ndX, b0x, (float*)pH1, Din / 4, 1);
    k_gemm_nn<<<dim3(Nn / 128, Dout / 128), 256>>>((float*)pH1, W1x, (float*)pY, Nn, Dout, Din);
    k_gather<<<Nn, Dout / 4>>>(offX, eidxX, (float*)pY, nsX, ndX, b1x, (float*)pHx, Dout / 4, 0);

    // ---- attention fusion + normalization ----
    k_attention<<<Nn / 256, 256>>>(Wp1, bp1, wp2);
    k_l2norm<<<Nn / 8, 256>>>((float*)pHadj, (__half*)pZah, nullptr, Nn, Dout);
    k_l2norm<<<Nn / 8, 256>>>((float*)pHx,   (__half*)pZxh, nullptr, Nn, Dout);
    k_l2norm<<<Nn / 8, 256>>>((float*)pHf,   (__half*)pZfh, (float*)pZf, Nn, Dout);

    // ---- dim_center ----
    cudaMemsetAsync(pCs, 0, Din * sizeof(float));
    k_colsum<<<dim3(2, 64), 256>>>(feat);
    cudaMemsetAsync(pDc, 0, (size_t)Din * Dout * sizeof(float));
    k_atb<<<dim3(Din / 128, Dout / 128, 32), 256>>>(feat, (float*)pHf, (float*)pDc, Din, Dout, Nn / 32);
    k_center<<<Din / 8, 256>>>();

    // ---- losses ----
    cudaMemsetAsync(pSum, 0, 4 * Nn * sizeof(float));
    cudaMemsetAsync(pPos, 0, 4 * Nn * sizeof(float));
    cudaMemsetAsync(pLoss, 0, 4 * sizeof(float));
    k_loss_adj_h<<<dim3(Nn / 128, 2), 256, LOSS_SMEM>>>((const __half*)pZah, bitsL, sum,          pos);
    k_loss_adj_h<<<dim3(Nn / 128, 2), 256, LOSS_SMEM>>>((const __half*)pZxh, bitsX, sum + Nn,     pos + Nn);
    k_loss_dim<<<dim3(Nn / 128, Din / 128), 256>>>((float*)pZf, (float*)pCn, feat,
                                                   sum + 2 * Nn, pos + 2 * Nn);
    k_loss_adj_h<<<dim3(Nn / 128, 2), 256, LOSS_SMEM>>>((const __half*)pZfh, bitsR, sum + 3 * Nn, pos + 3 * Nn);

    k_rowloss<<<Nn / 256, 256>>>(sum,          pos,          loss + 0, 0);
    k_rowloss<<<Nn / 256, 256>>>(sum + Nn,     pos + Nn,     loss + 1, 0);
    k_rowloss<<<Nn / 256, 256>>>(sum + 2 * Nn, pos + 2 * Nn, loss + 2, 1);
    k_rowloss<<<Nn / 256, 256>>>(sum + 3 * Nn, pos + 3 * Nn, loss + 3, 0);

    k_final<<<1, 1>>>((float*)d_out);
}

// round 6
// speedup vs baseline: 3.1812x; 1.3119x over previous
#include <cuda_runtime.h>
#include <cuda_fp16.h>
#include <cstdint>
#include <math.h>

#define Nn   8192
#define Din  512
#define Dout 256
#define Ne   131072
#define AH   16
#define LDH  264   // loss smem stride (halves): 528B, conflict-free ldmatrix
#define NW   256   // bitmask words per row
#define LDK  72    // gemm_h chunk stride (halves): 144B, conflict-free ldmatrix

// ---------------- static scratch ----------------
static __device__ float g_Y[Nn*Din];
static __device__ float g_H1[Nn*Din];
static __device__ float g_Hadj[Nn*Dout];
static __device__ float g_Hx[Nn*Dout];
static __device__ float g_Hf[Nn*Dout];
static __device__ float g_Zf[Nn*Dout];
static __device__ __half g_featH[Nn*Din];
static __device__ __half g_H1h[Nn*Din];
static __device__ __half g_Zah[Nn*Dout];
static __device__ __half g_Zxh[Nn*Dout];
static __device__ __half g_Zfh[Nn*Dout];
static __device__ __half g_Wt[2*(Din*Din + Din*Dout)];   // W0a^T, W1a^T, W0x^T, W1x^T (half)
static __device__ float g_deg[4*Nn];
static __device__ float g_nrm[4*Nn];
static __device__ int   g_off[2*(Nn+1)];
static __device__ int   g_cursor[2*Nn];
static __device__ int   g_eidx[2*Ne];
static __device__ unsigned g_bits[3u*Nn*NW];
static __device__ float g_dcraw[Din*Dout];
static __device__ float g_Cn[Din*Dout];
static __device__ float g_colsum[Din];
static __device__ float g_sum[4*Nn];
static __device__ float g_pos[4*Nn];
static __device__ float g_loss[4];

__device__ __forceinline__ unsigned int saddr(const void* p) {
    return (unsigned int)__cvta_generic_to_shared(p);
}
__device__ __forceinline__ void cpasync16(unsigned int dst, const void* src) {
    asm volatile("cp.async.cg.shared.global [%0], [%1], 16;" :: "r"(dst), "l"(src));
}
__device__ __forceinline__ void cpcommit() { asm volatile("cp.async.commit_group;"); }
__device__ __forceinline__ void cpwait0()  { asm volatile("cp.async.wait_group 0;"); }

// ---------------- graph preprocessing ----------------
__global__ void k_degree(const int* __restrict__ src, const int* __restrict__ dst,
                         float* degO, float* degI) {
    int t = blockIdx.x * 256 + threadIdx.x;
    if (t < Ne) { atomicAdd(degO + src[t], 1.f); atomicAdd(degI + dst[t], 1.f); }
}

__global__ void k_norm() {
    int t = blockIdx.x * 256 + threadIdx.x;
    if (t < 4 * Nn) { float d = g_deg[t]; g_nrm[t] = (d > 0.f) ? rsqrtf(d) : 0.f; }
}

__global__ void k_scan(const float* __restrict__ degIn, int* __restrict__ off) {
    __shared__ int part[1024];
    int t = threadIdx.x;
    int v[8]; int s = 0;
    #pragma unroll
    for (int i = 0; i < 8; i++) { v[i] = s; s += (int)degIn[t * 8 + i]; }
    part[t] = s;
    __syncthreads();
    for (int d = 1; d < 1024; d <<= 1) {
        int x = (t >= d) ? part[t - d] : 0;
        __syncthreads();
        part[t] += x;
        __syncthreads();
    }
    int base = (t > 0) ? part[t - 1] : 0;
    #pragma unroll
    for (int i = 0; i < 8; i++) off[t * 8 + i] = base + v[i];
    if (t == 1023) off[Nn] = part[1023];
}

__global__ void k_bucket(const int* __restrict__ src, const int* __restrict__ dst,
                         const int* __restrict__ off, int* __restrict__ cursor,
                         int* __restrict__ eidx) {
    int t = blockIdx.x * 256 + threadIdx.x;
    if (t >= Ne) return;
    int d = dst[t];
    int p = atomicAdd(&cursor[d], 1);
    eidx[off[d] + p] = src[t];
}

__global__ void k_gather(const int* __restrict__ off, const int* __restrict__ eidx,
                         const float* __restrict__ Y, const float* __restrict__ ns,
                         const float* __restrict__ nd, const float* __restrict__ bias,
                         float* __restrict__ H, int C4, int relu) {
    int n = blockIdx.x, c = threadIdx.x;
    int s0 = off[n], s1 = off[n + 1];
    float4 acc = {0.f, 0.f, 0.f, 0.f};
    for (int i = s0; i < s1; i++) {
        int s = eidx[i];
        float w = ns[s];
        float4 v = ((const float4*)Y)[(size_t)s * C4 + c];
        acc.x += v.x * w; acc.y += v.y * w; acc.z += v.z * w; acc.w += v.w * w;
    }
    float sc = nd[n];
    float4 b = ((const float4*)bias)[c];
    float4 o;
    o.x = acc.x * sc + b.x; o.y = acc.y * sc + b.y;
    o.z = acc.z * sc + b.z; o.w = acc.w * sc + b.w;
    if (relu) {
        o.x = fmaxf(o.x, 0.f); o.y = fmaxf(o.y, 0.f);
        o.z = fmaxf(o.z, 0.f); o.w = fmaxf(o.w, 0.f);
    }
    ((float4*)H)[(size_t)n * C4 + c] = o;
}

__global__ void k_pack(const float* __restrict__ a, unsigned* __restrict__ bits) {
    size_t w = (size_t)blockIdx.x * 8 + (threadIdx.x >> 5);
    int lane = threadIdx.x & 31;
    float v = __ldcs(&a[w * 32 + lane]);
    unsigned m = __ballot_sync(0xffffffffu, v != 0.f);
    if (lane == 0) bits[w] = m;
}

// ---------------- conversions ----------------
__global__ void k_f2h(const float* __restrict__ in, __half* __restrict__ out, int n4) {
    int i = blockIdx.x * 256 + threadIdx.x;
    if (i >= n4) return;
    float4 v = ((const float4*)in)[i];
    __half2 h0 = __floats2half2_rn(v.x, v.y);
    __half2 h1 = __floats2half2_rn(v.z, v.w);
    ((__half2*)out)[i * 2 + 0] = h0;
    ((__half2*)out)[i * 2 + 1] = h1;
}

// W[K,N] fp32 -> Wt[N,K] half
__global__ void k_wth(const float* __restrict__ W, __half* __restrict__ Wt, int K, int N) {
    int i = blockIdx.x * 256 + threadIdx.x;
    if (i >= K * N) return;
    int k = i / N, n = i % N;
    Wt[(size_t)n * K + k] = __float2half(W[i]);
}

// ---------------- fp16 tensor-core GEMM: C = A[MxK] @ Bt[NcxK]^T, fp32 out ----------------
// double-buffered cp.async, K chunked by 64
__global__ __launch_bounds__(256)
void k_gemm_h(const __half* __restrict__ A, const __half* __restrict__ Bt,
              float* __restrict__ C, int Nc, int K) {
    extern __shared__ __half sg[];
    __half* As = sg;                     // [2][128][LDK]
    __half* Bs = sg + 2 * 128 * LDK;     // [2][128][LDK]
    const int BUF = 128 * LDK;
    const int tid = threadIdx.x;
    const int lane = tid & 31, warp = tid >> 5;
    const int wm = warp >> 1, wn = warp & 1;
    const int r0 = blockIdx.x * 128, c0 = blockIdx.y * 128;

    const int mat = lane >> 3, r = lane & 7;
    unsigned int aB[2], bB[4];
    #pragma unroll
    for (int am = 0; am < 2; am++) {
        int row = wm * 32 + am * 16 + (mat & 1) * 8 + r;
        aB[am] = saddr(&As[row * LDK + (mat >> 1) * 8]);
    }
    #pragma unroll
    for (int p = 0; p < 4; p++) {
        int row = wn * 64 + p * 16 + (mat >> 1) * 8 + r;
        bB[p] = saddr(&Bs[row * LDK + (mat & 1) * 8]);
    }

    float acc[2][8][4] = {};
    const int nch = K / 64;

    // prefetch chunk 0 into buf 0
    #pragma unroll
    for (int i = 0; i < 4; i++) {
        int idx = tid + i * 256;
        int row = idx >> 3, c8 = (idx & 7) * 8;
        cpasync16(saddr(&As[row * LDK + c8]), &A[(size_t)(r0 + row) * K + c8]);
        cpasync16(saddr(&Bs[row * LDK + c8]), &Bt[(size_t)(c0 + row) * K + c8]);
    }
    cpcommit();

    for (int ch = 0; ch < nch; ch++) {
        int p = ch & 1;
        cpwait0();
        __syncthreads();
        if (ch + 1 < nch) {
            int np = 1 - p, k0g = (ch + 1) * 64;
            #pragma unroll
            for (int i = 0; i < 4; i++) {
                int idx = tid + i * 256;
                int row = idx >> 3, c8 = (idx & 7) * 8;
                cpasync16(saddr(&As[np * BUF + row * LDK + c8]),
                          &A[(size_t)(r0 + row) * K + k0g + c8]);
                cpasync16(saddr(&Bs[np * BUF + row * LDK + c8]),
                          &Bt[(size_t)(c0 + row) * K + k0g + c8]);
            }
            cpcommit();
        }
        const unsigned int bufOff = p * BUF * 2;   // byte offset of active buffer
        #pragma unroll
        for (int k0 = 0; k0 < 64; k0 += 16) {
            unsigned int a[2][4], b[4][4];
            #pragma unroll
            for (int am = 0; am < 2; am++)
                asm volatile("ldmatrix.sync.aligned.m8n8.x4.shared.b16 {%0,%1,%2,%3}, [%4];"
                    : "=r"(a[am][0]), "=r"(a[am][1]), "=r"(a[am][2]), "=r"(a[am][3])
                    : "r"(aB[am] + bufOff + k0 * 2));
            #pragma unroll
            for (int q = 0; q < 4; q++)
                asm volatile("ldmatrix.sync.aligned.m8n8.x4.shared.b16 {%0,%1,%2,%3}, [%4];"
                    : "=r"(b[q][0]), "=r"(b[q][1]), "=r"(b[q][2]), "=r"(b[q][3])
                    : "r"(bB[q] + bufOff + k0 * 2));
            #pragma unroll
            for (int am = 0; am < 2; am++)
                #pragma unroll
                for (int an = 0; an < 8; an++) {
                    int q = an >> 1, s = (an & 1) * 2;
                    asm volatile(
                        "mma.sync.aligned.m16n8k16.row.col.f32.f16.f16.f32 "
                        "{%0,%1,%2,%3}, {%4,%5,%6,%7}, {%8,%9}, {%0,%1,%2,%3};"
                        : "+f"(acc[am][an][0]), "+f"(acc[am][an][1]),
                          "+f"(acc[am][an][2]), "+f"(acc[am][an][3])
                        : "r"(a[am][0]), "r"(a[am][1]), "r"(a[am][2]), "r"(a[am][3]),
                          "r"(b[q][s]), "r"(b[q][s + 1]));
                }
        }
        __syncthreads();
    }

    #pragma unroll
    for (int am = 0; am < 2; am++) {
        int row = r0 + wm * 32 + am * 16 + (lane >> 2);
        #pragma unroll
        for (int an = 0; an < 8; an++) {
            int col = c0 + wn * 64 + an * 8 + (lane & 3) * 2;
            *(float2*)&C[(size_t)row * Nc + col] =
                make_float2(acc[am][an][0], acc[am][an][1]);
            *(float2*)&C[(size_t)(row + 8) * Nc + col] =
                make_float2(acc[am][an][2], acc[am][an][3]);
        }
    }
}

// ---------------- tensor-core fused contrastive loss (double-buffered) ----------------
__global__ __launch_bounds__(256)
void k_loss_adj_h(const __half* __restrict__ Zh, const unsigned* __restrict__ bits,
                  float* __restrict__ sumG, float* __restrict__ posG) {
    extern __shared__ __half sh[];
    __half* As = sh;                       // [128][LDH]
    __half* Bs = sh + 128 * LDH;           // [2][128][LDH]
    const int BUFB = 128 * LDH * 2;        // bytes per B buffer
    const int tid = threadIdx.x;
    const int lane = tid & 31, warp = tid >> 5;
    const int wm = warp >> 1, wn = warp & 1;
    const int r0 = blockIdx.x * 128;
    const int jBeg = blockIdx.y * 4096, jEnd = jBeg + 4096;

    for (int t = tid; t < 4096; t += 256) {
        int row = t >> 5, c8 = (t & 31) * 8;
        *(float4*)&As[row * LDH + c8] =
            *(const float4*)&Zh[(size_t)(r0 + row) * Dout + c8];
    }

    const int mat = lane >> 3, r = lane & 7;
    unsigned int aBase[2], bBase[4];
    #pragma unroll
    for (int am = 0; am < 2; am++) {
        int row = wm * 32 + am * 16 + (mat & 1) * 8 + r;
        aBase[am] = saddr(&As[row * LDH + (mat >> 1) * 8]);
    }
    #pragma unroll
    for (int p = 0; p < 4; p++) {
        int row = wn * 64 + p * 16 + (mat >> 1) * 8 + r;
        bBase[p] = saddr(&Bs[row * LDH + (mat & 1) * 8]);
    }

    float rs[4] = {}, rp[4] = {};
    const int bitPos = (lane & 3) * 2;

    // prefetch first B tile into buf 0
    #pragma unroll
    for (int i = 0; i < 16; i++) {
        int idx = tid + i * 256;
        int row = idx >> 5, c8 = (idx & 31) * 8;
        cpasync16(saddr(&Bs[row * LDH + c8]),
                  &Zh[(size_t)(jBeg + row) * Dout + c8]);
    }
    cpcommit();

    int pbuf = 0;
    for (int c0 = jBeg; c0 < jEnd; c0 += 128) {
        cpwait0();
        __syncthreads();
        if (c0 + 128 < jEnd) {
            int np = 1 - pbuf;
            #pragma unroll
            for (int i = 0; i < 16; i++) {
                int idx = tid + i * 256;
                int row = idx >> 5, c8 = (idx & 31) * 8;
                cpasync16(saddr(&Bs[np * 128 * LDH + row * LDH + c8]),
                          &Zh[(size_t)(c0 + 128 + row) * Dout + c8]);
            }
            cpcommit();
        }
        const unsigned int bOff = pbuf * BUFB;

        float acc[2][8][4] = {};
        #pragma unroll
        for (int k0 = 0; k0 < Dout; k0 += 16) {
            unsigned int a[2][4], b[4][4];
            #pragma unroll
            for (int am = 0; am < 2; am++)
                asm volatile("ldmatrix.sync.aligned.m8n8.x4.shared.b16 {%0,%1,%2,%3}, [%4];"
                    : "=r"(a[am][0]), "=r"(a[am][1]), "=r"(a[am][2]), "=r"(a[am][3])
                    : "r"(aBase[am] + k0 * 2));
            #pragma unroll
            for (int p = 0; p < 4; p++)
                asm volatile("ldmatrix.sync.aligned.m8n8.x4.shared.b16 {%0,%1,%2,%3}, [%4];"
                    : "=r"(b[p][0]), "=r"(b[p][1]), "=r"(b[p][2]), "=r"(b[p][3])
                    : "r"(bBase[p] + bOff + k0 * 2));
            #pragma unroll
            for (int am = 0; am < 2; am++)
                #pragma unroll
                for (int an = 0; an < 8; an++) {
                    int p = an >> 1, q = (an & 1) * 2;
                    asm volatile(
                        "mma.sync.aligned.m16n8k16.row.col.f32.f16.f16.f32 "
                        "{%0,%1,%2,%3}, {%4,%5,%6,%7}, {%8,%9}, {%0,%1,%2,%3};"
                        : "+f"(acc[am][an][0]), "+f"(acc[am][an][1]),
                          "+f"(acc[am][an][2]), "+f"(acc[am][an][3])
                        : "r"(a[am][0]), "r"(a[am][1]), "r"(a[am][2]), "r"(a[am][3]),
                          "r"(b[p][q]), "r"(b[p][q + 1]));
                }
        }

        const int wbase = (c0 >> 5) + wn * 2;
        #pragma unroll
        for (int am = 0; am < 2; am++) {
            int row0 = r0 + wm * 32 + am * 16 + (lane >> 2);
            uint2 wA = *(const uint2*)&bits[(size_t)row0 * NW + wbase];
            uint2 wB = *(const uint2*)&bits[(size_t)(row0 + 8) * NW + wbase];
            #pragma unroll
            for (int an = 0; an < 8; an++) {
                unsigned ma = (an < 4) ? wA.x : wA.y;
                unsigned mb = (an < 4) ? wB.x : wB.y;
                int pos = (an & 3) * 8 + bitPos;
                float e0 = __expf(acc[am][an][0]);
                float e1 = __expf(acc[am][an][1]);
                float e2 = __expf(acc[am][an][2]);
                float e3 = __expf(acc[am][an][3]);
                rs[am * 2 + 0] += e0 + e1;
                rs[am * 2 + 1] += e2 + e3;
                if ((ma >> pos) & 1u)       rp[am * 2 + 0] += e0;
                if ((ma >> (pos + 1)) & 1u) rp[am * 2 + 0] += e1;
                if ((mb >> pos) & 1u)       rp[am * 2 + 1] += e2;
                if ((mb >> (pos + 1)) & 1u) rp[am * 2 + 1] += e3;
            }
        }
        pbuf ^= 1;
    }

    #pragma unroll
    for (int s = 0; s < 4; s++) {
        float v = rs[s], p = rp[s];
        v += __shfl_xor_sync(0xffffffffu, v, 1);
        v += __shfl_xor_sync(0xffffffffu, v, 2);
        p += __shfl_xor_sync(0xffffffffu, p, 1);
        p += __shfl_xor_sync(0xffffffffu, p, 2);
        if ((lane & 3) == 0) {
            int row = r0 + wm * 32 + (s >> 1) * 16 + (s & 1) * 8 + (lane >> 2);
            atomicAdd(&sumG[row], v);
            atomicAdd(&posG[row], p);
        }
    }
}

// C[MxN] += A^T@B over K-slice (fp32, for dim_center)
__global__ __launch_bounds__(256, 2)
void k_atb(const float* __restrict__ A, const float* __restrict__ B,
           float* __restrict__ C, int M, int Nc, int kPerSlice) {
    __shared__ float As[32][132];
    __shared__ float Bs[32][132];
    int tid = threadIdx.x, tx = tid & 15, ty = tid >> 4;
    int r0 = blockIdx.x * 128, c0 = blockIdx.y * 128;
    int kb = blockIdx.z * kPerSlice;
    int ty8 = ty * 8, tx8 = tx * 8;
    float acc[8][8] = {};
    for (int k0 = kb; k0 < kb + kPerSlice; k0 += 32) {
        for (int t = tid; t < 4096; t += 256) {
            int m = t & 127, k = t >> 7;
            As[k][m] = A[(size_t)(k0 + k) * M + r0 + m];
        }
        for (int t = tid; t < 4096; t += 256) {
            int n = t & 127, k = t >> 7;
            Bs[k][n] = B[(size_t)(k0 + k) * Nc + c0 + n];
        }
        __syncthreads();
        #pragma unroll 8
        for (int k = 0; k < 32; k++) {
            float a[8], b[8];
            #pragma unroll
            for (int i = 0; i < 8; i++) a[i] = As[k][ty8 + i];
            #pragma unroll
            for (int j = 0; j < 8; j++) b[j] = Bs[k][tx8 + j];
            #pragma unroll
            for (int i = 0; i < 8; i++)
                #pragma unroll
                for (int j = 0; j < 8; j++) acc[i][j] = fmaf(a[i], b[j], acc[i][j]);
        }
        __syncthreads();
    }
    for (int i = 0; i < 8; i++) {
        size_t r = (size_t)(r0 + ty8 + i) * Nc + c0 + tx8;
        #pragma unroll
        for (int j = 0; j < 8; j++) atomicAdd(&C[r + j], acc[i][j]);
    }
}

// fused dim-label loss (fp32)
__global__ __launch_bounds__(256, 2)
void k_loss_dim(const float* __restrict__ Z, const float* __restrict__ Cn,
                const float* __restrict__ feat,
                float* __restrict__ sumG, float* __restrict__ posG) {
    __shared__ float As[32][132];
    __shared__ float Bs[32][132];
    int tid = threadIdx.x, tx = tid & 15, ty = tid >> 4;
    int r0 = blockIdx.x * 128;
    int c0 = blockIdx.y * 128;
    int ty8 = ty * 8, tx8 = tx * 8;
    float acc[8][8] = {};
    for (int k0 = 0; k0 < Dout; k0 += 32) {
        for (int t = tid; t < 4096; t += 256) {
            int k = t & 31, m = t >> 5;
            As[k][m] = Z[(size_t)(r0 + m) * Dout + k0 + k];
        }
        for (int t = tid; t < 4096; t += 256) {
            int k = t & 31, m = t >> 5;
            Bs[k][m] = Cn[(size_t)(c0 + m) * Dout + k0 + k];
        }
        __syncthreads();
        #pragma unroll 8
        for (int k = 0; k < 32; k++) {
            float a[8], b[8];
            #pragma unroll
            for (int i = 0; i < 8; i++) a[i] = As[k][ty8 + i];
            #pragma unroll
            for (int j = 0; j < 8; j++) b[j] = Bs[k][tx8 + j];
            #pragma unroll
            for (int i = 0; i < 8; i++)
                #pragma unroll
                for (int j = 0; j < 8; j++) acc[i][j] = fmaf(a[i], b[j], acc[i][j]);
        }
        __syncthreads();
    }
    for (int i = 0; i < 8; i++) {
        int rr = r0 + ty8 + i;
        const float* frow = feat + (size_t)rr * Din + c0 + tx8;
        float sA = 0.f, pA = 0.f;
        #pragma unroll
        for (int j = 0; j < 8; j++) {
            float e = __expf(acc[i][j]);
            sA += e;
            if (frow[j] > 0.f) pA += e;
        }
        atomicAdd(&sumG[rr], sA);
        atomicAdd(&posG[rr], pA);
    }
}

__global__ void k_rowloss(const float* __restrict__ sumG, const float* __restrict__ posG,
                          float* loss, int mode) {
    __shared__ float red[256];
    int t = blockIdx.x * 256 + threadIdx.x;
    float term = 0.f;
    if (t < Nn) {
        float pos = posG[t], tot = sumG[t];
        float neg = tot - pos;
        if (mode == 0) term = -logf((pos + 1e-10f) / (neg + 1e-10f));
        else           term = -logf((pos + 1e-10f) / neg + 1e-5f);
    }
    red[threadIdx.x] = term;
    __syncthreads();
    for (int s = 128; s; s >>= 1) {
        if (threadIdx.x < s) red[threadIdx.x] += red[threadIdx.x + s];
        __syncthreads();
    }
    if (threadIdx.x == 0) atomicAdd(loss, red[0]);
}

// ---------------- attention fuse + norms + centers ----------------
__global__ void k_attention(const float* __restrict__ Wp1, const float* __restrict__ bp1,
                            const float* __restrict__ wp2) {
    int nid = blockIdx.x * 256 + threadIdx.x;
    if (nid >= Nn) return;
    const float* hx = g_Hx + (size_t)nid * Dout;
    const float* ha = g_Hadj + (size_t)nid * Dout;
    float accx[AH], acca[AH];
    #pragma unroll
    for (int h = 0; h < AH; h++) { accx[h] = bp1[h]; acca[h] = bp1[h]; }
    for (int d = 0; d < Dout; d++) {
        float vx = hx[d], va = ha[d];
        #pragma unroll
        for (int h = 0; h < AH; h++) {
            float w = Wp1[d * AH + h];
            accx[h] += vx * w; acca[h] += va * w;
        }
    }
    float wx = 0.f, wa = 0.f;
    #pragma unroll
    for (int h = 0; h < AH; h++) {
        wx += tanhf(accx[h]) * wp2[h];
        wa += tanhf(acca[h]) * wp2[h];
    }
    float m = fmaxf(wx, wa);
    float ex = __expf(wx - m), ea = __expf(wa - m);
    float inv = 1.f / (ex + ea);
    float bx = ex * inv, ba = ea * inv;
    float* out = g_Hf + (size_t)nid * Dout;
    for (int d = 0; d < Dout; d++) out[d] = bx * hx[d] + ba * ha[d];
}

__global__ void k_l2norm(const float* __restrict__ in, __half* __restrict__ outH,
                         float* __restrict__ outF, int rows, int cols) {
    int w = (blockIdx.x * blockDim.x + threadIdx.x) >> 5;
    int lane = threadIdx.x & 31;
    if (w >= rows) return;
    const float* r = in + (size_t)w * cols;
    float ss = 0.f;
    for (int c = lane; c < cols; c += 32) { float v = r[c]; ss += v * v; }
    for (int o = 16; o; o >>= 1) ss += __shfl_xor_sync(0xffffffffu, ss, o);
    float inv = 1.f / fmaxf(sqrtf(ss), 1e-12f);
    __half* wh = outH + (size_t)w * cols;
    for (int c = lane; c < cols; c += 32) {
        float v = r[c] * inv;
        wh[c] = __float2half(v);
        if (outF) outF[(size_t)w * cols + c] = v;
    }
}

__global__ void k_colsum(const float* __restrict__ feat) {
    int c = blockIdx.x * 256 + threadIdx.x;
    int rbeg = blockIdx.y * 128;
    float s = 0.f;
    for (int i = rbeg; i < rbeg + 128; i++) s += feat[(size_t)i * Din + c];
    atomicAdd(&g_colsum[c], s);
}

__global__ void k_center() {
    int w = (blockIdx.x * blockDim.x + threadIdx.x) >> 5;
    int lane = threadIdx.x & 31;
    if (w >= Din) return;
    float s = g_colsum[w] + 1e-5f;
    float inv_s = 1.f / s;
    float v[8]; float ss = 0.f;
    #pragma unroll
    for (int i = 0; i < 8; i++) {
        v[i] = g_dcraw[(size_t)w * Dout + lane + 32 * i] * inv_s;
        ss += v[i] * v[i];
    }
    for (int o = 16; o; o >>= 1) ss += __shfl_xor_sync(0xffffffffu, ss, o);
    float inv = 1.f / fmaxf(sqrtf(ss), 1e-12f);
    #pragma unroll
    for (int i = 0; i < 8; i++) g_Cn[(size_t)w * Dout + lane + 32 * i] = v[i] * inv;
}

__global__ void k_final(float* out) {
    out[0] = (0.5f * (g_loss[0] + g_loss[1]) + 0.1f * g_loss[2] + g_loss[3]) * (1.0f / Nn);
}

// ---------------- host ----------------
extern "C" void kernel_launch(void* const* d_in, const int* in_sizes, int n_in,
                              void* d_out, int out_size) {
    const float* feat = (const float*)d_in[0];
    const float* adjL = (const float*)d_in[1];
    const float* adjX = (const float*)d_in[2];
    const float* adjR = (const float*)d_in[3];

    const int *eA, *eX; int pb;
    if (in_sizes[5] == 262144) { eA = (const int*)d_in[4]; eX = (const int*)d_in[5]; pb = 6; }
    else                       { pb = 4; eA = (const int*)d_in[15]; eX = (const int*)d_in[16]; }

    const float* W0a = (const float*)d_in[pb + 0];
    const float* b0a = (const float*)d_in[pb + 1];
    const float* W1a = (const float*)d_in[pb + 2];
    const float* b1a = (const float*)d_in[pb + 3];
    const float* W0x = (const float*)d_in[pb + 4];
    const float* b0x = (const float*)d_in[pb + 5];
    const float* W1x = (const float*)d_in[pb + 6];
    const float* b1x = (const float*)d_in[pb + 7];
    const float* Wp1 = (const float*)d_in[pb + 8];
    const float* bp1 = (const float*)d_in[pb + 9];
    const float* wp2 = (const float*)d_in[pb + 10];

    static int smemSet = 0;
    const int LOSS_SMEM = 3 * 128 * LDH * (int)sizeof(__half);     // A + 2x B = 202752
    const int GEMM_SMEM = 4 * 128 * LDK * (int)sizeof(__half);     // 73728
    if (!smemSet) {
        cudaFuncSetAttribute(k_loss_adj_h, cudaFuncAttributeMaxDynamicSharedMemorySize, LOSS_SMEM);
        cudaFuncSetAttribute(k_gemm_h, cudaFuncAttributeMaxDynamicSharedMemorySize, GEMM_SMEM);
        smemSet = 1;
    }

    void *pY, *pH1, *pHadj, *pHx, *pHf, *pZf, *pFH, *pH1h, *pZah, *pZxh, *pZfh, *pWt;
    void *pDeg, *pNrm, *pOff, *pCur, *pEidx, *pBits;
    void *pDc, *pCn, *pCs, *pSum, *pPos, *pLoss;
    cudaGetSymbolAddress(&pY, g_Y);       cudaGetSymbolAddress(&pH1, g_H1);
    cudaGetSymbolAddress(&pHadj, g_Hadj); cudaGetSymbolAddress(&pHx, g_Hx);
    cudaGetSymbolAddress(&pHf, g_Hf);     cudaGetSymbolAddress(&pZf, g_Zf);
    cudaGetSymbolAddress(&pFH, g_featH);  cudaGetSymbolAddress(&pH1h, g_H1h);
    cudaGetSymbolAddress(&pZah, g_Zah);   cudaGetSymbolAddress(&pZxh, g_Zxh);
    cudaGetSymbolAddress(&pZfh, g_Zfh);   cudaGetSymbolAddress(&pWt, g_Wt);
    cudaGetSymbolAddress(&pDeg, g_deg);   cudaGetSymbolAddress(&pNrm, g_nrm);
    cudaGetSymbolAddress(&pOff, g_off);   cudaGetSymbolAddress(&pCur, g_cursor);
    cudaGetSymbolAddress(&pEidx, g_eidx); cudaGetSymbolAddress(&pBits, g_bits);
    cudaGetSymbolAddress(&pDc, g_dcraw);  cudaGetSymbolAddress(&pCn, g_Cn);
    cudaGetSymbolAddress(&pCs, g_colsum); cudaGetSymbolAddress(&pSum, g_sum);
    cudaGetSymbolAddress(&pPos, g_pos);   cudaGetSymbolAddress(&pLoss, g_loss);

    float* deg = (float*)pDeg;
    float* nrm = (float*)pNrm;
    float* nsA = nrm;           float* ndA = nrm + Nn;
    float* nsX = nrm + 2 * Nn;  float* ndX = nrm + 3 * Nn;
    int* offA = (int*)pOff;     int* offX = offA + (Nn + 1);
    int* eidxA = (int*)pEidx;   int* eidxX = eidxA + Ne;
    unsigned* bitsL = (unsigned*)pBits;
    unsigned* bitsX = bitsL + (size_t)Nn * NW;
    unsigned* bitsR = bitsX + (size_t)Nn * NW;
    __half* featH = (__half*)pFH;
    __half* H1h = (__half*)pH1h;
    __half* W0aT = (__half*)pWt;
    __half* W1aT = W0aT + Din * Din;
    __half* W0xT = W1aT + Din * Dout;
    __half* W1xT = W0xT + Din * Din;
    float* sum = (float*)pSum;  float* pos = (float*)pPos;
    float* loss = (float*)pLoss;

    // ---- preprocessing ----
    cudaMemsetAsync(pDeg, 0, 4 * Nn * sizeof(float));
    cudaMemsetAsync(pCur, 0, 2 * Nn * sizeof(int));
    k_degree<<<(Ne + 255) / 256, 256>>>(eA, eA + Ne, deg, deg + Nn);
    k_degree<<<(Ne + 255) / 256, 256>>>(eX, eX + Ne, deg + 2 * Nn, deg + 3 * Nn);
    k_norm<<<(4 * Nn) / 256, 256>>>();
    k_scan<<<1, 1024>>>(deg + Nn, offA);
    k_scan<<<1, 1024>>>(deg + 3 * Nn, offX);
    k_bucket<<<(Ne + 255) / 256, 256>>>(eA, eA + Ne, offA, (int*)pCur, eidxA);
    k_bucket<<<(Ne + 255) / 256, 256>>>(eX, eX + Ne, offX, (int*)pCur + Nn, eidxX);

    const int packBlocks = (Nn * NW) / 8;
    k_pack<<<packBlocks, 256>>>(adjL, bitsL);
    k_pack<<<packBlocks, 256>>>(adjX, bitsX);
    k_pack<<<packBlocks, 256>>>(adjR, bitsR);

    // ---- weight + feature conversion ----
    k_f2h<<<(Nn * Din / 4 + 255) / 256, 256>>>(feat, featH, Nn * Din / 4);
    k_wth<<<(Din * Din + 255) / 256, 256>>>(W0a, W0aT, Din, Din);
    k_wth<<<(Din * Dout + 255) / 256, 256>>>(W1a, W1aT, Din, Dout);
    k_wth<<<(Din * Din + 255) / 256, 256>>>(W0x, W0xT, Din, Din);
    k_wth<<<(Din * Dout + 255) / 256, 256>>>(W1x, W1xT, Din, Dout);

    // ---- GCN over graph A ----
    k_gemm_h<<<dim3(Nn / 128, Din / 128), 256, GEMM_SMEM>>>(featH, W0aT, (float*)pY, Din, Din);
    k_gather<<<Nn, Din / 4>>>(offA, eidxA, (float*)pY, nsA, ndA, b0a, (float*)pH1, Din / 4, 1);
    k_f2h<<<(Nn * Din / 4 + 255) / 256, 256>>>((float*)pH1, H1h, Nn * Din / 4);
    k_gemm_h<<<dim3(Nn / 128, Dout / 128), 256, GEMM_SMEM>>>(H1h, W1aT, (float*)pY, Dout, Din);
    k_gather<<<Nn, Dout / 4>>>(offA, eidxA, (float*)pY, nsA, ndA, b1a, (float*)pHadj, Dout / 4, 0);

    // ---- GCN over graph X ----
    k_gemm_h<<<dim3(Nn / 128, Din / 128), 256, GEMM_SMEM>>>(featH, W0xT, (float*)pY, Din, Din);
    k_gather<<<Nn, Din / 4>>>(offX, eidxX, (float*)pY, nsX, ndX, b0x, (float*)pH1, Din / 4, 1);
    k_f2h<<<(Nn * Din / 4 + 255) / 256, 256>>>((float*)pH1, H1h, Nn * Din / 4);
    k_gemm_h<<<dim3(Nn / 128, Dout / 128), 256, GEMM_SMEM>>>(H1h, W1xT, (float*)pY, Dout, Din);
    k_gather<<<Nn, Dout / 4>>>(offX, eidxX, (float*)pY, nsX, ndX, b1x, (float*)pHx, Dout / 4, 0);

    // ---- attention fusion + normalization ----
    k_attention<<<Nn / 256, 256>>>(Wp1, bp1, wp2);
    k_l2norm<<<Nn / 8, 256>>>((float*)pHadj, (__half*)pZah, nullptr, Nn, Dout);
    k_l2norm<<<Nn / 8, 256>>>((float*)pHx,   (__half*)pZxh, nullptr, Nn, Dout);
    k_l2norm<<<Nn / 8, 256>>>((float*)pHf,   (__half*)pZfh, (float*)pZf, Nn, Dout);

    // ---- dim_center ----
    cudaMemsetAsync(pCs, 0, Din * sizeof(float));
    k_colsum<<<dim3(2, 64), 256>>>(feat);
    cudaMemsetAsync(pDc, 0, (size_t)Din * Dout * sizeof(float));
    k_atb<<<dim3(Din / 128, Dout / 128, 32), 256>>>(feat, (float*)pHf, (float*)pDc, Din, Dout, Nn / 32);
    k_center<<<Din / 8, 256>>>();

    // ---- losses ----
    cudaMemsetAsync(pSum, 0, 4 * Nn * sizeof(float));
    cudaMemsetAsync(pPos, 0, 4 * Nn * sizeof(float));
    cudaMemsetAsync(pLoss, 0, 4 * sizeof(float));
    k_loss_adj_h<<<dim3(Nn / 128, 2), 256, LOSS_SMEM>>>((const __half*)pZah, bitsL, sum,          pos);
    k_loss_adj_h<<<dim3(Nn / 128, 2), 256, LOSS_SMEM>>>((const __half*)pZxh, bitsX, sum + Nn,     pos + Nn);
    k_loss_dim<<<dim3(Nn / 128, Din / 128), 256>>>((float*)pZf, (float*)pCn, feat,
                                                   sum + 2 * Nn, pos + 2 * Nn);
    k_loss_adj_h<<<dim3(Nn / 128, 2), 256, LOSS_SMEM>>>((const __half*)pZfh, bitsR, sum + 3 * Nn, pos + 3 * Nn);

    k_rowloss<<<Nn / 256, 256>>>(sum,          pos,          loss + 0, 0);
    k_rowloss<<<Nn / 256, 256>>>(sum + Nn,     pos + Nn,     loss + 1, 0);
    k_rowloss<<<Nn / 256, 256>>>(sum + 2 * Nn, pos + 2 * Nn, loss + 2, 1);
    k_rowloss<<<Nn / 256, 256>>>(sum + 3 * Nn, pos + 3 * Nn, loss + 3, 0);

    k_final<<<1, 1>>>((float*)d_out);
}

// round 9
// speedup vs baseline: 3.2770x; 1.0301x over previous
#include <cuda_runtime.h>
#include <cuda_fp16.h>
#include <cstdint>
#include <math.h>

#define Nn   8192
#define Din  512
#define Dout 256
#define Ne   131072
#define AH   16
#define LDH  264   // loss smem stride (halves): 528B, conflict-free ldmatrix
#define NW   256   // bitmask words per row
#define LDK  72    // gemm_h chunk stride (halves)

// ---------------- static scratch ----------------
static __device__ float g_Y[Nn*Din];
static __device__ float g_H1[Nn*Din];
static __device__ float g_Hadj[Nn*Dout];
static __device__ float g_Hx[Nn*Dout];
static __device__ float g_Hf[Nn*Dout];
static __device__ float g_Zf[Nn*Dout];
static __device__ __half g_featH[Nn*Din];
static __device__ __half g_H1h[Nn*Din];
static __device__ __half g_Zah[Nn*Dout];
static __device__ __half g_Zxh[Nn*Dout];
static __device__ __half g_Zfh[Nn*Dout];
static __device__ __half g_Wt[2*(Din*Din + Din*Dout)];
static __device__ float g_deg[4*Nn];
static __device__ float g_nrm[4*Nn];
static __device__ int   g_off[2*(Nn+1)];
static __device__ int   g_cursor[2*Nn];
static __device__ int   g_eidx[2*Ne];
static __device__ unsigned g_bits[3u*Nn*NW];
static __device__ float g_dcraw[Din*Dout];
static __device__ float g_Cn[Din*Dout];
static __device__ float g_colsum[Din];
static __device__ float g_sum[4*Nn];
static __device__ float g_pos[4*Nn];
static __device__ float g_loss[4];

__device__ __forceinline__ unsigned int saddr(const void* p) {
    return (unsigned int)__cvta_generic_to_shared(p);
}
__device__ __forceinline__ void cpasync16(unsigned int dst, const void* src) {
    asm volatile("cp.async.cg.shared.global [%0], [%1], 16;" :: "r"(dst), "l"(src));
}
__device__ __forceinline__ void cpcommit() { asm volatile("cp.async.commit_group;"); }
__device__ __forceinline__ void cpwait0()  { asm volatile("cp.async.wait_group 0;"); }

// ---------------- graph preprocessing ----------------
__global__ void k_degree(const int* __restrict__ src, const int* __restrict__ dst,
                         float* degO, float* degI) {
    int t = blockIdx.x * 256 + threadIdx.x;
    if (t < Ne) { atomicAdd(degO + src[t], 1.f); atomicAdd(degI + dst[t], 1.f); }
}

__global__ void k_norm() {
    int t = blockIdx.x * 256 + threadIdx.x;
    if (t < 4 * Nn) { float d = g_deg[t]; g_nrm[t] = (d > 0.f) ? rsqrtf(d) : 0.f; }
}

__global__ void k_scan(const float* __restrict__ degIn, int* __restrict__ off) {
    __shared__ int part[1024];
    int t = threadIdx.x;
    int v[8]; int s = 0;
    #pragma unroll
    for (int i = 0; i < 8; i++) { v[i] = s; s += (int)degIn[t * 8 + i]; }
    part[t] = s;
    __syncthreads();
    for (int d = 1; d < 1024; d <<= 1) {
        int x = (t >= d) ? part[t - d] : 0;
        __syncthreads();
        part[t] += x;
        __syncthreads();
    }
    int base = (t > 0) ? part[t - 1] : 0;
    #pragma unroll
    for (int i = 0; i < 8; i++) off[t * 8 + i] = base + v[i];
    if (t == 1023) off[Nn] = part[1023];
}

__global__ void k_bucket(const int* __restrict__ src, const int* __restrict__ dst,
                         const int* __restrict__ off, int* __restrict__ cursor,
                         int* __restrict__ eidx) {
    int t = blockIdx.x * 256 + threadIdx.x;
    if (t >= Ne) return;
    int d = dst[t];
    int p = atomicAdd(&cursor[d], 1);
    eidx[off[d] + p] = src[t];
}

__global__ void k_gather(const int* __restrict__ off, const int* __restrict__ eidx,
                         const float* __restrict__ Y, const float* __restrict__ ns,
                         const float* __restrict__ nd, const float* __restrict__ bias,
                         float* __restrict__ H, int C4, int relu) {
    int n = blockIdx.x, c = threadIdx.x;
    int s0 = off[n], s1 = off[n + 1];
    float4 acc = {0.f, 0.f, 0.f, 0.f};
    for (int i = s0; i < s1; i++) {
        int s = eidx[i];
        float w = ns[s];
        float4 v = ((const float4*)Y)[(size_t)s * C4 + c];
        acc.x += v.x * w; acc.y += v.y * w; acc.z += v.z * w; acc.w += v.w * w;
    }
    float sc = nd[n];
    float4 b = ((const float4*)bias)[c];
    float4 o;
    o.x = acc.x * sc + b.x; o.y = acc.y * sc + b.y;
    o.z = acc.z * sc + b.z; o.w = acc.w * sc + b.w;
    if (relu) {
        o.x = fmaxf(o.x, 0.f); o.y = fmaxf(o.y, 0.f);
        o.z = fmaxf(o.z, 0.f); o.w = fmaxf(o.w, 0.f);
    }
    ((float4*)H)[(size_t)n * C4 + c] = o;
}

__global__ void k_pack(const float* __restrict__ a, unsigned* __restrict__ bits) {
    size_t w = (size_t)blockIdx.x * 8 + (threadIdx.x >> 5);
    int lane = threadIdx.x & 31;
    float v = __ldcs(&a[w * 32 + lane]);
    unsigned m = __ballot_sync(0xffffffffu, v != 0.f);
    if (lane == 0) bits[w] = m;
}

// ---------------- conversions ----------------
__global__ void k_f2h(const float* __restrict__ in, __half* __restrict__ out, int n4) {
    int i = blockIdx.x * 256 + threadIdx.x;
    if (i >= n4) return;
    float4 v = ((const float4*)in)[i];
    ((__half2*)out)[i * 2 + 0] = __floats2half2_rn(v.x, v.y);
    ((__half2*)out)[i * 2 + 1] = __floats2half2_rn(v.z, v.w);
}

__global__ void k_wth(const float* __restrict__ W, __half* __restrict__ Wt, int K, int N) {
    int i = blockIdx.x * 256 + threadIdx.x;
    if (i >= K * N) return;
    int k = i / N, n = i % N;
    Wt[(size_t)n * K + k] = __float2half(W[i]);
}

// ---------------- fp16 tensor-core GEMM: C = A[MxK] @ Bt[NcxK]^T ----------------
__global__ __launch_bounds__(256)
void k_gemm_h(const __half* __restrict__ A, const __half* __restrict__ Bt,
              float* __restrict__ C, int Nc, int K) {
    extern __shared__ __half sg[];
    __half* As = sg;
    __half* Bs = sg + 2 * 128 * LDK;
    const int BUF = 128 * LDK;
    const int tid = threadIdx.x;
    const int lane = tid & 31, warp = tid >> 5;
    const int wm = warp >> 1, wn = warp & 1;
    const int r0 = blockIdx.x * 128, c0 = blockIdx.y * 128;

    const int mat = lane >> 3, r = lane & 7;
    unsigned int aB[2], bB[4];
    #pragma unroll
    for (int am = 0; am < 2; am++) {
        int row = wm * 32 + am * 16 + (mat & 1) * 8 + r;
        aB[am] = saddr(&As[row * LDK + (mat >> 1) * 8]);
    }
    #pragma unroll
    for (int p = 0; p < 4; p++) {
        int row = wn * 64 + p * 16 + (mat >> 1) * 8 + r;
        bB[p] = saddr(&Bs[row * LDK + (mat & 1) * 8]);
    }

    float acc[2][8][4] = {};
    const int nch = K / 64;

    #pragma unroll
    for (int i = 0; i < 4; i++) {
        int idx = tid + i * 256;
        int row = idx >> 3, c8 = (idx & 7) * 8;
        cpasync16(saddr(&As[row * LDK + c8]), &A[(size_t)(r0 + row) * K + c8]);
        cpasync16(saddr(&Bs[row * LDK + c8]), &Bt[(size_t)(c0 + row) * K + c8]);
    }
    cpcommit();

    for (int ch = 0; ch < nch; ch++) {
        int p = ch & 1;
        cpwait0();
        __syncthreads();
        if (ch + 1 < nch) {
            int np = 1 - p, k0g = (ch + 1) * 64;
            #pragma unroll
            for (int i = 0; i < 4; i++) {
                int idx = tid + i * 256;
                int row = idx >> 3, c8 = (idx & 7) * 8;
                cpasync16(saddr(&As[np * BUF + row * LDK + c8]),
                          &A[(size_t)(r0 + row) * K + k0g + c8]);
                cpasync16(saddr(&Bs[np * BUF + row * LDK + c8]),
                          &Bt[(size_t)(c0 + row) * K + k0g + c8]);
            }
            cpcommit();
        }
        const unsigned int bufOff = p * BUF * 2;
        #pragma unroll
        for (int k0 = 0; k0 < 64; k0 += 16) {
            unsigned int a[2][4], b[4][4];
            #pragma unroll
            for (int am = 0; am < 2; am++)
                asm volatile("ldmatrix.sync.aligned.m8n8.x4.shared.b16 {%0,%1,%2,%3}, [%4];"
                    : "=r"(a[am][0]), "=r"(a[am][1]), "=r"(a[am][2]), "=r"(a[am][3])
                    : "r"(aB[am] + bufOff + k0 * 2));
            #pragma unroll
            for (int q = 0; q < 4; q++)
                asm volatile("ldmatrix.sync.aligned.m8n8.x4.shared.b16 {%0,%1,%2,%3}, [%4];"
                    : "=r"(b[q][0]), "=r"(b[q][1]), "=r"(b[q][2]), "=r"(b[q][3])
                    : "r"(bB[q] + bufOff + k0 * 2));
            #pragma unroll
            for (int am = 0; am < 2; am++)
                #pragma unroll
                for (int an = 0; an < 8; an++) {
                    int q = an >> 1, s = (an & 1) * 2;
                    asm volatile(
                        "mma.sync.aligned.m16n8k16.row.col.f32.f16.f16.f32 "
                        "{%0,%1,%2,%3}, {%4,%5,%6,%7}, {%8,%9}, {%0,%1,%2,%3};"
                        : "+f"(acc[am][an][0]), "+f"(acc[am][an][1]),
                          "+f"(acc[am][an][2]), "+f"(acc[am][an][3])
                        : "r"(a[am][0]), "r"(a[am][1]), "r"(a[am][2]), "r"(a[am][3]),
                          "r"(b[q][s]), "r"(b[q][s + 1]));
                }
        }
        __syncthreads();
    }

    #pragma unroll
    for (int am = 0; am < 2; am++) {
        int row = r0 + wm * 32 + am * 16 + (lane >> 2);
        #pragma unroll
        for (int an = 0; an < 8; an++) {
            int col = c0 + wn * 64 + an * 8 + (lane & 3) * 2;
            *(float2*)&C[(size_t)row * Nc + col] =
                make_float2(acc[am][an][0], acc[am][an][1]);
            *(float2*)&C[(size_t)(row + 8) * Nc + col] =
                make_float2(acc[am][an][2], acc[am][an][3]);
        }
    }
}

// ---------------- symmetric tensor-core contrastive loss ----------------
// Upper-triangle tile pairs only; off-diagonal tiles contribute row sums
// (rows of R) AND column sums (rows of C, via smem-staged adj[j,i] bits).
__global__ __launch_bounds__(256)
void k_loss_sym(const __half* __restrict__ Zh, const unsigned* __restrict__ bits,
                float* __restrict__ sumG, float* __restrict__ posG) {
    const int x = blockIdx.x, y = blockIdx.y;
    if (y == 32 && x >= 32) return;
    int cwrap = x + y;
    int R, C;
    if (cwrap < 64) { R = x; C = cwrap; }
    else            { R = cwrap - 64; C = x; }
    const int r0 = R * 128, c0 = C * 128;
    const bool notdiag = (R != C);

    extern __shared__ __half sh[];
    __half* As = sh;                              // [128][LDH]
    __half* Bs = sh + 128 * LDH;                  // [128][LDH]
    unsigned* bitsS = (unsigned*)(sh + 2 * 128 * LDH);  // [128][4]

    const int tid = threadIdx.x;
    const int lane = tid & 31, warp = tid >> 5;
    const int wm = warp >> 1, wn = warp & 1;

    // stage both tiles (single wait; cross-CTA overlap hides the latency)
    #pragma unroll
    for (int i = 0; i < 16; i++) {
        int idx = tid + i * 256;                  // [0,4096)
        int row = idx >> 5, c8 = (idx & 31) * 8;
        cpasync16(saddr(&As[row * LDH + c8]), &Zh[(size_t)(r0 + row) * Dout + c8]);
        cpasync16(saddr(&Bs[row * LDH + c8]), &Zh[(size_t)(c0 + row) * Dout + c8]);
    }
    cpcommit();

    if (notdiag && tid < 128) {
        *(uint4*)&bitsS[tid * 4] =
            *(const uint4*)&bits[(size_t)(c0 + tid) * NW + (r0 >> 5)];
    }

    const int mat = lane >> 3, r = lane & 7;
    unsigned int aBase[2], bBase[4];
    #pragma unroll
    for (int am = 0; am < 2; am++) {
        int row = wm * 32 + am * 16 + (mat & 1) * 8 + r;
        aBase[am] = saddr(&As[row * LDH + (mat >> 1) * 8]);
    }
    #pragma unroll
    for (int p = 0; p < 4; p++) {
        int row = wn * 64 + p * 16 + (mat >> 1) * 8 + r;
        bBase[p] = saddr(&Bs[row * LDH + (mat & 1) * 8]);
    }

    cpwait0();
    __syncthreads();

    float acc[2][8][4] = {};
    #pragma unroll
    for (int k0 = 0; k0 < Dout; k0 += 16) {
        unsigned int a[2][4], b[4][4];
        #pragma unroll
        for (int am = 0; am < 2; am++)
            asm volatile("ldmatrix.sync.aligned.m8n8.x4.shared.b16 {%0,%1,%2,%3}, [%4];"
                : "=r"(a[am][0]), "=r"(a[am][1]), "=r"(a[am][2]), "=r"(a[am][3])
                : "r"(aBase[am] + k0 * 2));
        #pragma unroll
        for (int p = 0; p < 4; p++)
            asm volatile("ldmatrix.sync.aligned.m8n8.x4.shared.b16 {%0,%1,%2,%3}, [%4];"
                : "=r"(b[p][0]), "=r"(b[p][1]), "=r"(b[p][2]), "=r"(b[p][3])
                : "r"(bBase[p] + k0 * 2));
        #pragma unroll
        for (int am = 0; am < 2; am++)
            #pragma unroll
            for (int an = 0; an < 8; an++) {
                int p = an >> 1, q = (an & 1) * 2;
                asm volatile(
                    "mma.sync.aligned.m16n8k16.row.col.f32.f16.f16.f32 "
                    "{%0,%1,%2,%3}, {%4,%5,%6,%7}, {%8,%9}, {%0,%1,%2,%3};"
                    : "+f"(acc[am][an][0]), "+f"(acc[am][an][1]),
                      "+f"(acc[am][an][2]), "+f"(acc[am][an][3])
                    : "r"(a[am][0]), "r"(a[am][1]), "r"(a[am][2]), "r"(a[am][3]),
                      "r"(b[p][q]), "r"(b[p][q + 1]));
            }
    }

    float rs[4] = {}, rp[4] = {};
    float cs[8][2] = {}, cp[8][2] = {};
    const int bitPos = (lane & 3) * 2;
    const int wbase = (c0 >> 5) + wn * 2;

    #pragma unroll
    for (int am = 0; am < 2; am++) {
        int baseRow = wm * 32 + am * 16;
        int row0 = r0 + baseRow + (lane >> 2);
        uint2 wA = *(const uint2*)&bits[(size_t)row0 * NW + wbase];
        uint2 wB = *(const uint2*)&bits[(size_t)(row0 + 8) * NW + wbase];
        int wi = baseRow >> 5;
        int bp0 = (baseRow & 31) + (lane >> 2);
        #pragma unroll
        for (int an = 0; an < 8; an++) {
            unsigned ma = (an < 4) ? wA.x : wA.y;
            unsigned mb = (an < 4) ? wB.x : wB.y;
            int pos = (an & 3) * 8 + bitPos;
            float e0 = __expf(acc[am][an][0]);
            float e1 = __expf(acc[am][an][1]);
            float e2 = __expf(acc[am][an][2]);
            float e3 = __expf(acc[am][an][3]);
            rs[am * 2 + 0] += e0 + e1;
            rs[am * 2 + 1] += e2 + e3;
            if ((ma >> pos) & 1u)       rp[am * 2 + 0] += e0;
            if ((ma >> (pos + 1)) & 1u) rp[am * 2 + 0] += e1;
            if ((mb >> pos) & 1u)       rp[am * 2 + 1] += e2;
            if ((mb >> (pos + 1)) & 1u) rp[am * 2 + 1] += e3;
            if (notdiag) {
                int colLoc = wn * 64 + an * 8 + (lane & 3) * 2;
                unsigned w0 = bitsS[colLoc * 4 + wi];
                unsigned w1 = bitsS[(colLoc + 1) * 4 + wi];
                cs[an][0] += e0 + e2;
                cs[an][1] += e1 + e3;
                if ((w0 >> bp0) & 1u)       cp[an][0] += e0;
                if ((w0 >> (bp0 + 8)) & 1u) cp[an][0] += e2;
                if ((w1 >> bp0) & 1u)       cp[an][1] += e1;
                if ((w1 >> (bp0 + 8)) & 1u) cp[an][1] += e3;
            }
        }
    }

    #pragma unroll
    for (int s = 0; s < 4; s++) {
        float v = rs[s], p = rp[s];
        v += __shfl_xor_sync(0xffffffffu, v, 1);
        v += __shfl_xor_sync(0xffffffffu, v, 2);
        p += __shfl_xor_sync(0xffffffffu, p, 1);
        p += __shfl_xor_sync(0xffffffffu, p, 2);
        if ((lane & 3) == 0) {
            int row = r0 + wm * 32 + (s >> 1) * 16 + (s & 1) * 8 + (lane >> 2);
            atomicAdd(&sumG[row], v);
            atomicAdd(&posG[row], p);
        }
    }

    if (notdiag) {
        #pragma unroll
        for (int an = 0; an < 8; an++) {
            #pragma unroll
            for (int j = 0; j < 2; j++) {
                float v = cs[an][j], p = cp[an][j];
                v += __shfl_xor_sync(0xffffffffu, v, 4);
                v += __shfl_xor_sync(0xffffffffu, v, 8);
                v += __shfl_xor_sync(0xffffffffu, v, 16);
                p += __shfl_xor_sync(0xffffffffu, p, 4);
                p += __shfl_xor_sync(0xffffffffu, p, 8);
                p += __shfl_xor_sync(0xffffffffu, p, 16);
                if (lane < 4) {
                    int col = c0 + wn * 64 + an * 8 + lane * 2 + j;
                    atomicAdd(&sumG[col], v);
                    atomicAdd(&posG[col], p);
                }
            }
        }
    }
}

// C[MxN] += A^T@B over K-slice (fp32, for dim_center)
__global__ __launch_bounds__(256, 2)
void k_atb(const float* __restrict__ A, const float* __restrict__ B,
           float* __restrict__ C, int M, int Nc, int kPerSlice) {
    __shared__ float As[32][132];
    __shared__ float Bs[32][132];
    int tid = threadIdx.x, tx = tid & 15, ty = tid >> 4;
    int r0 = blockIdx.x * 128, c0 = blockIdx.y * 128;
    int kb = blockIdx.z * kPerSlice;
    int ty8 = ty * 8, tx8 = tx * 8;
    float acc[8][8] = {};
    for (int k0 = kb; k0 < kb + kPerSlice; k0 += 32) {
        for (int t = tid; t < 4096; t += 256) {
            int m = t & 127, k = t >> 7;
            As[k][m] = A[(size_t)(k0 + k) * M + r0 + m];
        }
        for (int t = tid; t < 4096; t += 256) {
            int n = t & 127, k = t >> 7;
            Bs[k][n] = B[(size_t)(k0 + k) * Nc + c0 + n];
        }
        __syncthreads();
        #pragma unroll 8
        for (int k = 0; k < 32; k++) {
            float a[8], b[8];
            #pragma unroll
            for (int i = 0; i < 8; i++) a[i] = As[k][ty8 + i];
            #pragma unroll
            for (int j = 0; j < 8; j++) b[j] = Bs[k][tx8 + j];
            #pragma unroll
            for (int i = 0; i < 8; i++)
                #pragma unroll
                for (int j = 0; j < 8; j++) acc[i][j] = fmaf(a[i], b[j], acc[i][j]);
        }
        __syncthreads();
    }
    for (int i = 0; i < 8; i++) {
        size_t r = (size_t)(r0 + ty8 + i) * Nc + c0 + tx8;
        #pragma unroll
        for (int j = 0; j < 8; j++) atomicAdd(&C[r + j], acc[i][j]);
    }
}

// fused dim-label loss (fp32)
__global__ __launch_bounds__(256, 2)
void k_loss_dim(const float* __restrict__ Z, const float* __restrict__ Cn,
                const float* __restrict__ feat,
                float* __restrict__ sumG, float* __restrict__ posG) {
    __shared__ float As[32][132];
    __shared__ float Bs[32][132];
    int tid = threadIdx.x, tx = tid & 15, ty = tid >> 4;
    int r0 = blockIdx.x * 128;
    int c0 = blockIdx.y * 128;
    int ty8 = ty * 8, tx8 = tx * 8;
    float acc[8][8] = {};
    for (int k0 = 0; k0 < Dout; k0 += 32) {
        for (int t = tid; t < 4096; t += 256) {
            int k = t & 31, m = t >> 5;
            As[k][m] = Z[(size_t)(r0 + m) * Dout + k0 + k];
        }
        for (int t = tid; t < 4096; t += 256) {
            int k = t & 31, m = t >> 5;
            Bs[k][m] = Cn[(size_t)(c0 + m) * Dout + k0 + k];
        }
        __syncthreads();
        #pragma unroll 8
        for (int k = 0; k < 32; k++) {
            float a[8], b[8];
            #pragma unroll
            for (int i = 0; i < 8; i++) a[i] = As[k][ty8 + i];
            #pragma unroll
            for (int j = 0; j < 8; j++) b[j] = Bs[k][tx8 + j];
            #pragma unroll
            for (int i = 0; i < 8; i++)
                #pragma unroll
                for (int j = 0; j < 8; j++) acc[i][j] = fmaf(a[i], b[j], acc[i][j]);
        }
        __syncthreads();
    }
    for (int i = 0; i < 8; i++) {
        int rr = r0 + ty8 + i;
        const float* frow = feat + (size_t)rr * Din + c0 + tx8;
        float sA = 0.f, pA = 0.f;
        #pragma unroll
        for (int j = 0; j < 8; j++) {
            float e = __expf(acc[i][j]);
            sA += e;
            if (frow[j] > 0.f) pA += e;
        }
        atomicAdd(&sumG[rr], sA);
        atomicAdd(&posG[rr], pA);
    }
}

__global__ void k_rowloss(const float* __restrict__ sumG, const float* __restrict__ posG,
                          float* loss, int mode) {
    __shared__ float red[256];
    int t = blockIdx.x * 256 + threadIdx.x;
    float term = 0.f;
    if (t < Nn) {
        float pos = posG[t], tot = sumG[t];
        float neg = tot - pos;
        if (mode == 0) term = -logf((pos + 1e-10f) / (neg + 1e-10f));
        else           term = -logf((pos + 1e-10f) / neg + 1e-5f);
    }
    red[threadIdx.x] = term;
    __syncthreads();
    for (int s = 128; s; s >>= 1) {
        if (threadIdx.x < s) red[threadIdx.x] += red[threadIdx.x + s];
        __syncthreads();
    }
    if (threadIdx.x == 0) atomicAdd(loss, red[0]);
}

// ---------------- attention fuse + norms + centers ----------------
__global__ void k_attention(const float* __restrict__ Wp1, const float* __restrict__ bp1,
                            const float* __restrict__ wp2) {
    int nid = blockIdx.x * 256 + threadIdx.x;
    if (nid >= Nn) return;
    const float* hx = g_Hx + (size_t)nid * Dout;
    const float* ha = g_Hadj + (size_t)nid * Dout;
    float accx[AH], acca[AH];
    #pragma unroll
    for (int h = 0; h < AH; h++) { accx[h] = bp1[h]; acca[h] = bp1[h]; }
    for (int d = 0; d < Dout; d++) {
        float vx = hx[d], va = ha[d];
        #pragma unroll
        for (int h = 0; h < AH; h++) {
            float w = Wp1[d * AH + h];
            accx[h] += vx * w; acca[h] += va * w;
        }
    }
    float wx = 0.f, wa = 0.f;
    #pragma unroll
    for (int h = 0; h < AH; h++) {
        wx += tanhf(accx[h]) * wp2[h];
        wa += tanhf(acca[h]) * wp2[h];
    }
    float m = fmaxf(wx, wa);
    float ex = __expf(wx - m), ea = __expf(wa - m);
    float inv = 1.f / (ex + ea);
    float bx = ex * inv, ba = ea * inv;
    float* out = g_Hf + (size_t)nid * Dout;
    for (int d = 0; d < Dout; d++) out[d] = bx * hx[d] + ba * ha[d];
}

__global__ void k_l2norm(const float* __restrict__ in, __half* __restrict__ outH,
                         float* __restrict__ outF, int rows, int cols) {
    int w = (blockIdx.x * blockDim.x + threadIdx.x) >> 5;
    int lane = threadIdx.x & 31;
    if (w >= rows) return;
    const float* r = in + (size_t)w * cols;
    float ss = 0.f;
    for (int c = lane; c < cols; c += 32) { float v = r[c]; ss += v * v; }
    for (int o = 16; o; o >>= 1) ss += __shfl_xor_sync(0xffffffffu, ss, o);
    float inv = 1.f / fmaxf(sqrtf(ss), 1e-12f);
    __half* wh = outH + (size_t)w * cols;
    for (int c = lane; c < cols; c += 32) {
        float v = r[c] * inv;
        wh[c] = __float2half(v);
        if (outF) outF[(size_t)w * cols + c] = v;
    }
}

__global__ void k_colsum(const float* __restrict__ feat) {
    int c = blockIdx.x * 256 + threadIdx.x;
    int rbeg = blockIdx.y * 128;
    float s = 0.f;
    for (int i = rbeg; i < rbeg + 128; i++) s += feat[(size_t)i * Din + c];
    atomicAdd(&g_colsum[c], s);
}

__global__ void k_center() {
    int w = (blockIdx.x * blockDim.x + threadIdx.x) >> 5;
    int lane = threadIdx.x & 31;
    if (w >= Din) return;
    float s = g_colsum[w] + 1e-5f;
    float inv_s = 1.f / s;
    float v[8]; float ss = 0.f;
    #pragma unroll
    for (int i = 0; i < 8; i++) {
        v[i] = g_dcraw[(size_t)w * Dout + lane + 32 * i] * inv_s;
        ss += v[i] * v[i];
    }
    for (int o = 16; o; o >>= 1) ss += __shfl_xor_sync(0xffffffffu, ss, o);
    float inv = 1.f / fmaxf(sqrtf(ss), 1e-12f);
    #pragma unroll
    for (int i = 0; i < 8; i++) g_Cn[(size_t)w * Dout + lane + 32 * i] = v[i] * inv;
}

__global__ void k_final(float* out) {
    out[0] = (0.5f * (g_loss[0] + g_loss[1]) + 0.1f * g_loss[2] + g_loss[3]) * (1.0f / Nn);
}

// ---------------- host ----------------
extern "C" void kernel_launch(void* const* d_in, const int* in_sizes, int n_in,
                              void* d_out, int out_size) {
    const float* feat = (const float*)d_in[0];
    const float* adjL = (const float*)d_in[1];
    const float* adjX = (const float*)d_in[2];
    const float* adjR = (const float*)d_in[3];

    const int *eA, *eX; int pb;
    if (in_sizes[5] == 262144) { eA = (const int*)d_in[4]; eX = (const int*)d_in[5]; pb = 6; }
    else                       { pb = 4; eA = (const int*)d_in[15]; eX = (const int*)d_in[16]; }

    const float* W0a = (const float*)d_in[pb + 0];
    const float* b0a = (const float*)d_in[pb + 1];
    const float* W1a = (const float*)d_in[pb + 2];
    const float* b1a = (const float*)d_in[pb + 3];
    const float* W0x = (const float*)d_in[pb + 4];
    const float* b0x = (const float*)d_in[pb + 5];
    const float* W1x = (const float*)d_in[pb + 6];
    const float* b1x = (const float*)d_in[pb + 7];
    const float* Wp1 = (const float*)d_in[pb + 8];
    const float* bp1 = (const float*)d_in[pb + 9];
    const float* wp2 = (const float*)d_in[pb + 10];

    static int smemSet = 0;
    const int LOSS_SMEM = 2 * 128 * LDH * (int)sizeof(__half) + 2048;  // 137216
    const int GEMM_SMEM = 4 * 128 * LDK * (int)sizeof(__half);
    if (!smemSet) {
        cudaFuncSetAttribute(k_loss_sym, cudaFuncAttributeMaxDynamicSharedMemorySize, LOSS_SMEM);
        cudaFuncSetAttribute(k_gemm_h, cudaFuncAttributeMaxDynamicSharedMemorySize, GEMM_SMEM);
        smemSet = 1;
    }

    void *pY, *pH1, *pHadj, *pHx, *pHf, *pZf, *pFH, *pH1h, *pZah, *pZxh, *pZfh, *pWt;
    void *pDeg, *pNrm, *pOff, *pCur, *pEidx, *pBits;
    void *pDc, *pCn, *pCs, *pSum, *pPos, *pLoss;
    cudaGetSymbolAddress(&pY, g_Y);       cudaGetSymbolAddress(&pH1, g_H1);
    cudaGetSymbolAddress(&pHadj, g_Hadj); cudaGetSymbolAddress(&pHx, g_Hx);
    cudaGetSymbolAddress(&pHf, g_Hf);     cudaGetSymbolAddress(&pZf, g_Zf);
    cudaGetSymbolAddress(&pFH, g_featH);  cudaGetSymbolAddress(&pH1h, g_H1h);
    cudaGetSymbolAddress(&pZah, g_Zah);   cudaGetSymbolAddress(&pZxh, g_Zxh);
    cudaGetSymbolAddress(&pZfh, g_Zfh);   cudaGetSymbolAddress(&pWt, g_Wt);
    cudaGetSymbolAddress(&pDeg, g_deg);   cudaGetSymbolAddress(&pNrm, g_nrm);
    cudaGetSymbolAddress(&pOff, g_off);   cudaGetSymbolAddress(&pCur, g_cursor);
    cudaGetSymbolAddress(&pEidx, g_eidx); cudaGetSymbolAddress(&pBits, g_bits);
    cudaGetSymbolAddress(&pDc, g_dcraw);  cudaGetSymbolAddress(&pCn, g_Cn);
    cudaGetSymbolAddress(&pCs, g_colsum); cudaGetSymbolAddress(&pSum, g_sum);
    cudaGetSymbolAddress(&pPos, g_pos);   cudaGetSymbolAddress(&pLoss, g_loss);

    float* deg = (float*)pDeg;
    float* nrm = (float*)pNrm;
    float* nsA = nrm;           float* ndA = nrm + Nn;
    float* nsX = nrm + 2 * Nn;  float* ndX = nrm + 3 * Nn;
    int* offA = (int*)pOff;     int* offX = offA + (Nn + 1);
    int* eidxA = (int*)pEidx;   int* eidxX = eidxA + Ne;
    unsigned* bitsL = (unsigned*)pBits;
    unsigned* bitsX = bitsL + (size_t)Nn * NW;
    unsigned* bitsR = bitsX + (size_t)Nn * NW;
    __half* featH = (__half*)pFH;
    __half* H1h = (__half*)pH1h;
    __half* W0aT = (__half*)pWt;
    __half* W1aT = W0aT + Din * Din;
    __half* W0xT = W1aT + Din * Dout;
    __half* W1xT = W0xT + Din * Din;
    float* sum = (float*)pSum;  float* pos = (float*)pPos;
    float* loss = (float*)pLoss;

    // ---- preprocessing ----
    cudaMemsetAsync(pDeg, 0, 4 * Nn * sizeof(float));
    cudaMemsetAsync(pCur, 0, 2 * Nn * sizeof(int));
    k_degree<<<(Ne + 255) / 256, 256>>>(eA, eA + Ne, deg, deg + Nn);
    k_degree<<<(Ne + 255) / 256, 256>>>(eX, eX + Ne, deg + 2 * Nn, deg + 3 * Nn);
    k_norm<<<(4 * Nn) / 256, 256>>>();
    k_scan<<<1, 1024>>>(deg + Nn, offA);
    k_scan<<<1, 1024>>>(deg + 3 * Nn, offX);
    k_bucket<<<(Ne + 255) / 256, 256>>>(eA, eA + Ne, offA, (int*)pCur, eidxA);
    k_bucket<<<(Ne + 255) / 256, 256>>>(eX, eX + Ne, offX, (int*)pCur + Nn, eidxX);

    const int packBlocks = (Nn * NW) / 8;
    k_pack<<<packBlocks, 256>>>(adjL, bitsL);
    k_pack<<<packBlocks, 256>>>(adjX, bitsX);
    k_pack<<<packBlocks, 256>>>(adjR, bitsR);

    // ---- weight + feature conversion ----
    k_f2h<<<(Nn * Din / 4 + 255) / 256, 256>>>(feat, featH, Nn * Din / 4);
    k_wth<<<(Din * Din + 255) / 256, 256>>>(W0a, W0aT, Din, Din);
    k_wth<<<(Din * Dout + 255) / 256, 256>>>(W1a, W1aT, Din, Dout);
    k_wth<<<(Din * Din + 255) / 256, 256>>>(W0x, W0xT, Din, Din);
    k_wth<<<(Din * Dout + 255) / 256, 256>>>(W1x, W1xT, Din, Dout);

    // ---- GCN over graph A ----
    k_gemm_h<<<dim3(Nn / 128, Din / 128), 256, GEMM_SMEM>>>(featH, W0aT, (float*)pY, Din, Din);
    k_gather<<<Nn, Din / 4>>>(offA, eidxA, (float*)pY, nsA, ndA, b0a, (float*)pH1, Din / 4, 1);
    k_f2h<<<(Nn * Din / 4 + 255) / 256, 256>>>((float*)pH1, H1h, Nn * Din / 4);
    k_gemm_h<<<dim3(Nn / 128, Dout / 128), 256, GEMM_SMEM>>>(H1h, W1aT, (float*)pY, Dout, Din);
    k_gather<<<Nn, Dout / 4>>>(offA, eidxA, (float*)pY, nsA, ndA, b1a, (float*)pHadj, Dout / 4, 0);

    // ---- GCN over graph X ----
    k_gemm_h<<<dim3(Nn / 128, Din / 128), 256, GEMM_SMEM>>>(featH, W0xT, (float*)pY, Din, Din);
    k_gather<<<Nn, Din / 4>>>(offX, eidxX, (float*)pY, nsX, ndX, b0x, (float*)pH1, Din / 4, 1);
    k_f2h<<<(Nn * Din / 4 + 255) / 256, 256>>>((float*)pH1, H1h, Nn * Din / 4);
    k_gemm_h<<<dim3(Nn / 128, Dout / 128), 256, GEMM_SMEM>>>(H1h, W1xT, (float*)pY, Dout, Din);
    k_gather<<<Nn, Dout / 4>>>(offX, eidxX, (float*)pY, nsX, ndX, b1x, (float*)pHx, Dout / 4, 0);

    // ---- attention fusion + normalization ----
    k_attention<<<Nn / 256, 256>>>(Wp1, bp1, wp2);
    k_l2norm<<<Nn / 8, 256>>>((float*)pHadj, (__half*)pZah, nullptr, Nn, Dout);
    k_l2norm<<<Nn / 8, 256>>>((float*)pHx,   (__half*)pZxh, nullptr, Nn, Dout);
    k_l2norm<<<Nn / 8, 256>>>((float*)pHf,   (__half*)pZfh, (float*)pZf, Nn, Dout);

    // ---- dim_center ----
    cudaMemsetAsync(pCs, 0, Din * sizeof(float));
    k_colsum<<<dim3(2, 64), 256>>>(feat);
    cudaMemsetAsync(pDc, 0, (size_t)Din * Dout * sizeof(float));
    k_atb<<<dim3(Din / 128, Dout / 128, 32), 256>>>(feat, (float*)pHf, (float*)pDc, Din, Dout, Nn / 32);
    k_center<<<Din / 8, 256>>>();

    // ---- losses (symmetric tile-pair kernels) ----
    cudaMemsetAsync(pSum, 0, 4 * Nn * sizeof(float));
    cudaMemsetAsync(pPos, 0, 4 * Nn * sizeof(float));
    cudaMemsetAsync(pLoss, 0, 4 * sizeof(float));
    k_loss_sym<<<dim3(64, 33), 256, LOSS_SMEM>>>((const __half*)pZah, bitsL, sum,          pos);
    k_loss_sym<<<dim3(64, 33), 256, LOSS_SMEM>>>((const __half*)pZxh, bitsX, sum + Nn,     pos + Nn);
    k_loss_dim<<<dim3(Nn / 128, Din / 128), 256>>>((float*)pZf, (float*)pCn, feat,
                                                   sum + 2 * Nn, pos + 2 * Nn);
    k_loss_sym<<<dim3(64, 33), 256, LOSS_SMEM>>>((const __half*)pZfh, bitsR, sum + 3 * Nn, pos + 3 * Nn);

    k_rowloss<<<Nn / 256, 256>>>(sum,          pos,          loss + 0, 0);
    k_rowloss<<<Nn / 256, 256>>>(sum + Nn,     pos + Nn,     loss + 1, 0);
    k_rowloss<<<Nn / 256, 256>>>(sum + 2 * Nn, pos + 2 * Nn, loss + 2, 1);
    k_rowloss<<<Nn / 256, 256>>>(sum + 3 * Nn, pos + 3 * Nn, loss + 3, 0);

    k_final<<<1, 1>>>((float*)d_out);
}

// round 10
// speedup vs baseline: 3.4088x; 1.0402x over previous
#include <cuda_runtime.h>
#include <cuda_fp16.h>
#include <cstdint>
#include <math.h>

#define Nn   8192
#define Din  512
#define Dout 256
#define Ne   131072
#define AH   16
#define LDH  264   // loss smem stride (halves): 528B, conflict-free ldmatrix
#define NW   256   // bitmask words per row
#define LDK  72    // gemm_h chunk stride (halves)

// ---------------- static scratch ----------------
static __device__ float g_Y[Nn*Din];
static __device__ float g_Hadj[Nn*Dout];
static __device__ float g_Hx[Nn*Dout];
static __device__ float g_Hf[Nn*Dout];
static __device__ float g_Zf[Nn*Dout];
static __device__ __half g_featH[Nn*Din];
static __device__ __half g_H1h[Nn*Din];
static __device__ __half g_Zah[Nn*Dout];
static __device__ __half g_Zxh[Nn*Dout];
static __device__ __half g_Zfh[Nn*Dout];
static __device__ __half g_Wt[2*(Din*Din + Din*Dout)];
static __device__ float g_deg[4*Nn];
static __device__ float g_nrm[4*Nn];
static __device__ int   g_off[2*(Nn+1)];
static __device__ int   g_cursor[2*Nn];
static __device__ int   g_eidx[2*Ne];
static __device__ unsigned g_bits[3u*Nn*NW];
static __device__ float g_dcraw[Din*Dout];
static __device__ float g_Cn[Din*Dout];
static __device__ float g_colsum[Din];
static __device__ float g_sum[4*Nn];
static __device__ float g_pos[4*Nn];
static __device__ float g_loss[4];

__device__ __forceinline__ unsigned int saddr(const void* p) {
    return (unsigned int)__cvta_generic_to_shared(p);
}
__device__ __forceinline__ void cpasync16(unsigned int dst, const void* src) {
    asm volatile("cp.async.cg.shared.global [%0], [%1], 16;" :: "r"(dst), "l"(src));
}
__device__ __forceinline__ void cpcommit() { asm volatile("cp.async.commit_group;"); }
__device__ __forceinline__ void cpwait0()  { asm volatile("cp.async.wait_group 0;"); }

// ---------------- graph preprocessing ----------------
__global__ void k_degree(const int* __restrict__ src, const int* __restrict__ dst,
                         float* degO, float* degI) {
    int t = blockIdx.x * 256 + threadIdx.x;
    if (t < Ne) { atomicAdd(degO + src[t], 1.f); atomicAdd(degI + dst[t], 1.f); }
}

__global__ void k_norm() {
    int t = blockIdx.x * 256 + threadIdx.x;
    if (t < 4 * Nn) { float d = g_deg[t]; g_nrm[t] = (d > 0.f) ? rsqrtf(d) : 0.f; }
}

__global__ void k_scan(const float* __restrict__ degIn, int* __restrict__ off) {
    __shared__ int part[1024];
    int t = threadIdx.x;
    int v[8]; int s = 0;
    #pragma unroll
    for (int i = 0; i < 8; i++) { v[i] = s; s += (int)degIn[t * 8 + i]; }
    part[t] = s;
    __syncthreads();
    for (int d = 1; d < 1024; d <<= 1) {
        int x = (t >= d) ? part[t - d] : 0;
        __syncthreads();
        part[t] += x;
        __syncthreads();
    }
    int base = (t > 0) ? part[t - 1] : 0;
    #pragma unroll
    for (int i = 0; i < 8; i++) off[t * 8 + i] = base + v[i];
    if (t == 1023) off[Nn] = part[1023];
}

__global__ void k_bucket(const int* __restrict__ src, const int* __restrict__ dst,
                         const int* __restrict__ off, int* __restrict__ cursor,
                         int* __restrict__ eidx) {
    int t = blockIdx.x * 256 + threadIdx.x;
    if (t >= Ne) return;
    int d = dst[t];
    int p = atomicAdd(&cursor[d], 1);
    eidx[off[d] + p] = src[t];
}

// fp32-output gather (layer 2)
__global__ void k_gather(const int* __restrict__ off, const int* __restrict__ eidx,
                         const float* __restrict__ Y, const float* __restrict__ ns,
                         const float* __restrict__ nd, const float* __restrict__ bias,
                         float* __restrict__ H, int C4) {
    int n = blockIdx.x, c = threadIdx.x;
    int s0 = off[n], s1 = off[n + 1];
    float4 acc = {0.f, 0.f, 0.f, 0.f};
    for (int i = s0; i < s1; i++) {
        int s = eidx[i];
        float w = ns[s];
        float4 v = ((const float4*)Y)[(size_t)s * C4 + c];
        acc.x += v.x * w; acc.y += v.y * w; acc.z += v.z * w; acc.w += v.w * w;
    }
    float sc = nd[n];
    float4 b = ((const float4*)bias)[c];
    float4 o;
    o.x = acc.x * sc + b.x; o.y = acc.y * sc + b.y;
    o.z = acc.z * sc + b.z; o.w = acc.w * sc + b.w;
    ((float4*)H)[(size_t)n * C4 + c] = o;
}

// half-output gather with relu (layer 1: feeds next fp16 GEMM directly)
__global__ void k_gather_h(const int* __restrict__ off, const int* __restrict__ eidx,
                           const float* __restrict__ Y, const float* __restrict__ ns,
                           const float* __restrict__ nd, const float* __restrict__ bias,
                           __half* __restrict__ H, int C4) {
    int n = blockIdx.x, c = threadIdx.x;
    int s0 = off[n], s1 = off[n + 1];
    float4 acc = {0.f, 0.f, 0.f, 0.f};
    for (int i = s0; i < s1; i++) {
        int s = eidx[i];
        float w = ns[s];
        float4 v = ((const float4*)Y)[(size_t)s * C4 + c];
        acc.x += v.x * w; acc.y += v.y * w; acc.z += v.z * w; acc.w += v.w * w;
    }
    float sc = nd[n];
    float4 b = ((const float4*)bias)[c];
    float ox = fmaxf(acc.x * sc + b.x, 0.f);
    float oy = fmaxf(acc.y * sc + b.y, 0.f);
    float oz = fmaxf(acc.z * sc + b.z, 0.f);
    float ow = fmaxf(acc.w * sc + b.w, 0.f);
    ((__half2*)H)[((size_t)n * C4 + c) * 2 + 0] = __floats2half2_rn(ox, oy);
    ((__half2*)H)[((size_t)n * C4 + c) * 2 + 1] = __floats2half2_rn(oz, ow);
}

__global__ void k_pack(const float* __restrict__ a, unsigned* __restrict__ bits) {
    size_t w = (size_t)blockIdx.x * 8 + (threadIdx.x >> 5);
    int lane = threadIdx.x & 31;
    float v = __ldcs(&a[w * 32 + lane]);
    unsigned m = __ballot_sync(0xffffffffu, v != 0.f);
    if (lane == 0) bits[w] = m;
}

// ---------------- conversions ----------------
__global__ void k_f2h(const float* __restrict__ in, __half* __restrict__ out, int n4) {
    int i = blockIdx.x * 256 + threadIdx.x;
    if (i >= n4) return;
    float4 v = ((const float4*)in)[i];
    ((__half2*)out)[i * 2 + 0] = __floats2half2_rn(v.x, v.y);
    ((__half2*)out)[i * 2 + 1] = __floats2half2_rn(v.z, v.w);
}

__global__ void k_wth(const float* __restrict__ W, __half* __restrict__ Wt, int K, int N) {
    int i = blockIdx.x * 256 + threadIdx.x;
    if (i >= K * N) return;
    int k = i / N, n = i % N;
    Wt[(size_t)n * K + k] = __float2half(W[i]);
}

// ---------------- fp16 tensor-core GEMM: C = A[MxK] @ Bt[NcxK]^T ----------------
__global__ __launch_bounds__(256)
void k_gemm_h(const __half* __restrict__ A, const __half* __restrict__ Bt,
              float* __restrict__ C, int Nc, int K) {
    extern __shared__ __half sg[];
    __half* As = sg;
    __half* Bs = sg + 2 * 128 * LDK;
    const int BUF = 128 * LDK;
    const int tid = threadIdx.x;
    const int lane = tid & 31, warp = tid >> 5;
    const int wm = warp >> 1, wn = warp & 1;
    const int r0 = blockIdx.x * 128, c0 = blockIdx.y * 128;

    const int mat = lane >> 3, r = lane & 7;
    unsigned int aB[2], bB[4];
    #pragma unroll
    for (int am = 0; am < 2; am++) {
        int row = wm * 32 + am * 16 + (mat & 1) * 8 + r;
        aB[am] = saddr(&As[row * LDK + (mat >> 1) * 8]);
    }
    #pragma unroll
    for (int p = 0; p < 4; p++) {
        int row = wn * 64 + p * 16 + (mat >> 1) * 8 + r;
        bB[p] = saddr(&Bs[row * LDK + (mat & 1) * 8]);
    }

    float acc[2][8][4] = {};
    const int nch = K / 64;

    #pragma unroll
    for (int i = 0; i < 4; i++) {
        int idx = tid + i * 256;
        int row = idx >> 3, c8 = (idx & 7) * 8;
        cpasync16(saddr(&As[row * LDK + c8]), &A[(size_t)(r0 + row) * K + c8]);
        cpasync16(saddr(&Bs[row * LDK + c8]), &Bt[(size_t)(c0 + row) * K + c8]);
    }
    cpcommit();

    for (int ch = 0; ch < nch; ch++) {
        int p = ch & 1;
        cpwait0();
        __syncthreads();
        if (ch + 1 < nch) {
            int np = 1 - p, k0g = (ch + 1) * 64;
            #pragma unroll
            for (int i = 0; i < 4; i++) {
                int idx = tid + i * 256;
                int row = idx >> 3, c8 = (idx & 7) * 8;
                cpasync16(saddr(&As[np * BUF + row * LDK + c8]),
                          &A[(size_t)(r0 + row) * K + k0g + c8]);
                cpasync16(saddr(&Bs[np * BUF + row * LDK + c8]),
                          &Bt[(size_t)(c0 + row) * K + k0g + c8]);
            }
            cpcommit();
        }
        const unsigned int bufOff = p * BUF * 2;
        #pragma unroll
        for (int k0 = 0; k0 < 64; k0 += 16) {
            unsigned int a[2][4], b[4][4];
            #pragma unroll
            for (int am = 0; am < 2; am++)
                asm volatile("ldmatrix.sync.aligned.m8n8.x4.shared.b16 {%0,%1,%2,%3}, [%4];"
                    : "=r"(a[am][0]), "=r"(a[am][1]), "=r"(a[am][2]), "=r"(a[am][3])
                    : "r"(aB[am] + bufOff + k0 * 2));
            #pragma unroll
            for (int q = 0; q < 4; q++)
                asm volatile("ldmatrix.sync.aligned.m8n8.x4.shared.b16 {%0,%1,%2,%3}, [%4];"
                    : "=r"(b[q][0]), "=r"(b[q][1]), "=r"(b[q][2]), "=r"(b[q][3])
                    : "r"(bB[q] + bufOff + k0 * 2));
            #pragma unroll
            for (int am = 0; am < 2; am++)
                #pragma unroll
                for (int an = 0; an < 8; an++) {
                    int q = an >> 1, s = (an & 1) * 2;
                    asm volatile(
                        "mma.sync.aligned.m16n8k16.row.col.f32.f16.f16.f32 "
                        "{%0,%1,%2,%3}, {%4,%5,%6,%7}, {%8,%9}, {%0,%1,%2,%3};"
                        : "+f"(acc[am][an][0]), "+f"(acc[am][an][1]),
                          "+f"(acc[am][an][2]), "+f"(acc[am][an][3])
                        : "r"(a[am][0]), "r"(a[am][1]), "r"(a[am][2]), "r"(a[am][3]),
                          "r"(b[q][s]), "r"(b[q][s + 1]));
                }
        }
        __syncthreads();
    }

    #pragma unroll
    for (int am = 0; am < 2; am++) {
        int row = r0 + wm * 32 + am * 16 + (lane >> 2);
        #pragma unroll
        for (int an = 0; an < 8; an++) {
            int col = c0 + wn * 64 + an * 8 + (lane & 3) * 2;
            *(float2*)&C[(size_t)row * Nc + col] =
                make_float2(acc[am][an][0], acc[am][an][1]);
            *(float2*)&C[(size_t)(row + 8) * Nc + col] =
                make_float2(acc[am][an][2], acc[am][an][3]);
        }
    }
}

// ---------------- symmetric contrastive loss, resident-A + double-buffered B ----------------
// CTA x keeps Z rows [x*128..) resident. Iterates t over its half of [0,33):
// tile (rows x, cols j=(x+t)%64). Row sums accumulate in registers across t;
// col sums (rows of j, transposed bits staged per tile) merge per tile.
__global__ __launch_bounds__(256)
void k_loss_sym(const __half* __restrict__ Zh, const unsigned* __restrict__ bits,
                float* __restrict__ sumG, float* __restrict__ posG) {
    const int x = blockIdx.x, s = blockIdx.y;
    const int tmax = (x < 32) ? 33 : 32;
    const int tBeg = (s == 0) ? 0 : 17;
    const int tEnd = (s == 0) ? 17 : tmax;
    const int r0 = x * 128;

    extern __shared__ __half sh[];
    __half* As = sh;                                     // [128][LDH]
    __half* Bs = sh + 128 * LDH;                         // [2][128][LDH]
    unsigned* bitsS = (unsigned*)(sh + 3 * 128 * LDH);   // [2][512]
    const unsigned int BUFB = 128 * LDH * 2;             // bytes per B buffer

    const int tid = threadIdx.x;
    const int lane = tid & 31, warp = tid >> 5;
    const int wm = warp >> 1, wn = warp & 1;

    // resident A tile (plain loads, once)
    for (int t = tid; t < 4096; t += 256) {
        int row = t >> 5, c8 = (t & 31) * 8;
        *(float4*)&As[row * LDH + c8] =
            *(const float4*)&Zh[(size_t)(r0 + row) * Dout + c8];
    }

    const int mat = lane >> 3, r = lane & 7;
    unsigned int aBase[2], bBase[4];
    #pragma unroll
    for (int am = 0; am < 2; am++) {
        int row = wm * 32 + am * 16 + (mat & 1) * 8 + r;
        aBase[am] = saddr(&As[row * LDH + (mat >> 1) * 8]);
    }
    #pragma unroll
    for (int p = 0; p < 4; p++) {
        int row = wn * 64 + p * 16 + (mat >> 1) * 8 + r;
        bBase[p] = saddr(&Bs[row * LDH + (mat & 1) * 8]);
    }

    // prefetch first B tile + its transposed bits into buffer 0
    {
        int j = (x + tBeg) & 63;
        int c0 = j * 128;
        #pragma unroll
        for (int i = 0; i < 16; i++) {
            int idx = tid + i * 256;
            int row = idx >> 5, c8 = (idx & 31) * 8;
            cpasync16(saddr(&Bs[row * LDH + c8]),
                      &Zh[(size_t)(c0 + row) * Dout + c8]);
        }
        cpcommit();
        if (tid < 128)
            *(uint4*)&bitsS[tid * 4] =
                *(const uint4*)&bits[(size_t)(c0 + tid) * NW + (r0 >> 5)];
    }

    float rs[4] = {}, rp[4] = {};
    const int bitPos = (lane & 3) * 2;
    int pbuf = 0;

    for (int t = tBeg; t < tEnd; t++) {
        const int j = (x + t) & 63;
        const int c0 = j * 128;
        cpwait0();
        __syncthreads();
        if (t + 1 < tEnd) {
            int np = 1 - pbuf;
            int jn = (x + t + 1) & 63;
            int c0n = jn * 128;
            #pragma unroll
            for (int i = 0; i < 16; i++) {
                int idx = tid + i * 256;
                int row = idx >> 5, c8 = (idx & 31) * 8;
                cpasync16(saddr(&Bs[np * 128 * LDH + row * LDH + c8]),
                          &Zh[(size_t)(c0n + row) * Dout + c8]);
            }
            cpcommit();
            if (tid < 128)
                *(uint4*)&bitsS[np * 512 + tid * 4] =
                    *(const uint4*)&bits[(size_t)(c0n + tid) * NW + (r0 >> 5)];
        }
        const unsigned int bOff = pbuf * BUFB;

        float acc[2][8][4] = {};
        #pragma unroll
        for (int k0 = 0; k0 < Dout; k0 += 16) {
            unsigned int a[2][4], b[4][4];
            #pragma unroll
            for (int am = 0; am < 2; am++)
                asm volatile("ldmatrix.sync.aligned.m8n8.x4.shared.b16 {%0,%1,%2,%3}, [%4];"
                    : "=r"(a[am][0]), "=r"(a[am][1]), "=r"(a[am][2]), "=r"(a[am][3])
                    : "r"(aBase[am] + k0 * 2));
            #pragma unroll
            for (int p = 0; p < 4; p++)
                asm volatile("ldmatrix.sync.aligned.m8n8.x4.shared.b16 {%0,%1,%2,%3}, [%4];"
                    : "=r"(b[p][0]), "=r"(b[p][1]), "=r"(b[p][2]), "=r"(b[p][3])
                    : "r"(bBase[p] + bOff + k0 * 2));
            #pragma unroll
            for (int am = 0; am < 2; am++)
                #pragma unroll
                for (int an = 0; an < 8; an++) {
                    int p = an >> 1, q = (an & 1) * 2;
                    asm volatile(
                        "mma.sync.aligned.m16n8k16.row.col.f32.f16.f16.f32 "
                        "{%0,%1,%2,%3}, {%4,%5,%6,%7}, {%8,%9}, {%0,%1,%2,%3};"
                        : "+f"(acc[am][an][0]), "+f"(acc[am][an][1]),
                          "+f"(acc[am][an][2]), "+f"(acc[am][an][3])
                        : "r"(a[am][0]), "r"(a[am][1]), "r"(a[am][2]), "r"(a[am][3]),
                          "r"(b[p][q]), "r"(b[p][q + 1]));
                }
        }

        // epilogue: row sums (persistent) + col sums (per tile, skip diagonal t==0)
        const bool doCol = (t != 0);
        const int wbase = (c0 >> 5) + wn * 2;
        float cs[8][2] = {}, cp[8][2] = {};
        #pragma unroll
        for (int am = 0; am < 2; am++) {
            int baseRow = wm * 32 + am * 16;
            int row0 = r0 + baseRow + (lane >> 2);
            uint2 wA = *(const uint2*)&bits[(size_t)row0 * NW + wbase];
            uint2 wB = *(const uint2*)&bits[(size_t)(row0 + 8) * NW + wbase];
            int wi = baseRow >> 5;
            int bp0 = (baseRow & 31) + (lane >> 2);
            #pragma unroll
            for (int an = 0; an < 8; an++) {
                unsigned ma = (an < 4) ? wA.x : wA.y;
                unsigned mb = (an < 4) ? wB.x : wB.y;
                int pos = (an & 3) * 8 + bitPos;
                float e0 = __expf(acc[am][an][0]);
                float e1 = __expf(acc[am][an][1]);
                float e2 = __expf(acc[am][an][2]);
                float e3 = __expf(acc[am][an][3]);
                rs[am * 2 + 0] += e0 + e1;
                rs[am * 2 + 1] += e2 + e3;
                if ((ma >> pos) & 1u)       rp[am * 2 + 0] += e0;
                if ((ma >> (pos + 1)) & 1u) rp[am * 2 + 0] += e1;
                if ((mb >> pos) & 1u)       rp[am * 2 + 1] += e2;
                if ((mb >> (pos + 1)) & 1u) rp[am * 2 + 1] += e3;
                if (doCol) {
                    int colLoc = wn * 64 + an * 8 + (lane & 3) * 2;
                    unsigned w0 = bitsS[pbuf * 512 + colLoc * 4 + wi];
                    unsigned w1 = bitsS[pbuf * 512 + (colLoc + 1) * 4 + wi];
                    cs[an][0] += e0 + e2;
                    cs[an][1] += e1 + e3;
                    if ((w0 >> bp0) & 1u)       cp[an][0] += e0;
                    if ((w0 >> (bp0 + 8)) & 1u) cp[an][0] += e2;
                    if ((w1 >> bp0) & 1u)       cp[an][1] += e1;
                    if ((w1 >> (bp0 + 8)) & 1u) cp[an][1] += e3;
                }
            }
        }
        if (doCol) {
            #pragma unroll
            for (int an = 0; an < 8; an++) {
                #pragma unroll
                for (int jj = 0; jj < 2; jj++) {
                    float v = cs[an][jj], p = cp[an][jj];
                    v += __shfl_xor_sync(0xffffffffu, v, 4);
                    v += __shfl_xor_sync(0xffffffffu, v, 8);
                    v += __shfl_xor_sync(0xffffffffu, v, 16);
                    p += __shfl_xor_sync(0xffffffffu, p, 4);
                    p += __shfl_xor_sync(0xffffffffu, p, 8);
                    p += __shfl_xor_sync(0xffffffffu, p, 16);
                    if (lane < 4) {
                        int col = c0 + wn * 64 + an * 8 + lane * 2 + jj;
                        atomicAdd(&sumG[col], v);
                        atomicAdd(&posG[col], p);
                    }
                }
            }
        }
        pbuf ^= 1;
    }

    // row-part merge (once per CTA)
    #pragma unroll
    for (int q = 0; q < 4; q++) {
        float v = rs[q], p = rp[q];
        v += __shfl_xor_sync(0xffffffffu, v, 1);
        v += __shfl_xor_sync(0xffffffffu, v, 2);
        p += __shfl_xor_sync(0xffffffffu, p, 1);
        p += __shfl_xor_sync(0xffffffffu, p, 2);
        if ((lane & 3) == 0) {
            int row = r0 + wm * 32 + (q >> 1) * 16 + (q & 1) * 8 + (lane >> 2);
            atomicAdd(&sumG[row], v);
            atomicAdd(&posG[row], p);
        }
    }
}

// C[MxN] += A^T@B over K-slice (fp32, for dim_center)
__global__ __launch_bounds__(256, 2)
void k_atb(const float* __restrict__ A, const float* __restrict__ B,
           float* __restrict__ C, int M, int Nc, int kPerSlice) {
    __shared__ float As[32][132];
    __shared__ float Bs[32][132];
    int tid = threadIdx.x, tx = tid & 15, ty = tid >> 4;
    int r0 = blockIdx.x * 128, c0 = blockIdx.y * 128;
    int kb = blockIdx.z * kPerSlice;
    int ty8 = ty * 8, tx8 = tx * 8;
    float acc[8][8] = {};
    for (int k0 = kb; k0 < kb + kPerSlice; k0 += 32) {
        for (int t = tid; t < 4096; t += 256) {
            int m = t & 127, k = t >> 7;
            As[k][m] = A[(size_t)(k0 + k) * M + r0 + m];
        }
        for (int t = tid; t < 4096; t += 256) {
            int n = t & 127, k = t >> 7;
            Bs[k][n] = B[(size_t)(k0 + k) * Nc + c0 + n];
        }
        __syncthreads();
        #pragma unroll 8
        for (int k = 0; k < 32; k++) {
            float a[8], b[8];
            #pragma unroll
            for (int i = 0; i < 8; i++) a[i] = As[k][ty8 + i];
            #pragma unroll
            for (int j = 0; j < 8; j++) b[j] = Bs[k][tx8 + j];
            #pragma unroll
            for (int i = 0; i < 8; i++)
                #pragma unroll
                for (int j = 0; j < 8; j++) acc[i][j] = fmaf(a[i], b[j], acc[i][j]);
        }
        __syncthreads();
    }
    for (int i = 0; i < 8; i++) {
        size_t r = (size_t)(r0 + ty8 + i) * Nc + c0 + tx8;
        #pragma unroll
        for (int j = 0; j < 8; j++) atomicAdd(&C[r + j], acc[i][j]);
    }
}

// fused dim-label loss (fp32)
__global__ __launch_bounds__(256, 2)
void k_loss_dim(const float* __restrict__ Z, const float* __restrict__ Cn,
                const float* __restrict__ feat,
                float* __restrict__ sumG, float* __restrict__ posG) {
    __shared__ float As[32][132];
    __shared__ float Bs[32][132];
    int tid = threadIdx.x, tx = tid & 15, ty = tid >> 4;
    int r0 = blockIdx.x * 128;
    int c0 = blockIdx.y * 128;
    int ty8 = ty * 8, tx8 = tx * 8;
    float acc[8][8] = {};
    for (int k0 = 0; k0 < Dout; k0 += 32) {
        for (int t = tid; t < 4096; t += 256) {
            int k = t & 31, m = t >> 5;
            As[k][m] = Z[(size_t)(r0 + m) * Dout + k0 + k];
        }
        for (int t = tid; t < 4096; t += 256) {
            int k = t & 31, m = t >> 5;
            Bs[k][m] = Cn[(size_t)(c0 + m) * Dout + k0 + k];
        }
        __syncthreads();
        #pragma unroll 8
        for (int k = 0; k < 32; k++) {
            float a[8], b[8];
            #pragma unroll
            for (int i = 0; i < 8; i++) a[i] = As[k][ty8 + i];
            #pragma unroll
            for (int j = 0; j < 8; j++) b[j] = Bs[k][tx8 + j];
            #pragma unroll
            for (int i = 0; i < 8; i++)
                #pragma unroll
                for (int j = 0; j < 8; j++) acc[i][j] = fmaf(a[i], b[j], acc[i][j]);
        }
        __syncthreads();
    }
    for (int i = 0; i < 8; i++) {
        int rr = r0 + ty8 + i;
        const float* frow = feat + (size_t)rr * Din + c0 + tx8;
        float sA = 0.f, pA = 0.f;
        #pragma unroll
        for (int j = 0; j < 8; j++) {
            float e = __expf(acc[i][j]);
            sA += e;
            if (frow[j] > 0.f) pA += e;
        }
        atomicAdd(&sumG[rr], sA);
        atomicAdd(&posG[rr], pA);
    }
}

__global__ void k_rowloss(const float* __restrict__ sumG, const float* __restrict__ posG,
                          float* loss, int mode) {
    __shared__ float red[256];
    int t = blockIdx.x * 256 + threadIdx.x;
    float term = 0.f;
    if (t < Nn) {
        float pos = posG[t], tot = sumG[t];
        float neg = tot - pos;
        if (mode == 0) term = -logf((pos + 1e-10f) / (neg + 1e-10f));
        else           term = -logf((pos + 1e-10f) / neg + 1e-5f);
    }
    red[threadIdx.x] = term;
    __syncthreads();
    for (int s = 128; s; s >>= 1) {
        if (threadIdx.x < s) red[threadIdx.x] += red[threadIdx.x + s];
        __syncthreads();
    }
    if (threadIdx.x == 0) atomicAdd(loss, red[0]);
}

// ---------------- attention fuse + norms + centers ----------------
__global__ void k_attention(const float* __restrict__ Wp1, const float* __restrict__ bp1,
                            const float* __restrict__ wp2) {
    int nid = blockIdx.x * 256 + threadIdx.x;
    if (nid >= Nn) return;
    const float* hx = g_Hx + (size_t)nid * Dout;
    const float* ha = g_Hadj + (size_t)nid * Dout;
    float accx[AH], acca[AH];
    #pragma unroll
    for (int h = 0; h < AH; h++) { accx[h] = bp1[h]; acca[h] = bp1[h]; }
    for (int d = 0; d < Dout; d++) {
        float vx = hx[d], va = ha[d];
        #pragma unroll
        for (int h = 0; h < AH; h++) {
            float w = Wp1[d * AH + h];
            accx[h] += vx * w; acca[h] += va * w;
        }
    }
    float wx = 0.f, wa = 0.f;
    #pragma unroll
    for (int h = 0; h < AH; h++) {
        wx += tanhf(accx[h]) * wp2[h];
        wa += tanhf(acca[h]) * wp2[h];
    }
    float m = fmaxf(wx, wa);
    float ex = __expf(wx - m), ea = __expf(wa - m);
    float inv = 1.f / (ex + ea);
    float bx = ex * inv, ba = ea * inv;
    float* out = g_Hf + (size_t)nid * Dout;
    for (int d = 0; d < Dout; d++) out[d] = bx * hx[d] + ba * ha[d];
}

__global__ void k_l2norm(const float* __restrict__ in, __half* __restrict__ outH,
                         float* __restrict__ outF, int rows, int cols) {
    int w = (blockIdx.x * blockDim.x + threadIdx.x) >> 5;
    int lane = threadIdx.x & 31;
    if (w >= rows) return;
    const float* r = in + (size_t)w * cols;
    float ss = 0.f;
    for (int c = lane; c < cols; c += 32) { float v = r[c]; ss += v * v; }
    for (int o = 16; o; o >>= 1) ss += __shfl_xor_sync(0xffffffffu, ss, o);
    float inv = 1.f / fmaxf(sqrtf(ss), 1e-12f);
    __half* wh = outH + (size_t)w * cols;
    for (int c = lane; c < cols; c += 32) {
        float v = r[c] * inv;
        wh[c] = __float2half(v);
        if (outF) outF[(size_t)w * cols + c] = v;
    }
}

__global__ void k_colsum(const float* __restrict__ feat) {
    int c = blockIdx.x * 256 + threadIdx.x;
    int rbeg = blockIdx.y * 128;
    float s = 0.f;
    for (int i = rbeg; i < rbeg + 128; i++) s += feat[(size_t)i * Din + c];
    atomicAdd(&g_colsum[c], s);
}

__global__ void k_center() {
    int w = (blockIdx.x * blockDim.x + threadIdx.x) >> 5;
    int lane = threadIdx.x & 31;
    if (w >= Din) return;
    float s = g_colsum[w] + 1e-5f;
    float inv_s = 1.f / s;
    float v[8]; float ss = 0.f;
    #pragma unroll
    for (int i = 0; i < 8; i++) {
        v[i] = g_dcraw[(size_t)w * Dout + lane + 32 * i] * inv_s;
        ss += v[i] * v[i];
    }
    for (int o = 16; o; o >>= 1) ss += __shfl_xor_sync(0xffffffffu, ss, o);
    float inv = 1.f / fmaxf(sqrtf(ss), 1e-12f);
    #pragma unroll
    for (int i = 0; i < 8; i++) g_Cn[(size_t)w * Dout + lane + 32 * i] = v[i] * inv;
}

__global__ void k_final(float* out) {
    out[0] = (0.5f * (g_loss[0] + g_loss[1]) + 0.1f * g_loss[2] + g_loss[3]) * (1.0f / Nn);
}

// ---------------- host ----------------
extern "C" void kernel_launch(void* const* d_in, const int* in_sizes, int n_in,
                              void* d_out, int out_size) {
    const float* feat = (const float*)d_in[0];
    const float* adjL = (const float*)d_in[1];
    const float* adjX = (const float*)d_in[2];
    const float* adjR = (const float*)d_in[3];

    const int *eA, *eX; int pb;
    if (in_sizes[5] == 262144) { eA = (const int*)d_in[4]; eX = (const int*)d_in[5]; pb = 6; }
    else                       { pb = 4; eA = (const int*)d_in[15]; eX = (const int*)d_in[16]; }

    const float* W0a = (const float*)d_in[pb + 0];
    const float* b0a = (const float*)d_in[pb + 1];
    const float* W1a = (const float*)d_in[pb + 2];
    const float* b1a = (const float*)d_in[pb + 3];
    const float* W0x = (const float*)d_in[pb + 4];
    const float* b0x = (const float*)d_in[pb + 5];
    const float* W1x = (const float*)d_in[pb + 6];
    const float* b1x = (const float*)d_in[pb + 7];
    const float* Wp1 = (const float*)d_in[pb + 8];
    const float* bp1 = (const float*)d_in[pb + 9];
    const float* wp2 = (const float*)d_in[pb + 10];

    static int smemSet = 0;
    const int LOSS_SMEM = 3 * 128 * LDH * (int)sizeof(__half) + 4096;  // 206848
    const int GEMM_SMEM = 4 * 128 * LDK * (int)sizeof(__half);
    if (!smemSet) {
        cudaFuncSetAttribute(k_loss_sym, cudaFuncAttributeMaxDynamicSharedMemorySize, LOSS_SMEM);
        cudaFuncSetAttribute(k_gemm_h, cudaFuncAttributeMaxDynamicSharedMemorySize, GEMM_SMEM);
        smemSet = 1;
    }

    void *pY, *pHadj, *pHx, *pHf, *pZf, *pFH, *pH1h, *pZah, *pZxh, *pZfh, *pWt;
    void *pDeg, *pNrm, *pOff, *pCur, *pEidx, *pBits;
    void *pDc, *pCn, *pCs, *pSum, *pPos, *pLoss;
    cudaGetSymbolAddress(&pY, g_Y);
    cudaGetSymbolAddress(&pHadj, g_Hadj); cudaGetSymbolAddress(&pHx, g_Hx);
    cudaGetSymbolAddress(&pHf, g_Hf);     cudaGetSymbolAddress(&pZf, g_Zf);
    cudaGetSymbolAddress(&pFH, g_featH);  cudaGetSymbolAddress(&pH1h, g_H1h);
    cudaGetSymbolAddress(&pZah, g_Zah);   cudaGetSymbolAddress(&pZxh, g_Zxh);
    cudaGetSymbolAddress(&pZfh, g_Zfh);   cudaGetSymbolAddress(&pWt, g_Wt);
    cudaGetSymbolAddress(&pDeg, g_deg);   cudaGetSymbolAddress(&pNrm, g_nrm);
    cudaGetSymbolAddress(&pOff, g_off);   cudaGetSymbolAddress(&pCur, g_cursor);
    cudaGetSymbolAddress(&pEidx, g_eidx); cudaGetSymbolAddress(&pBits, g_bits);
    cudaGetSymbolAddress(&pDc, g_dcraw);  cudaGetSymbolAddress(&pCn, g_Cn);
    cudaGetSymbolAddress(&pCs, g_colsum); cudaGetSymbolAddress(&pSum, g_sum);
    cudaGetSymbolAddress(&pPos, g_pos);   cudaGetSymbolAddress(&pLoss, g_loss);

    float* deg = (float*)pDeg;
    float* nrm = (float*)pNrm;
    float* nsA = nrm;           float* ndA = nrm + Nn;
    float* nsX = nrm + 2 * Nn;  float* ndX = nrm + 3 * Nn;
    int* offA = (int*)pOff;     int* offX = offA + (Nn + 1);
    int* eidxA = (int*)pEidx;   int* eidxX = eidxA + Ne;
    unsigned* bitsL = (unsigned*)pBits;
    unsigned* bitsX = bitsL + (size_t)Nn * NW;
    unsigned* bitsR = bitsX + (size_t)Nn * NW;
    __half* featH = (__half*)pFH;
    __half* H1h = (__half*)pH1h;
    __half* W0aT = (__half*)pWt;
    __half* W1aT = W0aT + Din * Din;
    __half* W0xT = W1aT + Din * Dout;
    __half* W1xT = W0xT + Din * Din;
    float* sum = (float*)pSum;  float* pos = (float*)pPos;
    float* loss = (float*)pLoss;

    // ---- preprocessing ----
    cudaMemsetAsync(pDeg, 0, 4 * Nn * sizeof(float));
    cudaMemsetAsync(pCur, 0, 2 * Nn * sizeof(int));
    k_degree<<<(Ne + 255) / 256, 256>>>(eA, eA + Ne, deg, deg + Nn);
    k_degree<<<(Ne + 255) / 256, 256>>>(eX, eX + Ne, deg + 2 * Nn, deg + 3 * Nn);
    k_norm<<<(4 * Nn) / 256, 256>>>();
    k_scan<<<1, 1024>>>(deg + Nn, offA);
    k_scan<<<1, 1024>>>(deg + 3 * Nn, offX);
    k_bucket<<<(Ne + 255) / 256, 256>>>(eA, eA + Ne, offA, (int*)pCur, eidxA);
    k_bucket<<<(Ne + 255) / 256, 256>>>(eX, eX + Ne, offX, (int*)pCur + Nn, eidxX);

    const int packBlocks = (Nn * NW) / 8;
    k_pack<<<packBlocks, 256>>>(adjL, bitsL);
    k_pack<<<packBlocks, 256>>>(adjX, bitsX);
    k_pack<<<packBlocks, 256>>>(adjR, bitsR);

    // ---- weight + feature conversion ----
    k_f2h<<<(Nn * Din / 4 + 255) / 256, 256>>>(feat, featH, Nn * Din / 4);
    k_wth<<<(Din * Din + 255) / 256, 256>>>(W0a, W0aT, Din, Din);
    k_wth<<<(Din * Dout + 255) / 256, 256>>>(W1a, W1aT, Din, Dout);
    k_wth<<<(Din * Din + 255) / 256, 256>>>(W0x, W0xT, Din, Din);
    k_wth<<<(Din * Dout + 255) / 256, 256>>>(W1x, W1xT, Din, Dout);

    // ---- GCN over graph A ----
    k_gemm_h<<<dim3(Nn / 128, Din / 128), 256, GEMM_SMEM>>>(featH, W0aT, (float*)pY, Din, Din);
    k_gather_h<<<Nn, Din / 4>>>(offA, eidxA, (float*)pY, nsA, ndA, b0a, H1h, Din / 4);
    k_gemm_h<<<dim3(Nn / 128, Dout / 128), 256, GEMM_SMEM>>>(H1h, W1aT, (float*)pY, Dout, Din);
    k_gather<<<Nn, Dout / 4>>>(offA, eidxA, (float*)pY, nsA, ndA, b1a, (float*)pHadj, Dout / 4);

    // ---- GCN over graph X ----
    k_gemm_h<<<dim3(Nn / 128, Din / 128), 256, GEMM_SMEM>>>(featH, W0xT, (float*)pY, Din, Din);
    k_gather_h<<<Nn, Din / 4>>>(offX, eidxX, (float*)pY, nsX, ndX, b0x, H1h, Din / 4);
    k_gemm_h<<<dim3(Nn / 128, Dout / 128), 256, GEMM_SMEM>>>(H1h, W1xT, (float*)pY, Dout, Din);
    k_gather<<<Nn, Dout / 4>>>(offX, eidxX, (float*)pY, nsX, ndX, b1x, (float*)pHx, Dout / 4);

    // ---- attention fusion + normalization ----
    k_attention<<<Nn / 256, 256>>>(Wp1, bp1, wp2);
    k_l2norm<<<Nn / 8, 256>>>((float*)pHadj, (__half*)pZah, nullptr, Nn, Dout);
    k_l2norm<<<Nn / 8, 256>>>((float*)pHx,   (__half*)pZxh, nullptr, Nn, Dout);
    k_l2norm<<<Nn / 8, 256>>>((float*)pHf,   (__half*)pZfh, (float*)pZf, Nn, Dout);

    // ---- dim_center ----
    cudaMemsetAsync(pCs, 0, Din * sizeof(float));
    k_colsum<<<dim3(2, 64), 256>>>(feat);
    cudaMemsetAsync(pDc, 0, (size_t)Din * Dout * sizeof(float));
    k_atb<<<dim3(Din / 128, Dout / 128, 32), 256>>>(feat, (float*)pHf, (float*)pDc, Din, Dout, Nn / 32);
    k_center<<<Din / 8, 256>>>();

    // ---- losses ----
    cudaMemsetAsync(pSum, 0, 4 * Nn * sizeof(float));
    cudaMemsetAsync(pPos, 0, 4 * Nn * sizeof(float));
    cudaMemsetAsync(pLoss, 0, 4 * sizeof(float));
    k_loss_sym<<<dim3(64, 2), 256, LOSS_SMEM>>>((const __half*)pZah, bitsL, sum,          pos);
    k_loss_sym<<<dim3(64, 2), 256, LOSS_SMEM>>>((const __half*)pZxh, bitsX, sum + Nn,     pos + Nn);
    k_loss_dim<<<dim3(Nn / 128, Din / 128), 256>>>((float*)pZf, (float*)pCn, feat,
                                                   sum + 2 * Nn, pos + 2 * Nn);
    k_loss_sym<<<dim3(64, 2), 256, LOSS_SMEM>>>((const __half*)pZfh, bitsR, sum + 3 * Nn, pos + 3 * Nn);

    k_rowloss<<<Nn / 256, 256>>>(sum,          pos,          loss + 0, 0);
    k_rowloss<<<Nn / 256, 256>>>(sum + Nn,     pos + Nn,     loss + 1, 0);
    k_rowloss<<<Nn / 256, 256>>>(sum + 2 * Nn, pos + 2 * Nn, loss + 2, 1);
    k_rowloss<<<Nn / 256, 256>>>(sum + 3 * Nn, pos + 3 * Nn, loss + 3, 0);

    k_final<<<1, 1>>>((float*)d_out);
}

// round 11
// speedup vs baseline: 3.5564x; 1.0433x over previous
#include <cuda_runtime.h>
#include <cuda_fp16.h>
#include <cstdint>
#include <math.h>

#define Nn   8192
#define Din  512
#define Dout 256
#define Ne   131072
#define AH   16
#define LDH  264   // loss smem stride (halves): 528B, conflict-free ldmatrix
#define NW   256   // bitmask words per row
#define LDK  72    // gemm_h chunk stride (halves)

// ---------------- static scratch ----------------
static __device__ float g_Y[Nn*Din];
static __device__ float g_Y2[Nn*Din];
static __device__ float g_Hadj[Nn*Dout];
static __device__ float g_Hx[Nn*Dout];
static __device__ float g_Hf[Nn*Dout];
static __device__ float g_Zf[Nn*Dout];
static __device__ __half g_featH[Nn*Din];
static __device__ __half g_H1h[Nn*Din];
static __device__ __half g_H1h2[Nn*Din];
static __device__ __half g_Zah[Nn*Dout];
static __device__ __half g_Zxh[Nn*Dout];
static __device__ __half g_Zfh[Nn*Dout];
static __device__ __half g_Wt[2*(Din*Din + Din*Dout)];
static __device__ float g_deg[4*Nn];
static __device__ float g_nrm[4*Nn];
static __device__ int   g_off[2*(Nn+1)];
static __device__ int   g_cursor[2*Nn];
static __device__ int   g_eidx[2*Ne];
static __device__ unsigned g_bits[3u*Nn*NW];
static __device__ float g_dcraw[Din*Dout];
static __device__ float g_Cn[Din*Dout];
static __device__ float g_colsum[Din];
static __device__ float g_sum[4*Nn];
static __device__ float g_pos[4*Nn];
static __device__ float g_loss[4];

__device__ __forceinline__ unsigned int saddr(const void* p) {
    return (unsigned int)__cvta_generic_to_shared(p);
}
__device__ __forceinline__ void cpasync16(unsigned int dst, const void* src) {
    asm volatile("cp.async.cg.shared.global [%0], [%1], 16;" :: "r"(dst), "l"(src));
}
__device__ __forceinline__ void cpcommit() { asm volatile("cp.async.commit_group;"); }
__device__ __forceinline__ void cpwait0()  { asm volatile("cp.async.wait_group 0;"); }

// ---------------- graph preprocessing ----------------
__global__ void k_degree(const int* __restrict__ src, const int* __restrict__ dst,
                         float* degO, float* degI) {
    int t = blockIdx.x * 256 + threadIdx.x;
    if (t < Ne) { atomicAdd(degO + src[t], 1.f); atomicAdd(degI + dst[t], 1.f); }
}

__global__ void k_norm() {
    int t = blockIdx.x * 256 + threadIdx.x;
    if (t < 4 * Nn) { float d = g_deg[t]; g_nrm[t] = (d > 0.f) ? rsqrtf(d) : 0.f; }
}

__global__ void k_scan(const float* __restrict__ degIn, int* __restrict__ off) {
    __shared__ int part[1024];
    int t = threadIdx.x;
    int v[8]; int s = 0;
    #pragma unroll
    for (int i = 0; i < 8; i++) { v[i] = s; s += (int)degIn[t * 8 + i]; }
    part[t] = s;
    __syncthreads();
    for (int d = 1; d < 1024; d <<= 1) {
        int x = (t >= d) ? part[t - d] : 0;
        __syncthreads();
        part[t] += x;
        __syncthreads();
    }
    int base = (t > 0) ? part[t - 1] : 0;
    #pragma unroll
    for (int i = 0; i < 8; i++) off[t * 8 + i] = base + v[i];
    if (t == 1023) off[Nn] = part[1023];
}

__global__ void k_bucket(const int* __restrict__ src, const int* __restrict__ dst,
                         const int* __restrict__ off, int* __restrict__ cursor,
                         int* __restrict__ eidx) {
    int t = blockIdx.x * 256 + threadIdx.x;
    if (t >= Ne) return;
    int d = dst[t];
    int p = atomicAdd(&cursor[d], 1);
    eidx[off[d] + p] = src[t];
}

__global__ void k_gather(const int* __restrict__ off, const int* __restrict__ eidx,
                         const float* __restrict__ Y, const float* __restrict__ ns,
                         const float* __restrict__ nd, const float* __restrict__ bias,
                         float* __restrict__ H, int C4) {
    int n = blockIdx.x, c = threadIdx.x;
    int s0 = off[n], s1 = off[n + 1];
    float4 acc = {0.f, 0.f, 0.f, 0.f};
    for (int i = s0; i < s1; i++) {
        int s = eidx[i];
        float w = ns[s];
        float4 v = ((const float4*)Y)[(size_t)s * C4 + c];
        acc.x += v.x * w; acc.y += v.y * w; acc.z += v.z * w; acc.w += v.w * w;
    }
    float sc = nd[n];
    float4 b = ((const float4*)bias)[c];
    float4 o;
    o.x = acc.x * sc + b.x; o.y = acc.y * sc + b.y;
    o.z = acc.z * sc + b.z; o.w = acc.w * sc + b.w;
    ((float4*)H)[(size_t)n * C4 + c] = o;
}

__global__ void k_gather_h(const int* __restrict__ off, const int* __restrict__ eidx,
                           const float* __restrict__ Y, const float* __restrict__ ns,
                           const float* __restrict__ nd, const float* __restrict__ bias,
                           __half* __restrict__ H, int C4) {
    int n = blockIdx.x, c = threadIdx.x;
    int s0 = off[n], s1 = off[n + 1];
    float4 acc = {0.f, 0.f, 0.f, 0.f};
    for (int i = s0; i < s1; i++) {
        int s = eidx[i];
        float w = ns[s];
        float4 v = ((const float4*)Y)[(size_t)s * C4 + c];
        acc.x += v.x * w; acc.y += v.y * w; acc.z += v.z * w; acc.w += v.w * w;
    }
    float sc = nd[n];
    float4 b = ((const float4*)bias)[c];
    float ox = fmaxf(acc.x * sc + b.x, 0.f);
    float oy = fmaxf(acc.y * sc + b.y, 0.f);
    float oz = fmaxf(acc.z * sc + b.z, 0.f);
    float ow = fmaxf(acc.w * sc + b.w, 0.f);
    ((__half2*)H)[((size_t)n * C4 + c) * 2 + 0] = __floats2half2_rn(ox, oy);
    ((__half2*)H)[((size_t)n * C4 + c) * 2 + 1] = __floats2half2_rn(oz, ow);
}

__global__ void k_pack(const float* __restrict__ a, unsigned* __restrict__ bits) {
    size_t w = (size_t)blockIdx.x * 8 + (threadIdx.x >> 5);
    int lane = threadIdx.x & 31;
    float v = __ldcs(&a[w * 32 + lane]);
    unsigned m = __ballot_sync(0xffffffffu, v != 0.f);
    if (lane == 0) bits[w] = m;
}

// ---------------- conversions ----------------
__global__ void k_f2h(const float* __restrict__ in, __half* __restrict__ out, int n4) {
    int i = blockIdx.x * 256 + threadIdx.x;
    if (i >= n4) return;
    float4 v = ((const float4*)in)[i];
    ((__half2*)out)[i * 2 + 0] = __floats2half2_rn(v.x, v.y);
    ((__half2*)out)[i * 2 + 1] = __floats2half2_rn(v.z, v.w);
}

__global__ void k_wth(const float* __restrict__ W, __half* __restrict__ Wt, int K, int N) {
    int i = blockIdx.x * 256 + threadIdx.x;
    if (i >= K * N) return;
    int k = i / N, n = i % N;
    Wt[(size_t)n * K + k] = __float2half(W[i]);
}

// ---------------- fp16 tensor-core GEMM: C = A[MxK] @ Bt[NcxK]^T ----------------
__global__ __launch_bounds__(256)
void k_gemm_h(const __half* __restrict__ A, const __half* __restrict__ Bt,
              float* __restrict__ C, int Nc, int K) {
    extern __shared__ __half sg[];
    __half* As = sg;
    __half* Bs = sg + 2 * 128 * LDK;
    const int BUF = 128 * LDK;
    const int tid = threadIdx.x;
    const int lane = tid & 31, warp = tid >> 5;
    const int wm = warp >> 1, wn = warp & 1;
    const int r0 = blockIdx.x * 128, c0 = blockIdx.y * 128;

    const int mat = lane >> 3, r = lane & 7;
    unsigned int aB[2], bB[4];
    #pragma unroll
    for (int am = 0; am < 2; am++) {
        int row = wm * 32 + am * 16 + (mat & 1) * 8 + r;
        aB[am] = saddr(&As[row * LDK + (mat >> 1) * 8]);
    }
    #pragma unroll
    for (int p = 0; p < 4; p++) {
        int row = wn * 64 + p * 16 + (mat >> 1) * 8 + r;
        bB[p] = saddr(&Bs[row * LDK + (mat & 1) * 8]);
    }

    float acc[2][8][4] = {};
    const int nch = K / 64;

    #pragma unroll
    for (int i = 0; i < 4; i++) {
        int idx = tid + i * 256;
        int row = idx >> 3, c8 = (idx & 7) * 8;
        cpasync16(saddr(&As[row * LDK + c8]), &A[(size_t)(r0 + row) * K + c8]);
        cpasync16(saddr(&Bs[row * LDK + c8]), &Bt[(size_t)(c0 + row) * K + c8]);
    }
    cpcommit();

    for (int ch = 0; ch < nch; ch++) {
        int p = ch & 1;
        cpwait0();
        __syncthreads();
        if (ch + 1 < nch) {
            int np = 1 - p, k0g = (ch + 1) * 64;
            #pragma unroll
            for (int i = 0; i < 4; i++) {
                int idx = tid + i * 256;
                int row = idx >> 3, c8 = (idx & 7) * 8;
                cpasync16(saddr(&As[np * BUF + row * LDK + c8]),
                          &A[(size_t)(r0 + row) * K + k0g + c8]);
                cpasync16(saddr(&Bs[np * BUF + row * LDK + c8]),
                          &Bt[(size_t)(c0 + row) * K + k0g + c8]);
            }
            cpcommit();
        }
        const unsigned int bufOff = p * BUF * 2;
        #pragma unroll
        for (int k0 = 0; k0 < 64; k0 += 16) {
            unsigned int a[2][4], b[4][4];
            #pragma unroll
            for (int am = 0; am < 2; am++)
                asm volatile("ldmatrix.sync.aligned.m8n8.x4.shared.b16 {%0,%1,%2,%3}, [%4];"
                    : "=r"(a[am][0]), "=r"(a[am][1]), "=r"(a[am][2]), "=r"(a[am][3])
                    : "r"(aB[am] + bufOff + k0 * 2));
            #pragma unroll
            for (int q = 0; q < 4; q++)
                asm volatile("ldmatrix.sync.aligned.m8n8.x4.shared.b16 {%0,%1,%2,%3}, [%4];"
                    : "=r"(b[q][0]), "=r"(b[q][1]), "=r"(b[q][2]), "=r"(b[q][3])
                    : "r"(bB[q] + bufOff + k0 * 2));
            #pragma unroll
            for (int am = 0; am < 2; am++)
                #pragma unroll
                for (int an = 0; an < 8; an++) {
                    int q = an >> 1, s = (an & 1) * 2;
                    asm volatile(
                        "mma.sync.aligned.m16n8k16.row.col.f32.f16.f16.f32 "
                        "{%0,%1,%2,%3}, {%4,%5,%6,%7}, {%8,%9}, {%0,%1,%2,%3};"
                        : "+f"(acc[am][an][0]), "+f"(acc[am][an][1]),
                          "+f"(acc[am][an][2]), "+f"(acc[am][an][3])
                        : "r"(a[am][0]), "r"(a[am][1]), "r"(a[am][2]), "r"(a[am][3]),
                          "r"(b[q][s]), "r"(b[q][s + 1]));
                }
        }
        __syncthreads();
    }

    #pragma unroll
    for (int am = 0; am < 2; am++) {
        int row = r0 + wm * 32 + am * 16 + (lane >> 2);
        #pragma unroll
        for (int an = 0; an < 8; an++) {
            int col = c0 + wn * 64 + an * 8 + (lane & 3) * 2;
            *(float2*)&C[(size_t)row * Nc + col] =
                make_float2(acc[am][an][0], acc[am][an][1]);
            *(float2*)&C[(size_t)(row + 8) * Nc + col] =
                make_float2(acc[am][an][2], acc[am][an][3]);
        }
    }
}

// ---------------- symmetric contrastive loss, resident-A + double-buffered B ----------------
__global__ __launch_bounds__(256)
void k_loss_sym(const __half* __restrict__ Zh, const unsigned* __restrict__ bits,
                float* __restrict__ sumG, float* __restrict__ posG) {
    const int x = blockIdx.x, s = blockIdx.y;
    const int tmax = (x < 32) ? 33 : 32;
    const int tBeg = (s == 0) ? 0 : 17;
    const int tEnd = (s == 0) ? 17 : tmax;
    const int r0 = x * 128;

    extern __shared__ __half sh[];
    __half* As = sh;                                     // [128][LDH]
    __half* Bs = sh + 128 * LDH;                         // [2][128][LDH]
    unsigned* bitsS = (unsigned*)(sh + 3 * 128 * LDH);   // [2][512]
    const unsigned int BUFB = 128 * LDH * 2;

    const int tid = threadIdx.x;
    const int lane = tid & 31, warp = tid >> 5;
    const int wm = warp >> 1, wn = warp & 1;

    for (int t = tid; t < 4096; t += 256) {
        int row = t >> 5, c8 = (t & 31) * 8;
        *(float4*)&As[row * LDH + c8] =
            *(const float4*)&Zh[(size_t)(r0 + row) * Dout + c8];
    }

    const int mat = lane >> 3, r = lane & 7;
    unsigned int aBase[2], bBase[4];
    #pragma unroll
    for (int am = 0; am < 2; am++) {
        int row = wm * 32 + am * 16 + (mat & 1) * 8 + r;
        aBase[am] = saddr(&As[row * LDH + (mat >> 1) * 8]);
    }
    #pragma unroll
    for (int p = 0; p < 4; p++) {
        int row = wn * 64 + p * 16 + (mat >> 1) * 8 + r;
        bBase[p] = saddr(&Bs[row * LDH + (mat & 1) * 8]);
    }

    {
        int j = (x + tBeg) & 63;
        int c0 = j * 128;
        #pragma unroll
        for (int i = 0; i < 16; i++) {
            int idx = tid + i * 256;
            int row = idx >> 5, c8 = (idx & 31) * 8;
            cpasync16(saddr(&Bs[row * LDH + c8]),
                      &Zh[(size_t)(c0 + row) * Dout + c8]);
        }
        cpcommit();
        if (tid < 128)
            *(uint4*)&bitsS[tid * 4] =
                *(const uint4*)&bits[(size_t)(c0 + tid) * NW + (r0 >> 5)];
    }

    float rs[4] = {}, rp[4] = {};
    const int bitPos = (lane & 3) * 2;
    int pbuf = 0;

    for (int t = tBeg; t < tEnd; t++) {
        const int j = (x + t) & 63;
        const int c0 = j * 128;
        cpwait0();
        __syncthreads();
        if (t + 1 < tEnd) {
            int np = 1 - pbuf;
            int jn = (x + t + 1) & 63;
            int c0n = jn * 128;
            #pragma unroll
            for (int i = 0; i < 16; i++) {
                int idx = tid + i * 256;
                int row = idx >> 5, c8 = (idx & 31) * 8;
                cpasync16(saddr(&Bs[np * 128 * LDH + row * LDH + c8]),
                          &Zh[(size_t)(c0n + row) * Dout + c8]);
            }
            cpcommit();
            if (tid < 128)
                *(uint4*)&bitsS[np * 512 + tid * 4] =
                    *(const uint4*)&bits[(size_t)(c0n + tid) * NW + (r0 >> 5)];
        }
        const unsigned int bOff = pbuf * BUFB;

        float acc[2][8][4] = {};
        #pragma unroll
        for (int k0 = 0; k0 < Dout; k0 += 16) {
            unsigned int a[2][4], b[4][4];
            #pragma unroll
            for (int am = 0; am < 2; am++)
                asm volatile("ldmatrix.sync.aligned.m8n8.x4.shared.b16 {%0,%1,%2,%3}, [%4];"
                    : "=r"(a[am][0]), "=r"(a[am][1]), "=r"(a[am][2]), "=r"(a[am][3])
                    : "r"(aBase[am] + k0 * 2));
            #pragma unroll
            for (int p = 0; p < 4; p++)
                asm volatile("ldmatrix.sync.aligned.m8n8.x4.shared.b16 {%0,%1,%2,%3}, [%4];"
                    : "=r"(b[p][0]), "=r"(b[p][1]), "=r"(b[p][2]), "=r"(b[p][3])
                    : "r"(bBase[p] + bOff + k0 * 2));
            #pragma unroll
            for (int am = 0; am < 2; am++)
                #pragma unroll
                for (int an = 0; an < 8; an++) {
                    int p = an >> 1, q = (an & 1) * 2;
                    asm volatile(
                        "mma.sync.aligned.m16n8k16.row.col.f32.f16.f16.f32 "
                        "{%0,%1,%2,%3}, {%4,%5,%6,%7}, {%8,%9}, {%0,%1,%2,%3};"
                        : "+f"(acc[am][an][0]), "+f"(acc[am][an][1]),
                          "+f"(acc[am][an][2]), "+f"(acc[am][an][3])
                        : "r"(a[am][0]), "r"(a[am][1]), "r"(a[am][2]), "r"(a[am][3]),
                          "r"(b[p][q]), "r"(b[p][q + 1]));
                }
        }

        const bool doCol = (t != 0);
        const int wbase = (c0 >> 5) + wn * 2;
        float cs[8][2] = {}, cp[8][2] = {};
        #pragma unroll
        for (int am = 0; am < 2; am++) {
            int baseRow = wm * 32 + am * 16;
            int row0 = r0 + baseRow + (lane >> 2);
            uint2 wA = *(const uint2*)&bits[(size_t)row0 * NW + wbase];
            uint2 wB = *(const uint2*)&bits[(size_t)(row0 + 8) * NW + wbase];
            int wi = baseRow >> 5;
            int bp0 = (baseRow & 31) + (lane >> 2);
            #pragma unroll
            for (int an = 0; an < 8; an++) {
                unsigned ma = (an < 4) ? wA.x : wA.y;
                unsigned mb = (an < 4) ? wB.x : wB.y;
                int pos = (an & 3) * 8 + bitPos;
                float e0 = __expf(acc[am][an][0]);
                float e1 = __expf(acc[am][an][1]);
                float e2 = __expf(acc[am][an][2]);
                float e3 = __expf(acc[am][an][3]);
                rs[am * 2 + 0] += e0 + e1;
                rs[am * 2 + 1] += e2 + e3;
                if ((ma >> pos) & 1u)       rp[am * 2 + 0] += e0;
                if ((ma >> (pos + 1)) & 1u) rp[am * 2 + 0] += e1;
                if ((mb >> pos) & 1u)       rp[am * 2 + 1] += e2;
                if ((mb >> (pos + 1)) & 1u) rp[am * 2 + 1] += e3;
                if (doCol) {
                    int colLoc = wn * 64 + an * 8 + (lane & 3) * 2;
                    unsigned w0 = bitsS[pbuf * 512 + colLoc * 4 + wi];
                    unsigned w1 = bitsS[pbuf * 512 + (colLoc + 1) * 4 + wi];
                    cs[an][0] += e0 + e2;
                    cs[an][1] += e1 + e3;
                    if ((w0 >> bp0) & 1u)       cp[an][0] += e0;
                    if ((w0 >> (bp0 + 8)) & 1u) cp[an][0] += e2;
                    if ((w1 >> bp0) & 1u)       cp[an][1] += e1;
                    if ((w1 >> (bp0 + 8)) & 1u) cp[an][1] += e3;
                }
            }
        }
        if (doCol) {
            #pragma unroll
            for (int an = 0; an < 8; an++) {
                #pragma unroll
                for (int jj = 0; jj < 2; jj++) {
                    float v = cs[an][jj], p = cp[an][jj];
                    v += __shfl_xor_sync(0xffffffffu, v, 4);
                    v += __shfl_xor_sync(0xffffffffu, v, 8);
                    v += __shfl_xor_sync(0xffffffffu, v, 16);
                    p += __shfl_xor_sync(0xffffffffu, p, 4);
                    p += __shfl_xor_sync(0xffffffffu, p, 8);
                    p += __shfl_xor_sync(0xffffffffu, p, 16);
                    if (lane < 4) {
                        int col = c0 + wn * 64 + an * 8 + lane * 2 + jj;
                        atomicAdd(&sumG[col], v);
                        atomicAdd(&posG[col], p);
                    }
                }
            }
        }
        pbuf ^= 1;
    }

    #pragma unroll
    for (int q = 0; q < 4; q++) {
        float v = rs[q], p = rp[q];
        v += __shfl_xor_sync(0xffffffffu, v, 1);
        v += __shfl_xor_sync(0xffffffffu, v, 2);
        p += __shfl_xor_sync(0xffffffffu, p, 1);
        p += __shfl_xor_sync(0xffffffffu, p, 2);
        if ((lane & 3) == 0) {
            int row = r0 + wm * 32 + (q >> 1) * 16 + (q & 1) * 8 + (lane >> 2);
            atomicAdd(&sumG[row], v);
            atomicAdd(&posG[row], p);
        }
    }
}

// C[MxN] += A^T@B over K-slice (fp32, for dim_center)
__global__ __launch_bounds__(256, 2)
void k_atb(const float* __restrict__ A, const float* __restrict__ B,
           float* __restrict__ C, int M, int Nc, int kPerSlice) {
    __shared__ float As[32][132];
    __shared__ float Bs[32][132];
    int tid = threadIdx.x, tx = tid & 15, ty = tid >> 4;
    int r0 = blockIdx.x * 128, c0 = blockIdx.y * 128;
    int kb = blockIdx.z * kPerSlice;
    int ty8 = ty * 8, tx8 = tx * 8;
    float acc[8][8] = {};
    for (int k0 = kb; k0 < kb + kPerSlice; k0 += 32) {
        for (int t = tid; t < 4096; t += 256) {
            int m = t & 127, k = t >> 7;
            As[k][m] = A[(size_t)(k0 + k) * M + r0 + m];
        }
        for (int t = tid; t < 4096; t += 256) {
            int n = t & 127, k = t >> 7;
            Bs[k][n] = B[(size_t)(k0 + k) * Nc + c0 + n];
        }
        __syncthreads();
        #pragma unroll 8
        for (int k = 0; k < 32; k++) {
            float a[8], b[8];
            #pragma unroll
            for (int i = 0; i < 8; i++) a[i] = As[k][ty8 + i];
            #pragma unroll
            for (int j = 0; j < 8; j++) b[j] = Bs[k][tx8 + j];
            #pragma unroll
            for (int i = 0; i < 8; i++)
                #pragma unroll
                for (int j = 0; j < 8; j++) acc[i][j] = fmaf(a[i], b[j], acc[i][j]);
        }
        __syncthreads();
    }
    for (int i = 0; i < 8; i++) {
        size_t r = (size_t)(r0 + ty8 + i) * Nc + c0 + tx8;
        #pragma unroll
        for (int j = 0; j < 8; j++) atomicAdd(&C[r + j], acc[i][j]);
    }
}

// fused dim-label loss (fp32)
__global__ __launch_bounds__(256, 2)
void k_loss_dim(const float* __restrict__ Z, const float* __restrict__ Cn,
                const float* __restrict__ feat,
                float* __restrict__ sumG, float* __restrict__ posG) {
    __shared__ float As[32][132];
    __shared__ float Bs[32][132];
    int tid = threadIdx.x, tx = tid & 15, ty = tid >> 4;
    int r0 = blockIdx.x * 128;
    int c0 = blockIdx.y * 128;
    int ty8 = ty * 8, tx8 = tx * 8;
    float acc[8][8] = {};
    for (int k0 = 0; k0 < Dout; k0 += 32) {
        for (int t = tid; t < 4096; t += 256) {
            int k = t & 31, m = t >> 5;
            As[k][m] = Z[(size_t)(r0 + m) * Dout + k0 + k];
        }
        for (int t = tid; t < 4096; t += 256) {
            int k = t & 31, m = t >> 5;
            Bs[k][m] = Cn[(size_t)(c0 + m) * Dout + k0 + k];
        }
        __syncthreads();
        #pragma unroll 8
        for (int k = 0; k < 32; k++) {
            float a[8], b[8];
            #pragma unroll
            for (int i = 0; i < 8; i++) a[i] = As[k][ty8 + i];
            #pragma unroll
            for (int j = 0; j < 8; j++) b[j] = Bs[k][tx8 + j];
            #pragma unroll
            for (int i = 0; i < 8; i++)
                #pragma unroll
                for (int j = 0; j < 8; j++) acc[i][j] = fmaf(a[i], b[j], acc[i][j]);
        }
        __syncthreads();
    }
    for (int i = 0; i < 8; i++) {
        int rr = r0 + ty8 + i;
        const float* frow = feat + (size_t)rr * Din + c0 + tx8;
        float sA = 0.f, pA = 0.f;
        #pragma unroll
        for (int j = 0; j < 8; j++) {
            float e = __expf(acc[i][j]);
            sA += e;
            if (frow[j] > 0.f) pA += e;
        }
        atomicAdd(&sumG[rr], sA);
        atomicAdd(&posG[rr], pA);
    }
}

__global__ void k_rowloss(const float* __restrict__ sumG, const float* __restrict__ posG,
                          float* loss, int mode) {
    __shared__ float red[256];
    int t = blockIdx.x * 256 + threadIdx.x;
    float term = 0.f;
    if (t < Nn) {
        float pos = posG[t], tot = sumG[t];
        float neg = tot - pos;
        if (mode == 0) term = -logf((pos + 1e-10f) / (neg + 1e-10f));
        else           term = -logf((pos + 1e-10f) / neg + 1e-5f);
    }
    red[threadIdx.x] = term;
    __syncthreads();
    for (int s = 128; s; s >>= 1) {
        if (threadIdx.x < s) red[threadIdx.x] += red[threadIdx.x + s];
        __syncthreads();
    }
    if (threadIdx.x == 0) atomicAdd(loss, red[0]);
}

// ---------------- attention fuse + norms + centers ----------------
__global__ void k_attention(const float* __restrict__ Wp1, const float* __restrict__ bp1,
                            const float* __restrict__ wp2) {
    int nid = blockIdx.x * 256 + threadIdx.x;
    if (nid >= Nn) return;
    const float* hx = g_Hx + (size_t)nid * Dout;
    const float* ha = g_Hadj + (size_t)nid * Dout;
    float accx[AH], acca[AH];
    #pragma unroll
    for (int h = 0; h < AH; h++) { accx[h] = bp1[h]; acca[h] = bp1[h]; }
    for (int d = 0; d < Dout; d++) {
        float vx = hx[d], va = ha[d];
        #pragma unroll
        for (int h = 0; h < AH; h++) {
            float w = Wp1[d * AH + h];
            accx[h] += vx * w; acca[h] += va * w;
        }
    }
    float wx = 0.f, wa = 0.f;
    #pragma unroll
    for (int h = 0; h < AH; h++) {
        wx += tanhf(accx[h]) * wp2[h];
        wa += tanhf(acca[h]) * wp2[h];
    }
    float m = fmaxf(wx, wa);
    float ex = __expf(wx - m), ea = __expf(wa - m);
    float inv = 1.f / (ex + ea);
    float bx = ex * inv, ba = ea * inv;
    float* out = g_Hf + (size_t)nid * Dout;
    for (int d = 0; d < Dout; d++) out[d] = bx * hx[d] + ba * ha[d];
}

__global__ void k_l2norm(const float* __restrict__ in, __half* __restrict__ outH,
                         float* __restrict__ outF, int rows, int cols) {
    int w = (blockIdx.x * blockDim.x + threadIdx.x) >> 5;
    int lane = threadIdx.x & 31;
    if (w >= rows) return;
    const float* r = in + (size_t)w * cols;
    float ss = 0.f;
    for (int c = lane; c < cols; c += 32) { float v = r[c]; ss += v * v; }
    for (int o = 16; o; o >>= 1) ss += __shfl_xor_sync(0xffffffffu, ss, o);
    float inv = 1.f / fmaxf(sqrtf(ss), 1e-12f);
    __half* wh = outH + (size_t)w * cols;
    for (int c = lane; c < cols; c += 32) {
        float v = r[c] * inv;
        wh[c] = __float2half(v);
        if (outF) outF[(size_t)w * cols + c] = v;
    }
}

__global__ void k_colsum(const float* __restrict__ feat) {
    int c = blockIdx.x * 256 + threadIdx.x;
    int rbeg = blockIdx.y * 128;
    float s = 0.f;
    for (int i = rbeg; i < rbeg + 128; i++) s += feat[(size_t)i * Din + c];
    atomicAdd(&g_colsum[c], s);
}

__global__ void k_center() {
    int w = (blockIdx.x * blockDim.x + threadIdx.x) >> 5;
    int lane = threadIdx.x & 31;
    if (w >= Din) return;
    float s = g_colsum[w] + 1e-5f;
    float inv_s = 1.f / s;
    float v[8]; float ss = 0.f;
    #pragma unroll
    for (int i = 0; i < 8; i++) {
        v[i] = g_dcraw[(size_t)w * Dout + lane + 32 * i] * inv_s;
        ss += v[i] * v[i];
    }
    for (int o = 16; o; o >>= 1) ss += __shfl_xor_sync(0xffffffffu, ss, o);
    float inv = 1.f / fmaxf(sqrtf(ss), 1e-12f);
    #pragma unroll
    for (int i = 0; i < 8; i++) g_Cn[(size_t)w * Dout + lane + 32 * i] = v[i] * inv;
}

__global__ void k_final(float* out) {
    out[0] = (0.5f * (g_loss[0] + g_loss[1]) + 0.1f * g_loss[2] + g_loss[3]) * (1.0f / Nn);
}

// ---------------- host ----------------
extern "C" void kernel_launch(void* const* d_in, const int* in_sizes, int n_in,
                              void* d_out, int out_size) {
    const float* feat = (const float*)d_in[0];
    const float* adjL = (const float*)d_in[1];
    const float* adjX = (const float*)d_in[2];
    const float* adjR = (const float*)d_in[3];

    const int *eA, *eX; int pb;
    if (in_sizes[5] == 262144) { eA = (const int*)d_in[4]; eX = (const int*)d_in[5]; pb = 6; }
    else                       { pb = 4; eA = (const int*)d_in[15]; eX = (const int*)d_in[16]; }

    const float* W0a = (const float*)d_in[pb + 0];
    const float* b0a = (const float*)d_in[pb + 1];
    const float* W1a = (const float*)d_in[pb + 2];
    const float* b1a = (const float*)d_in[pb + 3];
    const float* W0x = (const float*)d_in[pb + 4];
    const float* b0x = (const float*)d_in[pb + 5];
    const float* W1x = (const float*)d_in[pb + 6];
    const float* b1x = (const float*)d_in[pb + 7];
    const float* Wp1 = (const float*)d_in[pb + 8];
    const float* bp1 = (const float*)d_in[pb + 9];
    const float* wp2 = (const float*)d_in[pb + 10];

    const int LOSS_SMEM = 3 * 128 * LDH * (int)sizeof(__half) + 4096;  // 206848
    const int GEMM_SMEM = 4 * 128 * LDK * (int)sizeof(__half);

    // one-time host resources (no device memory; graph replays never rerun host code)
    static int inited = 0;
    static cudaStream_t s1, s2, s3;
    static cudaEvent_t eStart, eConv, ePrep, ePack, eZero, eHadj, eZxh, eZf, eL1, eL2, eL3;
    if (!inited) {
        cudaFuncSetAttribute(k_loss_sym, cudaFuncAttributeMaxDynamicSharedMemorySize, LOSS_SMEM);
        cudaFuncSetAttribute(k_gemm_h, cudaFuncAttributeMaxDynamicSharedMemorySize, GEMM_SMEM);
        cudaStreamCreateWithFlags(&s1, cudaStreamNonBlocking);
        cudaStreamCreateWithFlags(&s2, cudaStreamNonBlocking);
        cudaStreamCreateWithFlags(&s3, cudaStreamNonBlocking);
        cudaEventCreateWithFlags(&eStart, cudaEventDisableTiming);
        cudaEventCreateWithFlags(&eConv,  cudaEventDisableTiming);
        cudaEventCreateWithFlags(&ePrep,  cudaEventDisableTiming);
        cudaEventCreateWithFlags(&ePack,  cudaEventDisableTiming);
        cudaEventCreateWithFlags(&eZero,  cudaEventDisableTiming);
        cudaEventCreateWithFlags(&eHadj,  cudaEventDisableTiming);
        cudaEventCreateWithFlags(&eZxh,   cudaEventDisableTiming);
        cudaEventCreateWithFlags(&eZf,    cudaEventDisableTiming);
        cudaEventCreateWithFlags(&eL1,    cudaEventDisableTiming);
        cudaEventCreateWithFlags(&eL2,    cudaEventDisableTiming);
        cudaEventCreateWithFlags(&eL3,    cudaEventDisableTiming);
        inited = 1;
    }

    void *pY, *pY2, *pHadj, *pHx, *pHf, *pZf, *pFH, *pH1h, *pH1h2, *pZah, *pZxh, *pZfh, *pWt;
    void *pDeg, *pNrm, *pOff, *pCur, *pEidx, *pBits;
    void *pDc, *pCn, *pCs, *pSum, *pPos, *pLoss;
    cudaGetSymbolAddress(&pY, g_Y);       cudaGetSymbolAddress(&pY2, g_Y2);
    cudaGetSymbolAddress(&pHadj, g_Hadj); cudaGetSymbolAddress(&pHx, g_Hx);
    cudaGetSymbolAddress(&pHf, g_Hf);     cudaGetSymbolAddress(&pZf, g_Zf);
    cudaGetSymbolAddress(&pFH, g_featH);  cudaGetSymbolAddress(&pH1h, g_H1h);
    cudaGetSymbolAddress(&pH1h2, g_H1h2);
    cudaGetSymbolAddress(&pZah, g_Zah);   cudaGetSymbolAddress(&pZxh, g_Zxh);
    cudaGetSymbolAddress(&pZfh, g_Zfh);   cudaGetSymbolAddress(&pWt, g_Wt);
    cudaGetSymbolAddress(&pDeg, g_deg);   cudaGetSymbolAddress(&pNrm, g_nrm);
    cudaGetSymbolAddress(&pOff, g_off);   cudaGetSymbolAddress(&pCur, g_cursor);
    cudaGetSymbolAddress(&pEidx, g_eidx); cudaGetSymbolAddress(&pBits, g_bits);
    cudaGetSymbolAddress(&pDc, g_dcraw);  cudaGetSymbolAddress(&pCn, g_Cn);
    cudaGetSymbolAddress(&pCs, g_colsum); cudaGetSymbolAddress(&pSum, g_sum);
    cudaGetSymbolAddress(&pPos, g_pos);   cudaGetSymbolAddress(&pLoss, g_loss);

    float* deg = (float*)pDeg;
    float* nrm = (float*)pNrm;
    float* nsA = nrm;           float* ndA = nrm + Nn;
    float* nsX = nrm + 2 * Nn;  float* ndX = nrm + 3 * Nn;
    int* offA = (int*)pOff;     int* offX = offA + (Nn + 1);
    int* eidxA = (int*)pEidx;   int* eidxX = eidxA + Ne;
    unsigned* bitsL = (unsigned*)pBits;
    unsigned* bitsX = bitsL + (size_t)Nn * NW;
    unsigned* bitsR = bitsX + (size_t)Nn * NW;
    __half* featH = (__half*)pFH;
    __half* H1h = (__half*)pH1h;
    __half* H1h2 = (__half*)pH1h2;
    __half* W0aT = (__half*)pWt;
    __half* W1aT = W0aT + Din * Din;
    __half* W0xT = W1aT + Din * Dout;
    __half* W1xT = W0xT + Din * Din;
    float* sum = (float*)pSum;  float* pos = (float*)pPos;
    float* loss = (float*)pLoss;
    const int packBlocks = (Nn * NW) / 8;

    // ---- fork ----
    cudaEventRecord(eStart, 0);
    cudaStreamWaitEvent(s1, eStart, 0);
    cudaStreamWaitEvent(s2, eStart, 0);

    // ---- s2: zeroing + colsum + packs ----
    cudaMemsetAsync(pCs, 0, Din * sizeof(float), s2);
    cudaMemsetAsync(pDc, 0, (size_t)Din * Dout * sizeof(float), s2);
    cudaMemsetAsync(pSum, 0, 4 * Nn * sizeof(float), s2);
    cudaMemsetAsync(pPos, 0, 4 * Nn * sizeof(float), s2);
    cudaMemsetAsync(pLoss, 0, 4 * sizeof(float), s2);
    k_colsum<<<dim3(2, 64), 256, 0, s2>>>(feat);
    cudaEventRecord(eZero, s2);
    k_pack<<<packBlocks, 256, 0, s2>>>(adjL, bitsL);
    k_pack<<<packBlocks, 256, 0, s2>>>(adjX, bitsX);
    k_pack<<<packBlocks, 256, 0, s2>>>(adjR, bitsR);
    cudaEventRecord(ePack, s2);

    // ---- s1: conversions + branch A start ----
    k_f2h<<<(Nn * Din / 4 + 255) / 256, 256, 0, s1>>>(feat, featH, Nn * Din / 4);
    k_wth<<<(Din * Din + 255) / 256, 256, 0, s1>>>(W0a, W0aT, Din, Din);
    k_wth<<<(Din * Dout + 255) / 256, 256, 0, s1>>>(W1a, W1aT, Din, Dout);
    k_wth<<<(Din * Din + 255) / 256, 256, 0, s1>>>(W0x, W0xT, Din, Din);
    k_wth<<<(Din * Dout + 255) / 256, 256, 0, s1>>>(W1x, W1xT, Din, Dout);
    cudaEventRecord(eConv, s1);
    k_gemm_h<<<dim3(Nn / 128, Din / 128), 256, GEMM_SMEM, s1>>>(featH, W0aT, (float*)pY, Din, Din);

    // ---- s0: graph prep ----
    cudaMemsetAsync(pDeg, 0, 4 * Nn * sizeof(float), 0);
    cudaMemsetAsync(pCur, 0, 2 * Nn * sizeof(int), 0);
    k_degree<<<(Ne + 255) / 256, 256>>>(eA, eA + Ne, deg, deg + Nn);
    k_degree<<<(Ne + 255) / 256, 256>>>(eX, eX + Ne, deg + 2 * Nn, deg + 3 * Nn);
    k_norm<<<(4 * Nn) / 256, 256>>>();
    k_scan<<<1, 1024>>>(deg + Nn, offA);
    k_scan<<<1, 1024>>>(deg + 3 * Nn, offX);
    k_bucket<<<(Ne + 255) / 256, 256>>>(eA, eA + Ne, offA, (int*)pCur, eidxA);
    k_bucket<<<(Ne + 255) / 256, 256>>>(eX, eX + Ne, offX, (int*)pCur + Nn, eidxX);
    cudaEventRecord(ePrep, 0);

    // ---- s1: branch A finish + loss A ----
    cudaStreamWaitEvent(s1, ePrep, 0);
    k_gather_h<<<Nn, Din / 4, 0, s1>>>(offA, eidxA, (float*)pY, nsA, ndA, b0a, H1h, Din / 4);
    k_gemm_h<<<dim3(Nn / 128, Dout / 128), 256, GEMM_SMEM, s1>>>(H1h, W1aT, (float*)pY, Dout, Din);
    k_gather<<<Nn, Dout / 4, 0, s1>>>(offA, eidxA, (float*)pY, nsA, ndA, b1a, (float*)pHadj, Dout / 4);
    cudaEventRecord(eHadj, s1);
    k_l2norm<<<Nn / 8, 256, 0, s1>>>((float*)pHadj, (__half*)pZah, nullptr, Nn, Dout);
    cudaStreamWaitEvent(s1, ePack, 0);
    k_loss_sym<<<dim3(64, 2), 256, LOSS_SMEM, s1>>>((const __half*)pZah, bitsL, sum, pos);
    k_rowloss<<<Nn / 256, 256, 0, s1>>>(sum, pos, loss + 0, 0);
    cudaEventRecord(eL1, s1);

    // ---- s0: branch X ----
    cudaStreamWaitEvent(0, eConv, 0);
    k_gemm_h<<<dim3(Nn / 128, Din / 128), 256, GEMM_SMEM>>>(featH, W0xT, (float*)pY2, Din, Din);
    k_gather_h<<<Nn, Din / 4>>>(offX, eidxX, (float*)pY2, nsX, ndX, b0x, H1h2, Din / 4);
    k_gemm_h<<<dim3(Nn / 128, Dout / 128), 256, GEMM_SMEM>>>(H1h2, W1xT, (float*)pY2, Dout, Din);
    k_gather<<<Nn, Dout / 4>>>(offX, eidxX, (float*)pY2, nsX, ndX, b1x, (float*)pHx, Dout / 4);
    k_l2norm<<<Nn / 8, 256>>>((float*)pHx, (__half*)pZxh, nullptr, Nn, Dout);
    cudaEventRecord(eZxh, 0);

    // ---- s3: loss X ----
    cudaStreamWaitEvent(s3, eZxh, 0);
    cudaStreamWaitEvent(s3, ePack, 0);
    k_loss_sym<<<dim3(64, 2), 256, LOSS_SMEM, s3>>>((const __half*)pZxh, bitsX, sum + Nn, pos + Nn);
    k_rowloss<<<Nn / 256, 256, 0, s3>>>(sum + Nn, pos + Nn, loss + 1, 0);
    cudaEventRecord(eL2, s3);

    // ---- s0: attention + fused embedding ----
    cudaStreamWaitEvent(0, eHadj, 0);
    k_attention<<<Nn / 256, 256>>>(Wp1, bp1, wp2);
    k_l2norm<<<Nn / 8, 256>>>((float*)pHf, (__half*)pZfh, (float*)pZf, Nn, Dout);
    cudaEventRecord(eZf, 0);

    // ---- s2: loss R (fused embedding vs adj_rec) ----
    cudaStreamWaitEvent(s2, eZf, 0);
    k_loss_sym<<<dim3(64, 2), 256, LOSS_SMEM, s2>>>((const __half*)pZfh, bitsR, sum + 3 * Nn, pos + 3 * Nn);
    k_rowloss<<<Nn / 256, 256, 0, s2>>>(sum + 3 * Nn, pos + 3 * Nn, loss + 3, 0);
    cudaEventRecord(eL3, s2);

    // ---- s0: dim_center + dim loss ----
    cudaStreamWaitEvent(0, eZero, 0);
    k_atb<<<dim3(Din / 128, Dout / 128, 32), 256>>>(feat, (float*)pHf, (float*)pDc, Din, Dout, Nn / 32);
    k_center<<<Din / 8, 256>>>();
    k_loss_dim<<<dim3(Nn / 128, Din / 128), 256>>>((float*)pZf, (float*)pCn, feat,
                                                   sum + 2 * Nn, pos + 2 * Nn);
    k_rowloss<<<Nn / 256, 256>>>(sum + 2 * Nn, pos + 2 * Nn, loss + 2, 1);

    // ---- join + final ----
    cudaStreamWaitEvent(0, eL1, 0);
    cudaStreamWaitEvent(0, eL2, 0);
    cudaStreamWaitEvent(0, eL3, 0);
    k_final<<<1, 1>>>((float*)d_out);
}

// round 12
// speedup vs baseline: 4.8655x; 1.3681x over previous
#include <cuda_runtime.h>
#include <cuda_fp16.h>
#include <cstdint>
#include <math.h>

#define Nn   8192
#define Din  512
#define Dout 256
#define Ne   131072
#define AH   16
#define LDH  264   // loss smem stride (halves): 528B, conflict-free ldmatrix
#define NW   256   // bitmask words per row
#define LDK  72    // gemm_h chunk stride (halves)

// ---------------- static scratch ----------------
static __device__ float g_Y[Nn*Din];
static __device__ float g_Y2[Nn*Din];
static __device__ float g_Hadj[Nn*Dout];
static __device__ float g_Hx[Nn*Dout];
static __device__ float g_Hf[Nn*Dout];
static __device__ float g_Zf[Nn*Dout];
static __device__ __half g_featH[Nn*Din];
static __device__ __half g_H1h[Nn*Din];
static __device__ __half g_H1h2[Nn*Din];
static __device__ __half g_Zah[Nn*Dout];
static __device__ __half g_Zxh[Nn*Dout];
static __device__ __half g_Zfh[Nn*Dout];
static __device__ __half g_Wt[2*(Din*Din + Din*Dout)];
static __device__ float g_deg[4*Nn];
static __device__ float g_nrm[4*Nn];
static __device__ int   g_off[2*(Nn+1)];
static __device__ int   g_cursor[2*Nn];
static __device__ int   g_eidx[2*Ne];
static __device__ unsigned g_bits[3u*Nn*NW];
static __device__ float g_dcraw[Din*Dout];
static __device__ float g_Cn[Din*Dout];
static __device__ float g_colsum[Din];
static __device__ float g_sum[4*Nn];
static __device__ float g_pos[4*Nn];
static __device__ float g_loss[4];

__device__ __forceinline__ unsigned int saddr(const void* p) {
    return (unsigned int)__cvta_generic_to_shared(p);
}
__device__ __forceinline__ void cpasync16(unsigned int dst, const void* src) {
    asm volatile("cp.async.cg.shared.global [%0], [%1], 16;" :: "r"(dst), "l"(src));
}
__device__ __forceinline__ void cpcommit() { asm volatile("cp.async.commit_group;"); }
__device__ __forceinline__ void cpwait0()  { asm volatile("cp.async.wait_group 0;"); }

// ---------------- graph preprocessing ----------------
__global__ void k_degree(const int* __restrict__ src, const int* __restrict__ dst,
                         float* degO, float* degI) {
    int t = blockIdx.x * 256 + threadIdx.x;
    if (t < Ne) { atomicAdd(degO + src[t], 1.f); atomicAdd(degI + dst[t], 1.f); }
}

__global__ void k_norm() {
    int t = blockIdx.x * 256 + threadIdx.x;
    if (t < 4 * Nn) { float d = g_deg[t]; g_nrm[t] = (d > 0.f) ? rsqrtf(d) : 0.f; }
}

__global__ void k_scan(const float* __restrict__ degIn, int* __restrict__ off) {
    __shared__ int part[1024];
    int t = threadIdx.x;
    int v[8]; int s = 0;
    #pragma unroll
    for (int i = 0; i < 8; i++) { v[i] = s; s += (int)degIn[t * 8 + i]; }
    part[t] = s;
    __syncthreads();
    for (int d = 1; d < 1024; d <<= 1) {
        int x = (t >= d) ? part[t - d] : 0;
        __syncthreads();
        part[t] += x;
        __syncthreads();
    }
    int base = (t > 0) ? part[t - 1] : 0;
    #pragma unroll
    for (int i = 0; i < 8; i++) off[t * 8 + i] = base + v[i];
    if (t == 1023) off[Nn] = part[1023];
}

__global__ void k_bucket(const int* __restrict__ src, const int* __restrict__ dst,
                         const int* __restrict__ off, int* __restrict__ cursor,
                         int* __restrict__ eidx) {
    int t = blockIdx.x * 256 + threadIdx.x;
    if (t >= Ne) return;
    int d = dst[t];
    int p = atomicAdd(&cursor[d], 1);
    eidx[off[d] + p] = src[t];
}

__global__ void k_gather(const int* __restrict__ off, const int* __restrict__ eidx,
                         const float* __restrict__ Y, const float* __restrict__ ns,
                         const float* __restrict__ nd, const float* __restrict__ bias,
                         float* __restrict__ H, int C4) {
    int n = blockIdx.x, c = threadIdx.x;
    int s0 = off[n], s1 = off[n + 1];
    float4 acc = {0.f, 0.f, 0.f, 0.f};
    for (int i = s0; i < s1; i++) {
        int s = eidx[i];
        float w = ns[s];
        float4 v = ((const float4*)Y)[(size_t)s * C4 + c];
        acc.x += v.x * w; acc.y += v.y * w; acc.z += v.z * w; acc.w += v.w * w;
    }
    float sc = nd[n];
    float4 b = ((const float4*)bias)[c];
    float4 o;
    o.x = acc.x * sc + b.x; o.y = acc.y * sc + b.y;
    o.z = acc.z * sc + b.z; o.w = acc.w * sc + b.w;
    ((float4*)H)[(size_t)n * C4 + c] = o;
}

__global__ void k_gather_h(const int* __restrict__ off, const int* __restrict__ eidx,
                           const float* __restrict__ Y, const float* __restrict__ ns,
                           const float* __restrict__ nd, const float* __restrict__ bias,
                           __half* __restrict__ H, int C4) {
    int n = blockIdx.x, c = threadIdx.x;
    int s0 = off[n], s1 = off[n + 1];
    float4 acc = {0.f, 0.f, 0.f, 0.f};
    for (int i = s0; i < s1; i++) {
        int s = eidx[i];
        float w = ns[s];
        float4 v = ((const float4*)Y)[(size_t)s * C4 + c];
        acc.x += v.x * w; acc.y += v.y * w; acc.z += v.z * w; acc.w += v.w * w;
    }
    float sc = nd[n];
    float4 b = ((const float4*)bias)[c];
    float ox = fmaxf(acc.x * sc + b.x, 0.f);
    float oy = fmaxf(acc.y * sc + b.y, 0.f);
    float oz = fmaxf(acc.z * sc + b.z, 0.f);
    float ow = fmaxf(acc.w * sc + b.w, 0.f);
    ((__half2*)H)[((size_t)n * C4 + c) * 2 + 0] = __floats2half2_rn(ox, oy);
    ((__half2*)H)[((size_t)n * C4 + c) * 2 + 1] = __floats2half2_rn(oz, ow);
}

// MLP-8 pack: each warp builds 8 bitmask words (8 independent coalesced loads
// issued before any ballot -> 8 loads in flight per warp).
__global__ void k_pack(const float* __restrict__ a, unsigned* __restrict__ bits) {
    size_t w8 = ((size_t)blockIdx.x * 8 + (threadIdx.x >> 5)) * 8;  // first word idx
    int lane = threadIdx.x & 31;
    const float* base = a + w8 * 32 + lane;
    float v0 = __ldcs(base + 0 * 32);
    float v1 = __ldcs(base + 1 * 32);
    float v2 = __ldcs(base + 2 * 32);
    float v3 = __ldcs(base + 3 * 32);
    float v4 = __ldcs(base + 4 * 32);
    float v5 = __ldcs(base + 5 * 32);
    float v6 = __ldcs(base + 6 * 32);
    float v7 = __ldcs(base + 7 * 32);
    unsigned m0 = __ballot_sync(0xffffffffu, v0 != 0.f);
    unsigned m1 = __ballot_sync(0xffffffffu, v1 != 0.f);
    unsigned m2 = __ballot_sync(0xffffffffu, v2 != 0.f);
    unsigned m3 = __ballot_sync(0xffffffffu, v3 != 0.f);
    unsigned m4 = __ballot_sync(0xffffffffu, v4 != 0.f);
    unsigned m5 = __ballot_sync(0xffffffffu, v5 != 0.f);
    unsigned m6 = __ballot_sync(0xffffffffu, v6 != 0.f);
    unsigned m7 = __ballot_sync(0xffffffffu, v7 != 0.f);
    if (lane == 0) {
        uint4 lo = make_uint4(m0, m1, m2, m3);
        uint4 hi = make_uint4(m4, m5, m6, m7);
        *(uint4*)&bits[w8 + 0] = lo;
        *(uint4*)&bits[w8 + 4] = hi;
    }
}

// ---------------- conversions ----------------
__global__ void k_f2h(const float* __restrict__ in, __half* __restrict__ out, int n4) {
    int i = blockIdx.x * 256 + threadIdx.x;
    if (i >= n4) return;
    float4 v = ((const float4*)in)[i];
    ((__half2*)out)[i * 2 + 0] = __floats2half2_rn(v.x, v.y);
    ((__half2*)out)[i * 2 + 1] = __floats2half2_rn(v.z, v.w);
}

__global__ void k_wth(const float* __restrict__ W, __half* __restrict__ Wt, int K, int N) {
    int i = blockIdx.x * 256 + threadIdx.x;
    if (i >= K * N) return;
    int k = i / N, n = i % N;
    Wt[(size_t)n * K + k] = __float2half(W[i]);
}

// ---------------- fp16 tensor-core GEMM: C = A[MxK] @ Bt[NcxK]^T ----------------
__global__ __launch_bounds__(256)
void k_gemm_h(const __half* __restrict__ A, const __half* __restrict__ Bt,
              float* __restrict__ C, int Nc, int K) {
    extern __shared__ __half sg[];
    __half* As = sg;
    __half* Bs = sg + 2 * 128 * LDK;
    const int BUF = 128 * LDK;
    const int tid = threadIdx.x;
    const int lane = tid & 31, warp = tid >> 5;
    const int wm = warp >> 1, wn = warp & 1;
    const int r0 = blockIdx.x * 128, c0 = blockIdx.y * 128;

    const int mat = lane >> 3, r = lane & 7;
    unsigned int aB[2], bB[4];
    #pragma unroll
    for (int am = 0; am < 2; am++) {
        int row = wm * 32 + am * 16 + (mat & 1) * 8 + r;
        aB[am] = saddr(&As[row * LDK + (mat >> 1) * 8]);
    }
    #pragma unroll
    for (int p = 0; p < 4; p++) {
        int row = wn * 64 + p * 16 + (mat >> 1) * 8 + r;
        bB[p] = saddr(&Bs[row * LDK + (mat & 1) * 8]);
    }

    float acc[2][8][4] = {};
    const int nch = K / 64;

    #pragma unroll
    for (int i = 0; i < 4; i++) {
        int idx = tid + i * 256;
        int row = idx >> 3, c8 = (idx & 7) * 8;
        cpasync16(saddr(&As[row * LDK + c8]), &A[(size_t)(r0 + row) * K + c8]);
        cpasync16(saddr(&Bs[row * LDK + c8]), &Bt[(size_t)(c0 + row) * K + c8]);
    }
    cpcommit();

    for (int ch = 0; ch < nch; ch++) {
        int p = ch & 1;
        cpwait0();
        __syncthreads();
        if (ch + 1 < nch) {
            int np = 1 - p, k0g = (ch + 1) * 64;
            #pragma unroll
            for (int i = 0; i < 4; i++) {
                int idx = tid + i * 256;
                int row = idx >> 3, c8 = (idx & 7) * 8;
                cpasync16(saddr(&As[np * BUF + row * LDK + c8]),
                          &A[(size_t)(r0 + row) * K + k0g + c8]);
                cpasync16(saddr(&Bs[np * BUF + row * LDK + c8]),
                          &Bt[(size_t)(c0 + row) * K + k0g + c8]);
            }
            cpcommit();
        }
        const unsigned int bufOff = p * BUF * 2;
        #pragma unroll
        for (int k0 = 0; k0 < 64; k0 += 16) {
            unsigned int a[2][4], b[4][4];
            #pragma unroll
            for (int am = 0; am < 2; am++)
                asm volatile("ldmatrix.sync.aligned.m8n8.x4.shared.b16 {%0,%1,%2,%3}, [%4];"
                    : "=r"(a[am][0]), "=r"(a[am][1]), "=r"(a[am][2]), "=r"(a[am][3])
                    : "r"(aB[am] + bufOff + k0 * 2));
            #pragma unroll
            for (int q = 0; q < 4; q++)
                asm volatile("ldmatrix.sync.aligned.m8n8.x4.shared.b16 {%0,%1,%2,%3}, [%4];"
                    : "=r"(b[q][0]), "=r"(b[q][1]), "=r"(b[q][2]), "=r"(b[q][3])
                    : "r"(bB[q] + bufOff + k0 * 2));
            #pragma unroll
            for (int am = 0; am < 2; am++)
                #pragma unroll
                for (int an = 0; an < 8; an++) {
                    int q = an >> 1, s = (an & 1) * 2;
                    asm volatile(
                        "mma.sync.aligned.m16n8k16.row.col.f32.f16.f16.f32 "
                        "{%0,%1,%2,%3}, {%4,%5,%6,%7}, {%8,%9}, {%0,%1,%2,%3};"
                        : "+f"(acc[am][an][0]), "+f"(acc[am][an][1]),
                          "+f"(acc[am][an][2]), "+f"(acc[am][an][3])
                        : "r"(a[am][0]), "r"(a[am][1]), "r"(a[am][2]), "r"(a[am][3]),
                          "r"(b[q][s]), "r"(b[q][s + 1]));
                }
        }
        __syncthreads();
    }

    #pragma unroll
    for (int am = 0; am < 2; am++) {
        int row = r0 + wm * 32 + am * 16 + (lane >> 2);
        #pragma unroll
        for (int an = 0; an < 8; an++) {
            int col = c0 + wn * 64 + an * 8 + (lane & 3) * 2;
            *(float2*)&C[(size_t)row * Nc + col] =
                make_float2(acc[am][an][0], acc[am][an][1]);
            *(float2*)&C[(size_t)(row + 8) * Nc + col] =
                make_float2(acc[am][an][2], acc[am][an][3]);
        }
    }
}

// ---------------- symmetric contrastive loss, resident-A + double-buffered B ----------------
__global__ __launch_bounds__(256)
void k_loss_sym(const __half* __restrict__ Zh, const unsigned* __restrict__ bits,
                float* __restrict__ sumG, float* __restrict__ posG) {
    const int x = blockIdx.x, s = blockIdx.y;
    const int tmax = (x < 32) ? 33 : 32;
    const int tBeg = (s == 0) ? 0 : 17;
    const int tEnd = (s == 0) ? 17 : tmax;
    const int r0 = x * 128;

    extern __shared__ __half sh[];
    __half* As = sh;                                     // [128][LDH]
    __half* Bs = sh + 128 * LDH;                         // [2][128][LDH]
    unsigned* bitsS = (unsigned*)(sh + 3 * 128 * LDH);   // [2][512]
    const unsigned int BUFB = 128 * LDH * 2;

    const int tid = threadIdx.x;
    const int lane = tid & 31, warp = tid >> 5;
    const int wm = warp >> 1, wn = warp & 1;

    for (int t = tid; t < 4096; t += 256) {
        int row = t >> 5, c8 = (t & 31) * 8;
        *(float4*)&As[row * LDH + c8] =
            *(const float4*)&Zh[(size_t)(r0 + row) * Dout + c8];
    }

    const int mat = lane >> 3, r = lane & 7;
    unsigned int aBase[2], bBase[4];
    #pragma unroll
    for (int am = 0; am < 2; am++) {
        int row = wm * 32 + am * 16 + (mat & 1) * 8 + r;
        aBase[am] = saddr(&As[row * LDH + (mat >> 1) * 8]);
    }
    #pragma unroll
    for (int p = 0; p < 4; p++) {
        int row = wn * 64 + p * 16 + (mat >> 1) * 8 + r;
        bBase[p] = saddr(&Bs[row * LDH + (mat & 1) * 8]);
    }

    {
        int j = (x + tBeg) & 63;
        int c0 = j * 128;
        #pragma unroll
        for (int i = 0; i < 16; i++) {
            int idx = tid + i * 256;
            int row = idx >> 5, c8 = (idx & 31) * 8;
            cpasync16(saddr(&Bs[row * LDH + c8]),
                      &Zh[(size_t)(c0 + row) * Dout + c8]);
        }
        cpcommit();
        if (tid < 128)
            *(uint4*)&bitsS[tid * 4] =
                *(const uint4*)&bits[(size_t)(c0 + tid) * NW + (r0 >> 5)];
    }

    float rs[4] = {}, rp[4] = {};
    const int bitPos = (lane & 3) * 2;
    int pbuf = 0;

    for (int t = tBeg; t < tEnd; t++) {
        const int j = (x + t) & 63;
        const int c0 = j * 128;
        cpwait0();
        __syncthreads();
        if (t + 1 < tEnd) {
            int np = 1 - pbuf;
            int jn = (x + t + 1) & 63;
            int c0n = jn * 128;
            #pragma unroll
            for (int i = 0; i < 16; i++) {
                int idx = tid + i * 256;
                int row = idx >> 5, c8 = (idx & 31) * 8;
                cpasync16(saddr(&Bs[np * 128 * LDH + row * LDH + c8]),
                          &Zh[(size_t)(c0n + row) * Dout + c8]);
            }
            cpcommit();
            if (tid < 128)
                *(uint4*)&bitsS[np * 512 + tid * 4] =
                    *(const uint4*)&bits[(size_t)(c0n + tid) * NW + (r0 >> 5)];
        }
        const unsigned int bOff = pbuf * BUFB;

        float acc[2][8][4] = {};
        #pragma unroll
        for (int k0 = 0; k0 < Dout; k0 += 16) {
            unsigned int a[2][4], b[4][4];
            #pragma unroll
            for (int am = 0; am < 2; am++)
                asm volatile("ldmatrix.sync.aligned.m8n8.x4.shared.b16 {%0,%1,%2,%3}, [%4];"
                    : "=r"(a[am][0]), "=r"(a[am][1]), "=r"(a[am][2]), "=r"(a[am][3])
                    : "r"(aBase[am] + k0 * 2));
            #pragma unroll
            for (int p = 0; p < 4; p++)
                asm volatile("ldmatrix.sync.aligned.m8n8.x4.shared.b16 {%0,%1,%2,%3}, [%4];"
                    : "=r"(b[p][0]), "=r"(b[p][1]), "=r"(b[p][2]), "=r"(b[p][3])
                    : "r"(bBase[p] + bOff + k0 * 2));
            #pragma unroll
            for (int am = 0; am < 2; am++)
                #pragma unroll
                for (int an = 0; an < 8; an++) {
                    int p = an >> 1, q = (an & 1) * 2;
                    asm volatile(
                        "mma.sync.aligned.m16n8k16.row.col.f32.f16.f16.f32 "
                        "{%0,%1,%2,%3}, {%4,%5,%6,%7}, {%8,%9}, {%0,%1,%2,%3};"
                        : "+f"(acc[am][an][0]), "+f"(acc[am][an][1]),
                          "+f"(acc[am][an][2]), "+f"(acc[am][an][3])
                        : "r"(a[am][0]), "r"(a[am][1]), "r"(a[am][2]), "r"(a[am][3]),
                          "r"(b[p][q]), "r"(b[p][q + 1]));
                }
        }

        const bool doCol = (t != 0);
        const int wbase = (c0 >> 5) + wn * 2;
        float cs[8][2] = {}, cp[8][2] = {};
        #pragma unroll
        for (int am = 0; am < 2; am++) {
            int baseRow = wm * 32 + am * 16;
            int row0 = r0 + baseRow + (lane >> 2);
            uint2 wA = *(const uint2*)&bits[(size_t)row0 * NW + wbase];
            uint2 wB = *(const uint2*)&bits[(size_t)(row0 + 8) * NW + wbase];
            int wi = baseRow >> 5;
            int bp0 = (baseRow & 31) + (lane >> 2);
            #pragma unroll
            for (int an = 0; an < 8; an++) {
                unsigned ma = (an < 4) ? wA.x : wA.y;
                unsigned mb = (an < 4) ? wB.x : wB.y;
                int pos = (an & 3) * 8 + bitPos;
                float e0 = __expf(acc[am][an][0]);
                float e1 = __expf(acc[am][an][1]);
                float e2 = __expf(acc[am][an][2]);
                float e3 = __expf(acc[am][an][3]);
                rs[am * 2 + 0] += e0 + e1;
                rs[am * 2 + 1] += e2 + e3;
                if ((ma >> pos) & 1u)       rp[am * 2 + 0] += e0;
                if ((ma >> (pos + 1)) & 1u) rp[am * 2 + 0] += e1;
                if ((mb >> pos) & 1u)       rp[am * 2 + 1] += e2;
                if ((mb >> (pos + 1)) & 1u) rp[am * 2 + 1] += e3;
                if (doCol) {
                    int colLoc = wn * 64 + an * 8 + (lane & 3) * 2;
                    unsigned w0 = bitsS[pbuf * 512 + colLoc * 4 + wi];
                    unsigned w1 = bitsS[pbuf * 512 + (colLoc + 1) * 4 + wi];
                    cs[an][0] += e0 + e2;
                    cs[an][1] += e1 + e3;
                    if ((w0 >> bp0) & 1u)       cp[an][0] += e0;
                    if ((w0 >> (bp0 + 8)) & 1u) cp[an][0] += e2;
                    if ((w1 >> bp0) & 1u)       cp[an][1] += e1;
                    if ((w1 >> (bp0 + 8)) & 1u) cp[an][1] += e3;
                }
            }
        }
        if (doCol) {
            #pragma unroll
            for (int an = 0; an < 8; an++) {
                #pragma unroll
                for (int jj = 0; jj < 2; jj++) {
                    float v = cs[an][jj], p = cp[an][jj];
                    v += __shfl_xor_sync(0xffffffffu, v, 4);
                    v += __shfl_xor_sync(0xffffffffu, v, 8);
                    v += __shfl_xor_sync(0xffffffffu, v, 16);
                    p += __shfl_xor_sync(0xffffffffu, p, 4);
                    p += __shfl_xor_sync(0xffffffffu, p, 8);
                    p += __shfl_xor_sync(0xffffffffu, p, 16);
                    if (lane < 4) {
                        int col = c0 + wn * 64 + an * 8 + lane * 2 + jj;
                        atomicAdd(&sumG[col], v);
                        atomicAdd(&posG[col], p);
                    }
                }
            }
        }
        pbuf ^= 1;
    }

    #pragma unroll
    for (int q = 0; q < 4; q++) {
        float v = rs[q], p = rp[q];
        v += __shfl_xor_sync(0xffffffffu, v, 1);
        v += __shfl_xor_sync(0xffffffffu, v, 2);
        p += __shfl_xor_sync(0xffffffffu, p, 1);
        p += __shfl_xor_sync(0xffffffffu, p, 2);
        if ((lane & 3) == 0) {
            int row = r0 + wm * 32 + (q >> 1) * 16 + (q & 1) * 8 + (lane >> 2);
            atomicAdd(&sumG[row], v);
            atomicAdd(&posG[row], p);
        }
    }
}

// C[MxN] += A^T@B over K-slice (fp32, for dim_center)
__global__ __launch_bounds__(256, 2)
void k_atb(const float* __restrict__ A, const float* __restrict__ B,
           float* __restrict__ C, int M, int Nc, int kPerSlice) {
    __shared__ float As[32][132];
    __shared__ float Bs[32][132];
    int tid = threadIdx.x, tx = tid & 15, ty = tid >> 4;
    int r0 = blockIdx.x * 128, c0 = blockIdx.y * 128;
    int kb = blockIdx.z * kPerSlice;
    int ty8 = ty * 8, tx8 = tx * 8;
    float acc[8][8] = {};
    for (int k0 = kb; k0 < kb + kPerSlice; k0 += 32) {
        for (int t = tid; t < 4096; t += 256) {
            int m = t & 127, k = t >> 7;
            As[k][m] = A[(size_t)(k0 + k) * M + r0 + m];
        }
        for (int t = tid; t < 4096; t += 256) {
            int n = t & 127, k = t >> 7;
            Bs[k][n] = B[(size_t)(k0 + k) * Nc + c0 + n];
        }
        __syncthreads();
        #pragma unroll 8
        for (int k = 0; k < 32; k++) {
            float a[8], b[8];
            #pragma unroll
            for (int i = 0; i < 8; i++) a[i] = As[k][ty8 + i];
            #pragma unroll
            for (int j = 0; j < 8; j++) b[j] = Bs[k][tx8 + j];
            #pragma unroll
            for (int i = 0; i < 8; i++)
                #pragma unroll
                for (int j = 0; j < 8; j++) acc[i][j] = fmaf(a[i], b[j], acc[i][j]);
        }
        __syncthreads();
    }
    for (int i = 0; i < 8; i++) {
        size_t r = (size_t)(r0 + ty8 + i) * Nc + c0 + tx8;
        #pragma unroll
        for (int j = 0; j < 8; j++) atomicAdd(&C[r + j], acc[i][j]);
    }
}

// fused dim-label loss (fp32)
__global__ __launch_bounds__(256, 2)
void k_loss_dim(const float* __restrict__ Z, const float* __restrict__ Cn,
                const float* __restrict__ feat,
                float* __restrict__ sumG, float* __restrict__ posG) {
    __shared__ float As[32][132];
    __shared__ float Bs[32][132];
    int tid = threadIdx.x, tx = tid & 15, ty = tid >> 4;
    int r0 = blockIdx.x * 128;
    int c0 = blockIdx.y * 128;
    int ty8 = ty * 8, tx8 = tx * 8;
    float acc[8][8] = {};
    for (int k0 = 0; k0 < Dout; k0 += 32) {
        for (int t = tid; t < 4096; t += 256) {
            int k = t & 31, m = t >> 5;
            As[k][m] = Z[(size_t)(r0 + m) * Dout + k0 + k];
        }
        for (int t = tid; t < 4096; t += 256) {
            int k = t & 31, m = t >> 5;
            Bs[k][m] = Cn[(size_t)(c0 + m) * Dout + k0 + k];
        }
        __syncthreads();
        #pragma unroll 8
        for (int k = 0; k < 32; k++) {
            float a[8], b[8];
            #pragma unroll
            for (int i = 0; i < 8; i++) a[i] = As[k][ty8 + i];
            #pragma unroll
            for (int j = 0; j < 8; j++) b[j] = Bs[k][tx8 + j];
            #pragma unroll
            for (int i = 0; i < 8; i++)
                #pragma unroll
                for (int j = 0; j < 8; j++) acc[i][j] = fmaf(a[i], b[j], acc[i][j]);
        }
        __syncthreads();
    }
    for (int i = 0; i < 8; i++) {
        int rr = r0 + ty8 + i;
        const float* frow = feat + (size_t)rr * Din + c0 + tx8;
        float sA = 0.f, pA = 0.f;
        #pragma unroll
        for (int j = 0; j < 8; j++) {
            float e = __expf(acc[i][j]);
            sA += e;
            if (frow[j] > 0.f) pA += e;
        }
        atomicAdd(&sumG[rr], sA);
        atomicAdd(&posG[rr], pA);
    }
}

__global__ void k_rowloss(const float* __restrict__ sumG, const float* __restrict__ posG,
                          float* loss, int mode) {
    __shared__ float red[256];
    int t = blockIdx.x * 256 + threadIdx.x;
    float term = 0.f;
    if (t < Nn) {
        float pos = posG[t], tot = sumG[t];
        float neg = tot - pos;
        if (mode == 0) term = -logf((pos + 1e-10f) / (neg + 1e-10f));
        else           term = -logf((pos + 1e-10f) / neg + 1e-5f);
    }
    red[threadIdx.x] = term;
    __syncthreads();
    for (int s = 128; s; s >>= 1) {
        if (threadIdx.x < s) red[threadIdx.x] += red[threadIdx.x + s];
        __syncthreads();
    }
    if (threadIdx.x == 0) atomicAdd(loss, red[0]);
}

// ---------------- attention fuse + norms + centers ----------------
__global__ void k_attention(const float* __restrict__ Wp1, const float* __restrict__ bp1,
                            const float* __restrict__ wp2) {
    int nid = blockIdx.x * 256 + threadIdx.x;
    if (nid >= Nn) return;
    const float* hx = g_Hx + (size_t)nid * Dout;
    const float* ha = g_Hadj + (size_t)nid * Dout;
    float accx[AH], acca[AH];
    #pragma unroll
    for (int h = 0; h < AH; h++) { accx[h] = bp1[h]; acca[h] = bp1[h]; }
    for (int d = 0; d < Dout; d++) {
        float vx = hx[d], va = ha[d];
        #pragma unroll
        for (int h = 0; h < AH; h++) {
            float w = Wp1[d * AH + h];
            accx[h] += vx * w; acca[h] += va * w;
        }
    }
    float wx = 0.f, wa = 0.f;
    #pragma unroll
    for (int h = 0; h < AH; h++) {
        wx += tanhf(accx[h]) * wp2[h];
        wa += tanhf(acca[h]) * wp2[h];
    }
    float m = fmaxf(wx, wa);
    float ex = __expf(wx - m), ea = __expf(wa - m);
    float inv = 1.f / (ex + ea);
    float bx = ex * inv, ba = ea * inv;
    float* out = g_Hf + (size_t)nid * Dout;
    for (int d = 0; d < Dout; d++) out[d] = bx * hx[d] + ba * ha[d];
}

__global__ void k_l2norm(const float* __restrict__ in, __half* __restrict__ outH,
                         float* __restrict__ outF, int rows, int cols) {
    int w = (blockIdx.x * blockDim.x + threadIdx.x) >> 5;
    int lane = threadIdx.x & 31;
    if (w >= rows) return;
    const float* r = in + (size_t)w * cols;
    float ss = 0.f;
    for (int c = lane; c < cols; c += 32) { float v = r[c]; ss += v * v; }
    for (int o = 16; o; o >>= 1) ss += __shfl_xor_sync(0xffffffffu, ss, o);
    float inv = 1.f / fmaxf(sqrtf(ss), 1e-12f);
    __half* wh = outH + (size_t)w * cols;
    for (int c = lane; c < cols; c += 32) {
        float v = r[c] * inv;
        wh[c] = __float2half(v);
        if (outF) outF[(size_t)w * cols + c] = v;
    }
}

__global__ void k_colsum(const float* __restrict__ feat) {
    int c = blockIdx.x * 256 + threadIdx.x;
    int rbeg = blockIdx.y * 128;
    float s = 0.f;
    for (int i = rbeg; i < rbeg + 128; i++) s += feat[(size_t)i * Din + c];
    atomicAdd(&g_colsum[c], s);
}

__global__ void k_center() {
    int w = (blockIdx.x * blockDim.x + threadIdx.x) >> 5;
    int lane = threadIdx.x & 31;
    if (w >= Din) return;
    float s = g_colsum[w] + 1e-5f;
    float inv_s = 1.f / s;
    float v[8]; float ss = 0.f;
    #pragma unroll
    for (int i = 0; i < 8; i++) {
        v[i] = g_dcraw[(size_t)w * Dout + lane + 32 * i] * inv_s;
        ss += v[i] * v[i];
    }
    for (int o = 16; o; o >>= 1) ss += __shfl_xor_sync(0xffffffffu, ss, o);
    float inv = 1.f / fmaxf(sqrtf(ss), 1e-12f);
    #pragma unroll
    for (int i = 0; i < 8; i++) g_Cn[(size_t)w * Dout + lane + 32 * i] = v[i] * inv;
}

__global__ void k_final(float* out) {
    out[0] = (0.5f * (g_loss[0] + g_loss[1]) + 0.1f * g_loss[2] + g_loss[3]) * (1.0f / Nn);
}

// ---------------- host ----------------
extern "C" void kernel_launch(void* const* d_in, const int* in_sizes, int n_in,
                              void* d_out, int out_size) {
    const float* feat = (const float*)d_in[0];
    const float* adjL = (const float*)d_in[1];
    const float* adjX = (const float*)d_in[2];
    const float* adjR = (const float*)d_in[3];

    const int *eA, *eX; int pb;
    if (in_sizes[5] == 262144) { eA = (const int*)d_in[4]; eX = (const int*)d_in[5]; pb = 6; }
    else                       { pb = 4; eA = (const int*)d_in[15]; eX = (const int*)d_in[16]; }

    const float* W0a = (const float*)d_in[pb + 0];
    const float* b0a = (const float*)d_in[pb + 1];
    const float* W1a = (const float*)d_in[pb + 2];
    const float* b1a = (const float*)d_in[pb + 3];
    const float* W0x = (const float*)d_in[pb + 4];
    const float* b0x = (const float*)d_in[pb + 5];
    const float* W1x = (const float*)d_in[pb + 6];
    const float* b1x = (const float*)d_in[pb + 7];
    const float* Wp1 = (const float*)d_in[pb + 8];
    const float* bp1 = (const float*)d_in[pb + 9];
    const float* wp2 = (const float*)d_in[pb + 10];

    const int LOSS_SMEM = 3 * 128 * LDH * (int)sizeof(__half) + 4096;  // 206848
    const int GEMM_SMEM = 4 * 128 * LDK * (int)sizeof(__half);

    static int inited = 0;
    static cudaStream_t s1, s2, s3;
    static cudaEvent_t eStart, eConv, ePrep, ePack, eZero, eHadj, eZxh, eZf, eL1, eL2, eL3;
    if (!inited) {
        cudaFuncSetAttribute(k_loss_sym, cudaFuncAttributeMaxDynamicSharedMemorySize, LOSS_SMEM);
        cudaFuncSetAttribute(k_gemm_h, cudaFuncAttributeMaxDynamicSharedMemorySize, GEMM_SMEM);
        cudaStreamCreateWithFlags(&s1, cudaStreamNonBlocking);
        cudaStreamCreateWithFlags(&s2, cudaStreamNonBlocking);
        cudaStreamCreateWithFlags(&s3, cudaStreamNonBlocking);
        cudaEventCreateWithFlags(&eStart, cudaEventDisableTiming);
        cudaEventCreateWithFlags(&eConv,  cudaEventDisableTiming);
        cudaEventCreateWithFlags(&ePrep,  cudaEventDisableTiming);
        cudaEventCreateWithFlags(&ePack,  cudaEventDisableTiming);
        cudaEventCreateWithFlags(&eZero,  cudaEventDisableTiming);
        cudaEventCreateWithFlags(&eHadj,  cudaEventDisableTiming);
        cudaEventCreateWithFlags(&eZxh,   cudaEventDisableTiming);
        cudaEventCreateWithFlags(&eZf,    cudaEventDisableTiming);
        cudaEventCreateWithFlags(&eL1,    cudaEventDisableTiming);
        cudaEventCreateWithFlags(&eL2,    cudaEventDisableTiming);
        cudaEventCreateWithFlags(&eL3,    cudaEventDisableTiming);
        inited = 1;
    }

    void *pY, *pY2, *pHadj, *pHx, *pHf, *pZf, *pFH, *pH1h, *pH1h2, *pZah, *pZxh, *pZfh, *pWt;
    void *pDeg, *pNrm, *pOff, *pCur, *pEidx, *pBits;
    void *pDc, *pCn, *pCs, *pSum, *pPos, *pLoss;
    cudaGetSymbolAddress(&pY, g_Y);       cudaGetSymbolAddress(&pY2, g_Y2);
    cudaGetSymbolAddress(&pHadj, g_Hadj); cudaGetSymbolAddress(&pHx, g_Hx);
    cudaGetSymbolAddress(&pHf, g_Hf);     cudaGetSymbolAddress(&pZf, g_Zf);
    cudaGetSymbolAddress(&pFH, g_featH);  cudaGetSymbolAddress(&pH1h, g_H1h);
    cudaGetSymbolAddress(&pH1h2, g_H1h2);
    cudaGetSymbolAddress(&pZah, g_Zah);   cudaGetSymbolAddress(&pZxh, g_Zxh);
    cudaGetSymbolAddress(&pZfh, g_Zfh);   cudaGetSymbolAddress(&pWt, g_Wt);
    cudaGetSymbolAddress(&pDeg, g_deg);   cudaGetSymbolAddress(&pNrm, g_nrm);
    cudaGetSymbolAddress(&pOff, g_off);   cudaGetSymbolAddress(&pCur, g_cursor);
    cudaGetSymbolAddress(&pEidx, g_eidx); cudaGetSymbolAddress(&pBits, g_bits);
    cudaGetSymbolAddress(&pDc, g_dcraw);  cudaGetSymbolAddress(&pCn, g_Cn);
    cudaGetSymbolAddress(&pCs, g_colsum); cudaGetSymbolAddress(&pSum, g_sum);
    cudaGetSymbolAddress(&pPos, g_pos);   cudaGetSymbolAddress(&pLoss, g_loss);

    float* deg = (float*)pDeg;
    float* nrm = (float*)pNrm;
    float* nsA = nrm;           float* ndA = nrm + Nn;
    float* nsX = nrm + 2 * Nn;  float* ndX = nrm + 3 * Nn;
    int* offA = (int*)pOff;     int* offX = offA + (Nn + 1);
    int* eidxA = (int*)pEidx;   int* eidxX = eidxA + Ne;
    unsigned* bitsL = (unsigned*)pBits;
    unsigned* bitsX = bitsL + (size_t)Nn * NW;
    unsigned* bitsR = bitsX + (size_t)Nn * NW;
    __half* featH = (__half*)pFH;
    __half* H1h = (__half*)pH1h;
    __half* H1h2 = (__half*)pH1h2;
    __half* W0aT = (__half*)pWt;
    __half* W1aT = W0aT + Din * Din;
    __half* W0xT = W1aT + Din * Dout;
    __half* W1xT = W0xT + Din * Din;
    float* sum = (float*)pSum;  float* pos = (float*)pPos;
    float* loss = (float*)pLoss;
    const int packBlocks = (Nn * NW) / 64;   // 8 words/warp, 8 warps/block

    // ---- fork ----
    cudaEventRecord(eStart, 0);
    cudaStreamWaitEvent(s1, eStart, 0);
    cudaStreamWaitEvent(s2, eStart, 0);

    // ---- s2: zeroing + colsum + packs ----
    cudaMemsetAsync(pCs, 0, Din * sizeof(float), s2);
    cudaMemsetAsync(pDc, 0, (size_t)Din * Dout * sizeof(float), s2);
    cudaMemsetAsync(pSum, 0, 4 * Nn * sizeof(float), s2);
    cudaMemsetAsync(pPos, 0, 4 * Nn * sizeof(float), s2);
    cudaMemsetAsync(pLoss, 0, 4 * sizeof(float), s2);
    k_colsum<<<dim3(2, 64), 256, 0, s2>>>(feat);
    cudaEventRecord(eZero, s2);
    k_pack<<<packBlocks, 256, 0, s2>>>(adjL, bitsL);
    k_pack<<<packBlocks, 256, 0, s2>>>(adjX, bitsX);
    k_pack<<<packBlocks, 256, 0, s2>>>(adjR, bitsR);
    cudaEventRecord(ePack, s2);

    // ---- s1: conversions + branch A start ----
    k_f2h<<<(Nn * Din / 4 + 255) / 256, 256, 0, s1>>>(feat, featH, Nn * Din / 4);
    k_wth<<<(Din * Din + 255) / 256, 256, 0, s1>>>(W0a, W0aT, Din, Din);
    k_wth<<<(Din * Dout + 255) / 256, 256, 0, s1>>>(W1a, W1aT, Din, Dout);
    k_wth<<<(Din * Din + 255) / 256, 256, 0, s1>>>(W0x, W0xT, Din, Din);
    k_wth<<<(Din * Dout + 255) / 256, 256, 0, s1>>>(W1x, W1xT, Din, Dout);
    cudaEventRecord(eConv, s1);
    k_gemm_h<<<dim3(Nn / 128, Din / 128), 256, GEMM_SMEM, s1>>>(featH, W0aT, (float*)pY, Din, Din);

    // ---- s0: graph prep ----
    cudaMemsetAsync(pDeg, 0, 4 * Nn * sizeof(float), 0);
    cudaMemsetAsync(pCur, 0, 2 * Nn * sizeof(int), 0);
    k_degree<<<(Ne + 255) / 256, 256>>>(eA, eA + Ne, deg, deg + Nn);
    k_degree<<<(Ne + 255) / 256, 256>>>(eX, eX + Ne, deg + 2 * Nn, deg + 3 * Nn);
    k_norm<<<(4 * Nn) / 256, 256>>>();
    k_scan<<<1, 1024>>>(deg + Nn, offA);
    k_scan<<<1, 1024>>>(deg + 3 * Nn, offX);
    k_bucket<<<(Ne + 255) / 256, 256>>>(eA, eA + Ne, offA, (int*)pCur, eidxA);
    k_bucket<<<(Ne + 255) / 256, 256>>>(eX, eX + Ne, offX, (int*)pCur + Nn, eidxX);
    cudaEventRecord(ePrep, 0);

    // ---- s1: branch A finish + loss A ----
    cudaStreamWaitEvent(s1, ePrep, 0);
    k_gather_h<<<Nn, Din / 4, 0, s1>>>(offA, eidxA, (float*)pY, nsA, ndA, b0a, H1h, Din / 4);
    k_gemm_h<<<dim3(Nn / 128, Dout / 128), 256, GEMM_SMEM, s1>>>(H1h, W1aT, (float*)pY, Dout, Din);
    k_gather<<<Nn, Dout / 4, 0, s1>>>(offA, eidxA, (float*)pY, nsA, ndA, b1a, (float*)pHadj, Dout / 4);
    cudaEventRecord(eHadj, s1);
    k_l2norm<<<Nn / 8, 256, 0, s1>>>((float*)pHadj, (__half*)pZah, nullptr, Nn, Dout);
    cudaStreamWaitEvent(s1, ePack, 0);
    k_loss_sym<<<dim3(64, 2), 256, LOSS_SMEM, s1>>>((const __half*)pZah, bitsL, sum, pos);
    k_rowloss<<<Nn / 256, 256, 0, s1>>>(sum, pos, loss + 0, 0);
    cudaEventRecord(eL1, s1);

    // ---- s0: branch X ----
    cudaStreamWaitEvent(0, eConv, 0);
    k_gemm_h<<<dim3(Nn / 128, Din / 128), 256, GEMM_SMEM>>>(featH, W0xT, (float*)pY2, Din, Din);
    k_gather_h<<<Nn, Din / 4>>>(offX, eidxX, (float*)pY2, nsX, ndX, b0x, H1h2, Din / 4);
    k_gemm_h<<<dim3(Nn / 128, Dout / 128), 256, GEMM_SMEM>>>(H1h2, W1xT, (float*)pY2, Dout, Din);
    k_gather<<<Nn, Dout / 4>>>(offX, eidxX, (float*)pY2, nsX, ndX, b1x, (float*)pHx, Dout / 4);
    k_l2norm<<<Nn / 8, 256>>>((float*)pHx, (__half*)pZxh, nullptr, Nn, Dout);
    cudaEventRecord(eZxh, 0);

    // ---- s3: loss X ----
    cudaStreamWaitEvent(s3, eZxh, 0);
    cudaStreamWaitEvent(s3, ePack, 0);
    k_loss_sym<<<dim3(64, 2), 256, LOSS_SMEM, s3>>>((const __half*)pZxh, bitsX, sum + Nn, pos + Nn);
    k_rowloss<<<Nn / 256, 256, 0, s3>>>(sum + Nn, pos + Nn, loss + 1, 0);
    cudaEventRecord(eL2, s3);

    // ---- s0: attention + fused embedding ----
    cudaStreamWaitEvent(0, eHadj, 0);
    k_attention<<<Nn / 256, 256>>>(Wp1, bp1, wp2);
    k_l2norm<<<Nn / 8, 256>>>((float*)pHf, (__half*)pZfh, (float*)pZf, Nn, Dout);
    cudaEventRecord(eZf, 0);

    // ---- s2: loss R ----
    cudaStreamWaitEvent(s2, eZf, 0);
    k_loss_sym<<<dim3(64, 2), 256, LOSS_SMEM, s2>>>((const __half*)pZfh, bitsR, sum + 3 * Nn, pos + 3 * Nn);
    k_rowloss<<<Nn / 256, 256, 0, s2>>>(sum + 3 * Nn, pos + 3 * Nn, loss + 3, 0);
    cudaEventRecord(eL3, s2);

    // ---- s0: dim_center + dim loss ----
    cudaStreamWaitEvent(0, eZero, 0);
    k_atb<<<dim3(Din / 128, Dout / 128, 32), 256>>>(feat, (float*)pHf, (float*)pDc, Din, Dout, Nn / 32);
    k_center<<<Din / 8, 256>>>();
    k_loss_dim<<<dim3(Nn / 128, Din / 128), 256>>>((float*)pZf, (float*)pCn, feat,
                                                   sum + 2 * Nn, pos + 2 * Nn);
    k_rowloss<<<Nn / 256, 256>>>(sum + 2 * Nn, pos + 2 * Nn, loss + 2, 1);

    // ---- join + final ----
    cudaStreamWaitEvent(0, eL1, 0);
    cudaStreamWaitEvent(0, eL2, 0);
    cudaStreamWaitEvent(0, eL3, 0);
    k_final<<<1, 1>>>((float*)d_out);
}

// round 15
// speedup vs baseline: 4.8929x; 1.0056x over previous
#include <cuda_runtime.h>
#include <cuda_fp16.h>
#include <cstdint>
#include <math.h>

#define Nn   8192
#define Din  512
#define Dout 256
#define Ne   131072
#define AH   16
#define LDH  264   // loss smem stride (halves): 528B, conflict-free ldmatrix
#define NW   256   // bitmask words per row
#define LDK  72    // gemm_h chunk stride (halves)

// ---------------- static scratch ----------------
static __device__ float g_Y[Nn*Din];
static __device__ float g_Y2[Nn*Din];
static __device__ float g_Hadj[Nn*Dout];
static __device__ float g_Hx[Nn*Dout];
static __device__ float g_Hf[Nn*Dout];
static __device__ float g_Zf[Nn*Dout];
static __device__ __half g_featH[Nn*Din];
static __device__ __half g_H1h[Nn*Din];
static __device__ __half g_H1h2[Nn*Din];
static __device__ __half g_Zah[Nn*Dout];
static __device__ __half g_Zxh[Nn*Dout];
static __device__ __half g_Zfh[Nn*Dout];
static __device__ __half g_Wt[2*(Din*Din + Din*Dout)];
static __device__ float g_deg[4*Nn];
static __device__ float g_nrm[4*Nn];
static __device__ int   g_off[2*(Nn+1)];
static __device__ int   g_cursor[2*Nn];
static __device__ int   g_eidx[2*Ne];
static __device__ unsigned g_bits[3u*Nn*NW];
static __device__ float g_dcraw[Din*Dout];
static __device__ float g_Cn[Din*Dout];
static __device__ float g_colsum[Din];
static __device__ float g_sum[4*Nn];
static __device__ float g_pos[4*Nn];
static __device__ float g_loss[4];

__device__ __forceinline__ unsigned int saddr(const void* p) {
    return (unsigned int)__cvta_generic_to_shared(p);
}
__device__ __forceinline__ void cpasync16(unsigned int dst, const void* src) {
    asm volatile("cp.async.cg.shared.global [%0], [%1], 16;" :: "r"(dst), "l"(src));
}
__device__ __forceinline__ void cpcommit() { asm volatile("cp.async.commit_group;"); }
__device__ __forceinline__ void cpwait0()  { asm volatile("cp.async.wait_group 0;"); }

// ---------------- graph preprocessing ----------------
__global__ void k_degree(const int* __restrict__ src, const int* __restrict__ dst,
                         float* degO, float* degI) {
    int t = blockIdx.x * 256 + threadIdx.x;
    if (t < Ne) { atomicAdd(degO + src[t], 1.f); atomicAdd(degI + dst[t], 1.f); }
}

__global__ void k_norm() {
    int t = blockIdx.x * 256 + threadIdx.x;
    if (t < 4 * Nn) { float d = g_deg[t]; g_nrm[t] = (d > 0.f) ? rsqrtf(d) : 0.f; }
}

__global__ void k_scan(const float* __restrict__ degIn, int* __restrict__ off) {
    __shared__ int part[1024];
    int t = threadIdx.x;
    int v[8]; int s = 0;
    #pragma unroll
    for (int i = 0; i < 8; i++) { v[i] = s; s += (int)degIn[t * 8 + i]; }
    part[t] = s;
    __syncthreads();
    for (int d = 1; d < 1024; d <<= 1) {
        int x = (t >= d) ? part[t - d] : 0;
        __syncthreads();
        part[t] += x;
        __syncthreads();
    }
    int base = (t > 0) ? part[t - 1] : 0;
    #pragma unroll
    for (int i = 0; i < 8; i++) off[t * 8 + i] = base + v[i];
    if (t == 1023) off[Nn] = part[1023];
}

__global__ void k_bucket(const int* __restrict__ src, const int* __restrict__ dst,
                         const int* __restrict__ off, int* __restrict__ cursor,
                         int* __restrict__ eidx) {
    int t = blockIdx.x * 256 + threadIdx.x;
    if (t >= Ne) return;
    int d = dst[t];
    int p = atomicAdd(&cursor[d], 1);
    eidx[off[d] + p] = src[t];
}

__global__ void k_gather(const int* __restrict__ off, const int* __restrict__ eidx,
                         const float* __restrict__ Y, const float* __restrict__ ns,
                         const float* __restrict__ nd, const float* __restrict__ bias,
                         float* __restrict__ H, int C4) {
    int n = blockIdx.x, c = threadIdx.x;
    int s0 = off[n], s1 = off[n + 1];
    float4 acc = {0.f, 0.f, 0.f, 0.f};
    for (int i = s0; i < s1; i++) {
        int s = eidx[i];
        float w = ns[s];
        float4 v = ((const float4*)Y)[(size_t)s * C4 + c];
        acc.x += v.x * w; acc.y += v.y * w; acc.z += v.z * w; acc.w += v.w * w;
    }
    float sc = nd[n];
    float4 b = ((const float4*)bias)[c];
    float4 o;
    o.x = acc.x * sc + b.x; o.y = acc.y * sc + b.y;
    o.z = acc.z * sc + b.z; o.w = acc.w * sc + b.w;
    ((float4*)H)[(size_t)n * C4 + c] = o;
}

__global__ void k_gather_h(const int* __restrict__ off, const int* __restrict__ eidx,
                           const float* __restrict__ Y, const float* __restrict__ ns,
                           const float* __restrict__ nd, const float* __restrict__ bias,
                           __half* __restrict__ H, int C4) {
    int n = blockIdx.x, c = threadIdx.x;
    int s0 = off[n], s1 = off[n + 1];
    float4 acc = {0.f, 0.f, 0.f, 0.f};
    for (int i = s0; i < s1; i++) {
        int s = eidx[i];
        float w = ns[s];
        float4 v = ((const float4*)Y)[(size_t)s * C4 + c];
        acc.x += v.x * w; acc.y += v.y * w; acc.z += v.z * w; acc.w += v.w * w;
    }
    float sc = nd[n];
    float4 b = ((const float4*)bias)[c];
    float ox = fmaxf(acc.x * sc + b.x, 0.f);
    float oy = fmaxf(acc.y * sc + b.y, 0.f);
    float oz = fmaxf(acc.z * sc + b.z, 0.f);
    float ow = fmaxf(acc.w * sc + b.w, 0.f);
    ((__half2*)H)[((size_t)n * C4 + c) * 2 + 0] = __floats2half2_rn(ox, oy);
    ((__half2*)H)[((size_t)n * C4 + c) * 2 + 1] = __floats2half2_rn(oz, ow);
}

__global__ void k_pack(const float* __restrict__ a, unsigned* __restrict__ bits) {
    size_t w8 = ((size_t)blockIdx.x * 8 + (threadIdx.x >> 5)) * 8;
    int lane = threadIdx.x & 31;
    const float* base = a + w8 * 32 + lane;
    float v0 = __ldcs(base + 0 * 32);
    float v1 = __ldcs(base + 1 * 32);
    float v2 = __ldcs(base + 2 * 32);
    float v3 = __ldcs(base + 3 * 32);
    float v4 = __ldcs(base + 4 * 32);
    float v5 = __ldcs(base + 5 * 32);
    float v6 = __ldcs(base + 6 * 32);
    float v7 = __ldcs(base + 7 * 32);
    unsigned m0 = __ballot_sync(0xffffffffu, v0 != 0.f);
    unsigned m1 = __ballot_sync(0xffffffffu, v1 != 0.f);
    unsigned m2 = __ballot_sync(0xffffffffu, v2 != 0.f);
    unsigned m3 = __ballot_sync(0xffffffffu, v3 != 0.f);
    unsigned m4 = __ballot_sync(0xffffffffu, v4 != 0.f);
    unsigned m5 = __ballot_sync(0xffffffffu, v5 != 0.f);
    unsigned m6 = __ballot_sync(0xffffffffu, v6 != 0.f);
    unsigned m7 = __ballot_sync(0xffffffffu, v7 != 0.f);
    if (lane == 0) {
        *(uint4*)&bits[w8 + 0] = make_uint4(m0, m1, m2, m3);
        *(uint4*)&bits[w8 + 4] = make_uint4(m4, m5, m6, m7);
    }
}

// ---------------- conversions ----------------
__global__ void k_f2h(const float* __restrict__ in, __half* __restrict__ out, int n4) {
    int i = blockIdx.x * 256 + threadIdx.x;
    if (i >= n4) return;
    float4 v = ((const float4*)in)[i];
    ((__half2*)out)[i * 2 + 0] = __floats2half2_rn(v.x, v.y);
    ((__half2*)out)[i * 2 + 1] = __floats2half2_rn(v.z, v.w);
}

__global__ void k_wth(const float* __restrict__ W, __half* __restrict__ Wt, int K, int N) {
    int i = blockIdx.x * 256 + threadIdx.x;
    if (i >= K * N) return;
    int k = i / N, n = i % N;
    Wt[(size_t)n * K + k] = __float2half(W[i]);
}

// ---------------- fp16 tensor-core GEMM: C = A[MxK] @ Bt[NcxK]^T ----------------
__global__ __launch_bounds__(256)
void k_gemm_h(const __half* __restrict__ A, const __half* __restrict__ Bt,
              float* __restrict__ C, int Nc, int K) {
    extern __shared__ __half sg[];
    __half* As = sg;
    __half* Bs = sg + 2 * 128 * LDK;
    const int BUF = 128 * LDK;
    const int tid = threadIdx.x;
    const int lane = tid & 31, warp = tid >> 5;
    const int wm = warp >> 1, wn = warp & 1;
    const int r0 = blockIdx.x * 128, c0 = blockIdx.y * 128;

    const int mat = lane >> 3, r = lane & 7;
    unsigned int aB[2], bB[4];
    #pragma unroll
    for (int am = 0; am < 2; am++) {
        int row = wm * 32 + am * 16 + (mat & 1) * 8 + r;
        aB[am] = saddr(&As[row * LDK + (mat >> 1) * 8]);
    }
    #pragma unroll
    for (int p = 0; p < 4; p++) {
        int row = wn * 64 + p * 16 + (mat >> 1) * 8 + r;
        bB[p] = saddr(&Bs[row * LDK + (mat & 1) * 8]);
    }

    float acc[2][8][4] = {};
    const int nch = K / 64;

    #pragma unroll
    for (int i = 0; i < 4; i++) {
        int idx = tid + i * 256;
        int row = idx >> 3, c8 = (idx & 7) * 8;
        cpasync16(saddr(&As[row * LDK + c8]), &A[(size_t)(r0 + row) * K + c8]);
        cpasync16(saddr(&Bs[row * LDK + c8]), &Bt[(size_t)(c0 + row) * K + c8]);
    }
    cpcommit();

    for (int ch = 0; ch < nch; ch++) {
        int p = ch & 1;
        cpwait0();
        __syncthreads();
        if (ch + 1 < nch) {
            int np = 1 - p, k0g = (ch + 1) * 64;
            #pragma unroll
            for (int i = 0; i < 4; i++) {
                int idx = tid + i * 256;
                int row = idx >> 3, c8 = (idx & 7) * 8;
                cpasync16(saddr(&As[np * BUF + row * LDK + c8]),
                          &A[(size_t)(r0 + row) * K + k0g + c8]);
                cpasync16(saddr(&Bs[np * BUF + row * LDK + c8]),
                          &Bt[(size_t)(c0 + row) * K + k0g + c8]);
            }
            cpcommit();
        }
        const unsigned int bufOff = p * BUF * 2;
        #pragma unroll
        for (int k0 = 0; k0 < 64; k0 += 16) {
            unsigned int a[2][4], b[4][4];
            #pragma unroll
            for (int am = 0; am < 2; am++)
                asm volatile("ldmatrix.sync.aligned.m8n8.x4.shared.b16 {%0,%1,%2,%3}, [%4];"
                    : "=r"(a[am][0]), "=r"(a[am][1]), "=r"(a[am][2]), "=r"(a[am][3])
                    : "r"(aB[am] + bufOff + k0 * 2));
            #pragma unroll
            for (int q = 0; q < 4; q++)
                asm volatile("ldmatrix.sync.aligned.m8n8.x4.shared.b16 {%0,%1,%2,%3}, [%4];"
                    : "=r"(b[q][0]), "=r"(b[q][1]), "=r"(b[q][2]), "=r"(b[q][3])
                    : "r"(bB[q] + bufOff + k0 * 2));
            #pragma unroll
            for (int am = 0; am < 2; am++)
                #pragma unroll
                for (int an = 0; an < 8; an++) {
                    int q = an >> 1, s = (an & 1) * 2;
                    asm volatile(
                        "mma.sync.aligned.m16n8k16.row.col.f32.f16.f16.f32 "
                        "{%0,%1,%2,%3}, {%4,%5,%6,%7}, {%8,%9}, {%0,%1,%2,%3};"
                        : "+f"(acc[am][an][0]), "+f"(acc[am][an][1]),
                          "+f"(acc[am][an][2]), "+f"(acc[am][an][3])
                        : "r"(a[am][0]), "r"(a[am][1]), "r"(a[am][2]), "r"(a[am][3]),
                          "r"(b[q][s]), "r"(b[q][s + 1]));
                }
        }
        __syncthreads();
    }

    #pragma unroll
    for (int am = 0; am < 2; am++) {
        int row = r0 + wm * 32 + am * 16 + (lane >> 2);
        #pragma unroll
        for (int an = 0; an < 8; an++) {
            int col = c0 + wn * 64 + an * 8 + (lane & 3) * 2;
            *(float2*)&C[(size_t)row * Nc + col] =
                make_float2(acc[am][an][0], acc[am][an][1]);
            *(float2*)&C[(size_t)(row + 8) * Nc + col] =
                make_float2(acc[am][an][2], acc[am][an][3]);
        }
    }
}

// ---------------- symmetric contrastive loss, 16 warps, resident-A + dbl-buffered B ----------------
__global__ __launch_bounds__(512)
void k_loss_sym(const __half* __restrict__ Zh, const unsigned* __restrict__ bits,
                float* __restrict__ sumG, float* __restrict__ posG) {
    const int x = blockIdx.x, s = blockIdx.y;
    const int tmax = (x < 32) ? 33 : 32;
    const int tBeg = (s == 0) ? 0 : 17;
    const int tEnd = (s == 0) ? 17 : tmax;
    const int r0 = x * 128;

    extern __shared__ __half sh[];
    __half* As = sh;                                     // [128][LDH]
    __half* Bs = sh + 128 * LDH;                         // [2][128][LDH]
    unsigned* bitsS = (unsigned*)(sh + 3 * 128 * LDH);   // [2][512]
    const unsigned int BUFB = 128 * LDH * 2;

    const int tid = threadIdx.x;
    const int lane = tid & 31, warp = tid >> 5;
    const int wm = warp >> 2, wn = warp & 3;             // 4x4 warp grid, 32x32 each

    for (int t = tid; t < 4096; t += 512) {
        int row = t >> 5, c8 = (t & 31) * 8;
        *(float4*)&As[row * LDH + c8] =
            *(const float4*)&Zh[(size_t)(r0 + row) * Dout + c8];
    }

    const int mat = lane >> 3, r = lane & 7;
    unsigned int aBase[2], bBase[2];
    #pragma unroll
    for (int am = 0; am < 2; am++) {
        int row = wm * 32 + am * 16 + (mat & 1) * 8 + r;
        aBase[am] = saddr(&As[row * LDH + (mat >> 1) * 8]);
    }
    #pragma unroll
    for (int p = 0; p < 2; p++) {
        int row = wn * 32 + p * 16 + (mat >> 1) * 8 + r;
        bBase[p] = saddr(&Bs[row * LDH + (mat & 1) * 8]);
    }

    {
        int j = (x + tBeg) & 63;
        int c0 = j * 128;
        #pragma unroll
        for (int i = 0; i < 8; i++) {
            int idx = tid + i * 512;
            int row = idx >> 5, c8 = (idx & 31) * 8;
            cpasync16(saddr(&Bs[row * LDH + c8]),
                      &Zh[(size_t)(c0 + row) * Dout + c8]);
        }
        cpcommit();
        if (tid < 128)
            *(uint4*)&bitsS[tid * 4] =
                *(const uint4*)&bits[(size_t)(c0 + tid) * NW + (r0 >> 5)];
    }

    float rs[4] = {}, rp[4] = {};
    const int bitPos = (lane & 3) * 2;
    int pbuf = 0;

    for (int t = tBeg; t < tEnd; t++) {
        const int j = (x + t) & 63;
        const int c0 = j * 128;
        cpwait0();
        __syncthreads();
        if (t + 1 < tEnd) {
            int np = 1 - pbuf;
            int jn = (x + t + 1) & 63;
            int c0n = jn * 128;
            #pragma unroll
            for (int i = 0; i < 8; i++) {
                int idx = tid + i * 512;
                int row = idx >> 5, c8 = (idx & 31) * 8;
                cpasync16(saddr(&Bs[np * 128 * LDH + row * LDH + c8]),
                          &Zh[(size_t)(c0n + row) * Dout + c8]);
            }
            cpcommit();
            if (tid < 128)
                *(uint4*)&bitsS[np * 512 + tid * 4] =
                    *(const uint4*)&bits[(size_t)(c0n + tid) * NW + (r0 >> 5)];
        }
        const unsigned int bOff = pbuf * BUFB;

        float acc[2][4][4] = {};
        #pragma unroll
        for (int k0 = 0; k0 < Dout; k0 += 16) {
            unsigned int a[2][4], b[2][4];
            #pragma unroll
            for (int am = 0; am < 2; am++)
                asm volatile("ldmatrix.sync.aligned.m8n8.x4.shared.b16 {%0,%1,%2,%3}, [%4];"
                    : "=r"(a[am][0]), "=r"(a[am][1]), "=r"(a[am][2]), "=r"(a[am][3])
                    : "r"(aBase[am] + k0 * 2));
            #pragma unroll
            for (int p = 0; p < 2; p++)
                asm volatile("ldmatrix.sync.aligned.m8n8.x4.shared.b16 {%0,%1,%2,%3}, [%4];"
                    : "=r"(b[p][0]), "=r"(b[p][1]), "=r"(b[p][2]), "=r"(b[p][3])
                    : "r"(bBase[p] + bOff + k0 * 2));
            #pragma unroll
            for (int am = 0; am < 2; am++)
                #pragma unroll
                for (int an = 0; an < 4; an++) {
                    int q = an >> 1, sx = (an & 1) * 2;
                    asm volatile(
                        "mma.sync.aligned.m16n8k16.row.col.f32.f16.f16.f32 "
                        "{%0,%1,%2,%3}, {%4,%5,%6,%7}, {%8,%9}, {%0,%1,%2,%3};"
                        : "+f"(acc[am][an][0]), "+f"(acc[am][an][1]),
                          "+f"(acc[am][an][2]), "+f"(acc[am][an][3])
                        : "r"(a[am][0]), "r"(a[am][1]), "r"(a[am][2]), "r"(a[am][3]),
                          "r"(b[q][sx]), "r"(b[q][sx + 1]));
                }
        }

        // epilogue: warp covers rows wm*32..+32, cols wn*32..+32 (one bit-word/row)
        const bool doCol = (t != 0);
        const int wbase = (c0 >> 5) + wn;
        float cs[4][2] = {}, cp[4][2] = {};
        #pragma unroll
        for (int am = 0; am < 2; am++) {
            int baseRow = wm * 32 + am * 16;
            int row0 = r0 + baseRow + (lane >> 2);
            unsigned wA = bits[(size_t)row0 * NW + wbase];
            unsigned wB = bits[(size_t)(row0 + 8) * NW + wbase];
            int wi = baseRow >> 5;
            int bp0 = (baseRow & 31) + (lane >> 2);
            #pragma unroll
            for (int an = 0; an < 4; an++) {
                int pos = an * 8 + bitPos;
                float e0 = __expf(acc[am][an][0]);
                float e1 = __expf(acc[am][an][1]);
                float e2 = __expf(acc[am][an][2]);
                float e3 = __expf(acc[am][an][3]);
                rs[am * 2 + 0] += e0 + e1;
                rs[am * 2 + 1] += e2 + e3;
                if ((wA >> pos) & 1u)       rp[am * 2 + 0] += e0;
                if ((wA >> (pos + 1)) & 1u) rp[am * 2 + 0] += e1;
                if ((wB >> pos) & 1u)       rp[am * 2 + 1] += e2;
                if ((wB >> (pos + 1)) & 1u) rp[am * 2 + 1] += e3;
                if (doCol) {
                    int colLoc = wn * 32 + an * 8 + (lane & 3) * 2;
                    unsigned w0 = bitsS[pbuf * 512 + colLoc * 4 + wi];
                    unsigned w1 = bitsS[pbuf * 512 + (colLoc + 1) * 4 + wi];
                    cs[an][0] += e0 + e2;
                    cs[an][1] += e1 + e3;
                    if ((w0 >> bp0) & 1u)       cp[an][0] += e0;
                    if ((w0 >> (bp0 + 8)) & 1u) cp[an][0] += e2;
                    if ((w1 >> bp0) & 1u)       cp[an][1] += e1;
                    if ((w1 >> (bp0 + 8)) & 1u) cp[an][1] += e3;
                }
            }
        }
        if (doCol) {
            #pragma unroll
            for (int an = 0; an < 4; an++) {
                #pragma unroll
                for (int jj = 0; jj < 2; jj++) {
                    float v = cs[an][jj], p = cp[an][jj];
                    v += __shfl_xor_sync(0xffffffffu, v, 4);
                    v += __shfl_xor_sync(0xffffffffu, v, 8);
                    v += __shfl_xor_sync(0xffffffffu, v, 16);
                    p += __shfl_xor_sync(0xffffffffu, p, 4);
                    p += __shfl_xor_sync(0xffffffffu, p, 8);
                    p += __shfl_xor_sync(0xffffffffu, p, 16);
                    if (lane < 4) {
                        int col = c0 + wn * 32 + an * 8 + lane * 2 + jj;
                        atomicAdd(&sumG[col], v);
                        atomicAdd(&posG[col], p);
                    }
                }
            }
        }
        pbuf ^= 1;
    }

    #pragma unroll
    for (int q = 0; q < 4; q++) {
        float v = rs[q], p = rp[q];
        v += __shfl_xor_sync(0xffffffffu, v, 1);
        v += __shfl_xor_sync(0xffffffffu, v, 2);
        p += __shfl_xor_sync(0xffffffffu, p, 1);
        p += __shfl_xor_sync(0xffffffffu, p, 2);
        if ((lane & 3) == 0) {
            int row = r0 + wm * 32 + (q >> 1) * 16 + (q & 1) * 8 + (lane >> 2);
            atomicAdd(&sumG[row], v);
            atomicAdd(&posG[row], p);
        }
    }
}

// C[MxN] += A^T@B over K-slice (fp32, for dim_center)
__global__ __launch_bounds__(256, 2)
void k_atb(const float* __restrict__ A, const float* __restrict__ B,
           float* __restrict__ C, int M, int Nc, int kPerSlice) {
    __shared__ float As[32][132];
    __shared__ float Bs[32][132];
    int tid = threadIdx.x, tx = tid & 15, ty = tid >> 4;
    int r0 = blockIdx.x * 128, c0 = blockIdx.y * 128;
    int kb = blockIdx.z * kPerSlice;
    int ty8 = ty * 8, tx8 = tx * 8;
    float acc[8][8] = {};
    for (int k0 = kb; k0 < kb + kPerSlice; k0 += 32) {
        for (int t = tid; t < 4096; t += 256) {
            int m = t & 127, k = t >> 7;
            As[k][m] = A[(size_t)(k0 + k) * M + r0 + m];
        }
        for (int t = tid; t < 4096; t += 256) {
            int n = t & 127, k = t >> 7;
            Bs[k][n] = B[(size_t)(k0 + k) * Nc + c0 + n];
        }
        __syncthreads();
        #pragma unroll 8
        for (int k = 0; k < 32; k++) {
            float a[8], b[8];
            #pragma unroll
            for (int i = 0; i < 8; i++) a[i] = As[k][ty8 + i];
            #pragma unroll
            for (int j = 0; j < 8; j++) b[j] = Bs[k][tx8 + j];
            #pragma unroll
            for (int i = 0; i < 8; i++)
                #pragma unroll
                for (int j = 0; j < 8; j++) acc[i][j] = fmaf(a[i], b[j], acc[i][j]);
        }
        __syncthreads();
    }
    for (int i = 0; i < 8; i++) {
        size_t r = (size_t)(r0 + ty8 + i) * Nc + c0 + tx8;
        #pragma unroll
        for (int j = 0; j < 8; j++) atomicAdd(&C[r + j], acc[i][j]);
    }
}

// fused dim-label loss (fp32)
__global__ __launch_bounds__(256, 2)
void k_loss_dim(const float* __restrict__ Z, const float* __restrict__ Cn,
                const float* __restrict__ feat,
                float* __restrict__ sumG, float* __restrict__ posG) {
    __shared__ float As[32][132];
    __shared__ float Bs[32][132];
    int tid = threadIdx.x, tx = tid & 15, ty = tid >> 4;
    int r0 = blockIdx.x * 128;
    int c0 = blockIdx.y * 128;
    int ty8 = ty * 8, tx8 = tx * 8;
    float acc[8][8] = {};
    for (int k0 = 0; k0 < Dout; k0 += 32) {
        for (int t = tid; t < 4096; t += 256) {
            int k = t & 31, m = t >> 5;
            As[k][m] = Z[(size_t)(r0 + m) * Dout + k0 + k];
        }
        for (int t = tid; t < 4096; t += 256) {
            int k = t & 31, m = t >> 5;
            Bs[k][m] = Cn[(size_t)(c0 + m) * Dout + k0 + k];
        }
        __syncthreads();
        #pragma unroll 8
        for (int k = 0; k < 32; k++) {
            float a[8], b[8];
            #pragma unroll
            for (int i = 0; i < 8; i++) a[i] = As[k][ty8 + i];
            #pragma unroll
            for (int j = 0; j < 8; j++) b[j] = Bs[k][tx8 + j];
            #pragma unroll
            for (int i = 0; i < 8; i++)
                #pragma unroll
                for (int j = 0; j < 8; j++) acc[i][j] = fmaf(a[i], b[j], acc[i][j]);
        }
        __syncthreads();
    }
    for (int i = 0; i < 8; i++) {
        int rr = r0 + ty8 + i;
        const float* frow = feat + (size_t)rr * Din + c0 + tx8;
        float sA = 0.f, pA = 0.f;
        #pragma unroll
        for (int j = 0; j < 8; j++) {
            float e = __expf(acc[i][j]);
            sA += e;
            if (frow[j] > 0.f) pA += e;
        }
        atomicAdd(&sumG[rr], sA);
        atomicAdd(&posG[rr], pA);
    }
}

__global__ void k_rowloss(const float* __restrict__ sumG, const float* __restrict__ posG,
                          float* loss, int mode) {
    __shared__ float red[256];
    int t = blockIdx.x * 256 + threadIdx.x;
    float term = 0.f;
    if (t < Nn) {
        float pos = posG[t], tot = sumG[t];
        float neg = tot - pos;
        if (mode == 0) term = -logf((pos + 1e-10f) / (neg + 1e-10f));
        else           term = -logf((pos + 1e-10f) / neg + 1e-5f);
    }
    red[threadIdx.x] = term;
    __syncthreads();
    for (int s = 128; s; s >>= 1) {
        if (threadIdx.x < s) red[threadIdx.x] += red[threadIdx.x + s];
        __syncthreads();
    }
    if (threadIdx.x == 0) atomicAdd(loss, red[0]);
}

// ---------------- attention fuse + norms + centers ----------------
__global__ void k_attention(const float* __restrict__ Wp1, const float* __restrict__ bp1,
                            const float* __restrict__ wp2) {
    int nid = blockIdx.x * 256 + threadIdx.x;
    if (nid >= Nn) return;
    const float* hx = g_Hx + (size_t)nid * Dout;
    const float* ha = g_Hadj + (size_t)nid * Dout;
    float accx[AH], acca[AH];
    #pragma unroll
    for (int h = 0; h < AH; h++) { accx[h] = bp1[h]; acca[h] = bp1[h]; }
    for (int d = 0; d < Dout; d++) {
        float vx = hx[d], va = ha[d];
        #pragma unroll
        for (int h = 0; h < AH; h++) {
            float w = Wp1[d * AH + h];
            accx[h] += vx * w; acca[h] += va * w;
        }
    }
    float wx = 0.f, wa = 0.f;
    #pragma unroll
    for (int h = 0; h < AH; h++) {
        wx += tanhf(accx[h]) * wp2[h];
        wa += tanhf(acca[h]) * wp2[h];
    }
    float m = fmaxf(wx, wa);
    float ex = __expf(wx - m), ea = __expf(wa - m);
    float inv = 1.f / (ex + ea);
    float bx = ex * inv, ba = ea * inv;
    float* out = g_Hf + (size_t)nid * Dout;
    for (int d = 0; d < Dout; d++) out[d] = bx * hx[d] + ba * ha[d];
}

__global__ void k_l2norm(const float* __restrict__ in, __half* __restrict__ outH,
                         float* __restrict__ outF, int rows, int cols) {
    int w = (blockIdx.x * blockDim.x + threadIdx.x) >> 5;
    int lane = threadIdx.x & 31;
    if (w >= rows) return;
    const float* r = in + (size_t)w * cols;
    float ss = 0.f;
    for (int c = lane; c < cols; c += 32) { float v = r[c]; ss += v * v; }
    for (int o = 16; o; o >>= 1) ss += __shfl_xor_sync(0xffffffffu, ss, o);
    float inv = 1.f / fmaxf(sqrtf(ss), 1e-12f);
    __half* wh = outH + (size_t)w * cols;
    for (int c = lane; c < cols; c += 32) {
        float v = r[c] * inv;
        wh[c] = __float2half(v);
        if (outF) outF[(size_t)w * cols + c] = v;
    }
}

__global__ void k_colsum(const float* __restrict__ feat) {
    int c = blockIdx.x * 256 + threadIdx.x;
    int rbeg = blockIdx.y * 128;
    float s = 0.f;
    for (int i = rbeg; i < rbeg + 128; i++) s += feat[(size_t)i * Din + c];
    atomicAdd(&g_colsum[c], s);
}

__global__ void k_center() {
    int w = (blockIdx.x * blockDim.x + threadIdx.x) >> 5;
    int lane = threadIdx.x & 31;
    if (w >= Din) return;
    float s = g_colsum[w] + 1e-5f;
    float inv_s = 1.f / s;
    float v[8]; float ss = 0.f;
    #pragma unroll
    for (int i = 0; i < 8; i++) {
        v[i] = g_dcraw[(size_t)w * Dout + lane + 32 * i] * inv_s;
        ss += v[i] * v[i];
    }
    for (int o = 16; o; o >>= 1) ss += __shfl_xor_sync(0xffffffffu, ss, o);
    float inv = 1.f / fmaxf(sqrtf(ss), 1e-12f);
    #pragma unroll
    for (int i = 0; i < 8; i++) g_Cn[(size_t)w * Dout + lane + 32 * i] = v[i] * inv;
}

__global__ void k_final(float* out) {
    out[0] = (0.5f * (g_loss[0] + g_loss[1]) + 0.1f * g_loss[2] + g_loss[3]) * (1.0f / Nn);
}

// ---------------- host ----------------
extern "C" void kernel_launch(void* const* d_in, const int* in_sizes, int n_in,
                              void* d_out, int out_size) {
    const float* feat = (const float*)d_in[0];
    const float* adjL = (const float*)d_in[1];
    const float* adjX = (const float*)d_in[2];
    const float* adjR = (const float*)d_in[3];

    const int *eA, *eX; int pb;
    if (in_sizes[5] == 262144) { eA = (const int*)d_in[4]; eX = (const int*)d_in[5]; pb = 6; }
    else                       { pb = 4; eA = (const int*)d_in[15]; eX = (const int*)d_in[16]; }

    const float* W0a = (const float*)d_in[pb + 0];
    const float* b0a = (const float*)d_in[pb + 1];
    const float* W1a = (const float*)d_in[pb + 2];
    const float* b1a = (const float*)d_in[pb + 3];
    const float* W0x = (const float*)d_in[pb + 4];
    const float* b0x = (const float*)d_in[pb + 5];
    const float* W1x = (const float*)d_in[pb + 6];
    const float* b1x = (const float*)d_in[pb + 7];
    const float* Wp1 = (const float*)d_in[pb + 8];
    const float* bp1 = (const float*)d_in[pb + 9];
    const float* wp2 = (const float*)d_in[pb + 10];

    const int LOSS_SMEM = 3 * 128 * LDH * (int)sizeof(__half) + 4096;  // 206848
    const int GEMM_SMEM = 4 * 128 * LDK * (int)sizeof(__half);

    static int inited = 0;
    static cudaStream_t s1, s2, s3;
    static cudaEvent_t eStart, eConv, ePrep, ePack, eZero, eHadj, eZxh, eZf, eL1, eL2, eL3;
    if (!inited) {
        cudaFuncSetAttribute(k_loss_sym, cudaFuncAttributeMaxDynamicSharedMemorySize, LOSS_SMEM);
        cudaFuncSetAttribute(k_gemm_h, cudaFuncAttributeMaxDynamicSharedMemorySize, GEMM_SMEM);
        cudaStreamCreateWithFlags(&s1, cudaStreamNonBlocking);
        cudaStreamCreateWithFlags(&s2, cudaStreamNonBlocking);
        cudaStreamCreateWithFlags(&s3, cudaStreamNonBlocking);
        cudaEventCreateWithFlags(&eStart, cudaEventDisableTiming);
        cudaEventCreateWithFlags(&eConv,  cudaEventDisableTiming);
        cudaEventCreateWithFlags(&ePrep,  cudaEventDisableTiming);
        cudaEventCreateWithFlags(&ePack,  cudaEventDisableTiming);
        cudaEventCreateWithFlags(&eZero,  cudaEventDisableTiming);
        cudaEventCreateWithFlags(&eHadj,  cudaEventDisableTiming);
        cudaEventCreateWithFlags(&eZxh,   cudaEventDisableTiming);
        cudaEventCreateWithFlags(&eZf,    cudaEventDisableTiming);
        cudaEventCreateWithFlags(&eL1,    cudaEventDisableTiming);
        cudaEventCreateWithFlags(&eL2,    cudaEventDisableTiming);
        cudaEventCreateWithFlags(&eL3,    cudaEventDisableTiming);
        inited = 1;
    }

    void *pY, *pY2, *pHadj, *pHx, *pHf, *pZf, *pFH, *pH1h, *pH1h2, *pZah, *pZxh, *pZfh, *pWt;
    void *pDeg, *pNrm, *pOff, *pCur, *pEidx, *pBits;
    void *pDc, *pCn, *pCs, *pSum, *pPos, *pLoss;
    cudaGetSymbolAddress(&pY, g_Y);       cudaGetSymbolAddress(&pY2, g_Y2);
    cudaGetSymbolAddress(&pHadj, g_Hadj); cudaGetSymbolAddress(&pHx, g_Hx);
    cudaGetSymbolAddress(&pHf, g_Hf);     cudaGetSymbolAddress(&pZf, g_Zf);
    cudaGetSymbolAddress(&pFH, g_featH);  cudaGetSymbolAddress(&pH1h, g_H1h);
    cudaGetSymbolAddress(&pH1h2, g_H1h2);
    cudaGetSymbolAddress(&pZah, g_Zah);   cudaGetSymbolAddress(&pZxh, g_Zxh);
    cudaGetSymbolAddress(&pZfh, g_Zfh);   cudaGetSymbolAddress(&pWt, g_Wt);
    cudaGetSymbolAddress(&pDeg, g_deg);   cudaGetSymbolAddress(&pNrm, g_nrm);
    cudaGetSymbolAddress(&pOff, g_off);   cudaGetSymbolAddress(&pCur, g_cursor);
    cudaGetSymbolAddress(&pEidx, g_eidx); cudaGetSymbolAddress(&pBits, g_bits);
    cudaGetSymbolAddress(&pDc, g_dcraw);  cudaGetSymbolAddress(&pCn, g_Cn);
    cudaGetSymbolAddress(&pCs, g_colsum); cudaGetSymbolAddress(&pSum, g_sum);
    cudaGetSymbolAddress(&pPos, g_pos);   cudaGetSymbolAddress(&pLoss, g_loss);

    float* deg = (float*)pDeg;
    float* nrm = (float*)pNrm;
    float* nsA = nrm;           float* ndA = nrm + Nn;
    float* nsX = nrm + 2 * Nn;  float* ndX = nrm + 3 * Nn;
    int* offA = (int*)pOff;     int* offX = offA + (Nn + 1);
    int* eidxA = (int*)pEidx;   int* eidxX = eidxA + Ne;
    unsigned* bitsL = (unsigned*)pBits;
    unsigned* bitsX = bitsL + (size_t)Nn * NW;
    unsigned* bitsR = bitsX + (size_t)Nn * NW;
    __half* featH = (__half*)pFH;
    __half* H1h = (__half*)pH1h;
    __half* H1h2 = (__half*)pH1h2;
    __half* W0aT = (__half*)pWt;
    __half* W1aT = W0aT + Din * Din;
    __half* W0xT = W1aT + Din * Dout;
    __half* W1xT = W0xT + Din * Din;
    float* sum = (float*)pSum;  float* pos = (float*)pPos;
    float* loss = (float*)pLoss;
    const int packBlocks = (Nn * NW) / 64;

    // ---- fork ----
    cudaEventRecord(eStart, 0);
    cudaStreamWaitEvent(s1, eStart, 0);
    cudaStreamWaitEvent(s2, eStart, 0);

    // ---- s2: zeroing + colsum + packs ----
    cudaMemsetAsync(pCs, 0, Din * sizeof(float), s2);
    cudaMemsetAsync(pDc, 0, (size_t)Din * Dout * sizeof(float), s2);
    cudaMemsetAsync(pSum, 0, 4 * Nn * sizeof(float), s2);
    cudaMemsetAsync(pPos, 0, 4 * Nn * sizeof(float), s2);
    cudaMemsetAsync(pLoss, 0, 4 * sizeof(float), s2);
    k_colsum<<<dim3(2, 64), 256, 0, s2>>>(feat);
    cudaEventRecord(eZero, s2);
    k_pack<<<packBlocks, 256, 0, s2>>>(adjL, bitsL);
    k_pack<<<packBlocks, 256, 0, s2>>>(adjX, bitsX);
    k_pack<<<packBlocks, 256, 0, s2>>>(adjR, bitsR);
    cudaEventRecord(ePack, s2);

    // ---- s1: conversions + branch A start ----
    k_f2h<<<(Nn * Din / 4 + 255) / 256, 256, 0, s1>>>(feat, featH, Nn * Din / 4);
    k_wth<<<(Din * Din + 255) / 256, 256, 0, s1>>>(W0a, W0aT, Din, Din);
    k_wth<<<(Din * Dout + 255) / 256, 256, 0, s1>>>(W1a, W1aT, Din, Dout);
    k_wth<<<(Din * Din + 255) / 256, 256, 0, s1>>>(W0x, W0xT, Din, Din);
    k_wth<<<(Din * Dout + 255) / 256, 256, 0, s1>>>(W1x, W1xT, Din, Dout);
    cudaEventRecord(eConv, s1);
    k_gemm_h<<<dim3(Nn / 128, Din / 128), 256, GEMM_SMEM, s1>>>(featH, W0aT, (float*)pY, Din, Din);

    // ---- s0: graph prep ----
    cudaMemsetAsync(pDeg, 0, 4 * Nn * sizeof(float), 0);
    cudaMemsetAsync(pCur, 0, 2 * Nn * sizeof(int), 0);
    k_degree<<<(Ne + 255) / 256, 256>>>(eA, eA + Ne, deg, deg + Nn);
    k_degree<<<(Ne + 255) / 256, 256>>>(eX, eX + Ne, deg + 2 * Nn, deg + 3 * Nn);
    k_norm<<<(4 * Nn) / 256, 256>>>();
    k_scan<<<1, 1024>>>(deg + Nn, offA);
    k_scan<<<1, 1024>>>(deg + 3 * Nn, offX);
    k_bucket<<<(Ne + 255) / 256, 256>>>(eA, eA + Ne, offA, (int*)pCur, eidxA);
    k_bucket<<<(Ne + 255) / 256, 256>>>(eX, eX + Ne, offX, (int*)pCur + Nn, eidxX);
    cudaEventRecord(ePrep, 0);

    // ---- s1: branch A finish + loss A ----
    cudaStreamWaitEvent(s1, ePrep, 0);
    k_gather_h<<<Nn, Din / 4, 0, s1>>>(offA, eidxA, (float*)pY, nsA, ndA, b0a, H1h, Din / 4);
    k_gemm_h<<<dim3(Nn / 128, Dout / 128), 256, GEMM_SMEM, s1>>>(H1h, W1aT, (float*)pY, Dout, Din);
    k_gather<<<Nn, Dout / 4, 0, s1>>>(offA, eidxA, (float*)pY, nsA, ndA, b1a, (float*)pHadj, Dout / 4);
    cudaEventRecord(eHadj, s1);
    k_l2norm<<<Nn / 8, 256, 0, s1>>>((float*)pHadj, (__half*)pZah, nullptr, Nn, Dout);
    cudaStreamWaitEvent(s1, ePack, 0);
    k_loss_sym<<<dim3(64, 2), 512, LOSS_SMEM, s1>>>((const __half*)pZah, bitsL, sum, pos);
    k_rowloss<<<Nn / 256, 256, 0, s1>>>(sum, pos, loss + 0, 0);
    cudaEventRecord(eL1, s1);

    // ---- s0: branch X ----
    cudaStreamWaitEvent(0, eConv, 0);
    k_gemm_h<<<dim3(Nn / 128, Din / 128), 256, GEMM_SMEM>>>(featH, W0xT, (float*)pY2, Din, Din);
    k_gather_h<<<Nn, Din / 4>>>(offX, eidxX, (float*)pY2, nsX, ndX, b0x, H1h2, Din / 4);
    k_gemm_h<<<dim3(Nn / 128, Dout / 128), 256, GEMM_SMEM>>>(H1h2, W1xT, (float*)pY2, Dout, Din);
    k_gather<<<Nn, Dout / 4>>>(offX, eidxX, (float*)pY2, nsX, ndX, b1x, (float*)pHx, Dout / 4);
    k_l2norm<<<Nn / 8, 256>>>((float*)pHx, (__half*)pZxh, nullptr, Nn, Dout);
    cudaEventRecord(eZxh, 0);

    // ---- s3: loss X ----
    cudaStreamWaitEvent(s3, eZxh, 0);
    cudaStreamWaitEvent(s3, ePack, 0);
    k_loss_sym<<<dim3(64, 2), 512, LOSS_SMEM, s3>>>((const __half*)pZxh, bitsX, sum + Nn, pos + Nn);
    k_rowloss<<<Nn / 256, 256, 0, s3>>>(sum + Nn, pos + Nn, loss + 1, 0);
    cudaEventRecord(eL2, s3);

    // ---- s0: attention + fused embedding ----
    cudaStreamWaitEvent(0, eHadj, 0);
    k_attention<<<Nn / 256, 256>>>(Wp1, bp1, wp2);
    k_l2norm<<<Nn / 8, 256>>>((float*)pHf, (__half*)pZfh, (float*)pZf, Nn, Dout);
    cudaEventRecord(eZf, 0);

    // ---- s2: loss R ----
    cudaStreamWaitEvent(s2, eZf, 0);
    k_loss_sym<<<dim3(64, 2), 512, LOSS_SMEM, s2>>>((const __half*)pZfh, bitsR, sum + 3 * Nn, pos + 3 * Nn);
    k_rowloss<<<Nn / 256, 256, 0, s2>>>(sum + 3 * Nn, pos + 3 * Nn, loss + 3, 0);
    cudaEventRecord(eL3, s2);

    // ---- s0: dim_center + dim loss ----
    cudaStreamWaitEvent(0, eZero, 0);
    k_atb<<<dim3(Din / 128, Dout / 128, 32), 256>>>(feat, (float*)pHf, (float*)pDc, Din, Dout, Nn / 32);
    k_center<<<Din / 8, 256>>>();
    k_loss_dim<<<dim3(Nn / 128, Din / 128), 256>>>((float*)pZf, (float*)pCn, feat,
                                                   sum + 2 * Nn, pos + 2 * Nn);
    k_rowloss<<<Nn / 256, 256>>>(sum + 2 * Nn, pos + 2 * Nn, loss + 2, 1);

    // ---- join + final ----
    cudaStreamWaitEvent(0, eL1, 0);
    cudaStreamWaitEvent(0, eL2, 0);
    cudaStreamWaitEvent(0, eL3, 0);
    k_final<<<1, 1>>>((float*)d_out);
}

// round 16
// speedup vs baseline: 5.7426x; 1.1737x over previous
#include <cuda_runtime.h>
#include <cuda_fp16.h>
#include <cstdint>
#include <math.h>

#define Nn   8192
#define Din  512
#define Dout 256
#define Ne   131072
#define AH   16
#define LDH  264   // loss smem stride (halves): 528B, conflict-free ldmatrix
#define NW   256   // bitmask words per row (adj)
#define NWF  16    // bitmask words per row (feat)
#define LDK  72    // gemm_h chunk stride (halves)

// ---------------- static scratch ----------------
static __device__ float g_Y[Nn*Din];
static __device__ float g_Y2[Nn*Din];
static __device__ float g_Hadj[Nn*Dout];
static __device__ float g_Hx[Nn*Dout];
static __device__ float g_Hf[Nn*Dout];
static __device__ __half g_featH[Nn*Din];
static __device__ __half g_featTh[Din*Nn];
static __device__ __half g_HfTh[Dout*Nn];
static __device__ __half g_H1h[Nn*Din];
static __device__ __half g_H1h2[Nn*Din];
static __device__ __half g_Zah[Nn*Dout];
static __device__ __half g_Zxh[Nn*Dout];
static __device__ __half g_Zfh[Nn*Dout];
static __device__ __half g_CnH[Din*Dout];
static __device__ __half g_Wt[2*(Din*Din + Din*Dout)];
static __device__ float g_deg[4*Nn];
static __device__ float g_nrm[4*Nn];
static __device__ int   g_off[2*(Nn+1)];
static __device__ int   g_cursor[2*Nn];
static __device__ int   g_eidx[2*Ne];
static __device__ unsigned g_bits[3u*Nn*NW];
static __device__ unsigned g_fbits[Nn*NWF];
static __device__ float g_dcraw[Din*Dout];
static __device__ float g_Cn[Din*Dout];
static __device__ float g_colsum[Din];
static __device__ float g_sum[4*Nn];
static __device__ float g_pos[4*Nn];
static __device__ float g_loss[4];

__device__ __forceinline__ unsigned int saddr(const void* p) {
    return (unsigned int)__cvta_generic_to_shared(p);
}
__device__ __forceinline__ void cpasync16(unsigned int dst, const void* src) {
    asm volatile("cp.async.cg.shared.global [%0], [%1], 16;" :: "r"(dst), "l"(src));
}
__device__ __forceinline__ void cpcommit() { asm volatile("cp.async.commit_group;"); }
__device__ __forceinline__ void cpwait0()  { asm volatile("cp.async.wait_group 0;"); }

// ---------------- graph preprocessing ----------------
__global__ void k_degree(const int* __restrict__ src, const int* __restrict__ dst,
                         float* degO, float* degI) {
    int t = blockIdx.x * 256 + threadIdx.x;
    if (t < Ne) { atomicAdd(degO + src[t], 1.f); atomicAdd(degI + dst[t], 1.f); }
}

__global__ void k_norm(int base, int cnt) {
    int t = blockIdx.x * 256 + threadIdx.x;
    if (t < cnt) {
        float d = g_deg[base + t];
        g_nrm[base + t] = (d > 0.f) ? rsqrtf(d) : 0.f;
    }
}

__global__ void k_scan(const float* __restrict__ degIn, int* __restrict__ off) {
    __shared__ int part[1024];
    int t = threadIdx.x;
    int v[8]; int s = 0;
    #pragma unroll
    for (int i = 0; i < 8; i++) { v[i] = s; s += (int)degIn[t * 8 + i]; }
    part[t] = s;
    __syncthreads();
    for (int d = 1; d < 1024; d <<= 1) {
        int x = (t >= d) ? part[t - d] : 0;
        __syncthreads();
        part[t] += x;
        __syncthreads();
    }
    int base = (t > 0) ? part[t - 1] : 0;
    #pragma unroll
    for (int i = 0; i < 8; i++) off[t * 8 + i] = base + v[i];
    if (t == 1023) off[Nn] = part[1023];
}

__global__ void k_bucket(const int* __restrict__ src, const int* __restrict__ dst,
                         const int* __restrict__ off, int* __restrict__ cursor,
                         int* __restrict__ eidx) {
    int t = blockIdx.x * 256 + threadIdx.x;
    if (t >= Ne) return;
    int d = dst[t];
    int p = atomicAdd(&cursor[d], 1);
    eidx[off[d] + p] = src[t];
}

__global__ void k_gather(const int* __restrict__ off, const int* __restrict__ eidx,
                         const float* __restrict__ Y, const float* __restrict__ ns,
                         const float* __restrict__ nd, const float* __restrict__ bias,
                         float* __restrict__ H, int C4) {
    int n = blockIdx.x, c = threadIdx.x;
    int s0 = off[n], s1 = off[n + 1];
    float4 acc = {0.f, 0.f, 0.f, 0.f};
    for (int i = s0; i < s1; i++) {
        int s = eidx[i];
        float w = ns[s];
        float4 v = ((const float4*)Y)[(size_t)s * C4 + c];
        acc.x += v.x * w; acc.y += v.y * w; acc.z += v.z * w; acc.w += v.w * w;
    }
    float sc = nd[n];
    float4 b = ((const float4*)bias)[c];
    float4 o;
    o.x = acc.x * sc + b.x; o.y = acc.y * sc + b.y;
    o.z = acc.z * sc + b.z; o.w = acc.w * sc + b.w;
    ((float4*)H)[(size_t)n * C4 + c] = o;
}

__global__ void k_gather_h(const int* __restrict__ off, const int* __restrict__ eidx,
                           const float* __restrict__ Y, const float* __restrict__ ns,
                           const float* __restrict__ nd, const float* __restrict__ bias,
                           __half* __restrict__ H, int C4) {
    int n = blockIdx.x, c = threadIdx.x;
    int s0 = off[n], s1 = off[n + 1];
    float4 acc = {0.f, 0.f, 0.f, 0.f};
    for (int i = s0; i < s1; i++) {
        int s = eidx[i];
        float w = ns[s];
        float4 v = ((const float4*)Y)[(size_t)s * C4 + c];
        acc.x += v.x * w; acc.y += v.y * w; acc.z += v.z * w; acc.w += v.w * w;
    }
    float sc = nd[n];
    float4 b = ((const float4*)bias)[c];
    float ox = fmaxf(acc.x * sc + b.x, 0.f);
    float oy = fmaxf(acc.y * sc + b.y, 0.f);
    float oz = fmaxf(acc.z * sc + b.z, 0.f);
    float ow = fmaxf(acc.w * sc + b.w, 0.f);
    ((__half2*)H)[((size_t)n * C4 + c) * 2 + 0] = __floats2half2_rn(ox, oy);
    ((__half2*)H)[((size_t)n * C4 + c) * 2 + 1] = __floats2half2_rn(oz, ow);
}

__global__ void k_pack(const float* __restrict__ a, unsigned* __restrict__ bits) {
    size_t w8 = ((size_t)blockIdx.x * 8 + (threadIdx.x >> 5)) * 8;
    int lane = threadIdx.x & 31;
    const float* base = a + w8 * 32 + lane;
    float v0 = __ldcs(base + 0 * 32);
    float v1 = __ldcs(base + 1 * 32);
    float v2 = __ldcs(base + 2 * 32);
    float v3 = __ldcs(base + 3 * 32);
    float v4 = __ldcs(base + 4 * 32);
    float v5 = __ldcs(base + 5 * 32);
    float v6 = __ldcs(base + 6 * 32);
    float v7 = __ldcs(base + 7 * 32);
    unsigned m0 = __ballot_sync(0xffffffffu, v0 != 0.f);
    unsigned m1 = __ballot_sync(0xffffffffu, v1 != 0.f);
    unsigned m2 = __ballot_sync(0xffffffffu, v2 != 0.f);
    unsigned m3 = __ballot_sync(0xffffffffu, v3 != 0.f);
    unsigned m4 = __ballot_sync(0xffffffffu, v4 != 0.f);
    unsigned m5 = __ballot_sync(0xffffffffu, v5 != 0.f);
    unsigned m6 = __ballot_sync(0xffffffffu, v6 != 0.f);
    unsigned m7 = __ballot_sync(0xffffffffu, v7 != 0.f);
    if (lane == 0) {
        *(uint4*)&bits[w8 + 0] = make_uint4(m0, m1, m2, m3);
        *(uint4*)&bits[w8 + 4] = make_uint4(m4, m5, m6, m7);
    }
}

// positivity pack (feat > 0)
__global__ void k_packp(const float* __restrict__ a, unsigned* __restrict__ bits) {
    size_t w8 = ((size_t)blockIdx.x * 8 + (threadIdx.x >> 5)) * 8;
    int lane = threadIdx.x & 31;
    const float* base = a + w8 * 32 + lane;
    float v0 = __ldcs(base + 0 * 32);
    float v1 = __ldcs(base + 1 * 32);
    float v2 = __ldcs(base + 2 * 32);
    float v3 = __ldcs(base + 3 * 32);
    float v4 = __ldcs(base + 4 * 32);
    float v5 = __ldcs(base + 5 * 32);
    float v6 = __ldcs(base + 6 * 32);
    float v7 = __ldcs(base + 7 * 32);
    unsigned m0 = __ballot_sync(0xffffffffu, v0 > 0.f);
    unsigned m1 = __ballot_sync(0xffffffffu, v1 > 0.f);
    unsigned m2 = __ballot_sync(0xffffffffu, v2 > 0.f);
    unsigned m3 = __ballot_sync(0xffffffffu, v3 > 0.f);
    unsigned m4 = __ballot_sync(0xffffffffu, v4 > 0.f);
    unsigned m5 = __ballot_sync(0xffffffffu, v5 > 0.f);
    unsigned m6 = __ballot_sync(0xffffffffu, v6 > 0.f);
    unsigned m7 = __ballot_sync(0xffffffffu, v7 > 0.f);
    if (lane == 0) {
        *(uint4*)&bits[w8 + 0] = make_uint4(m0, m1, m2, m3);
        *(uint4*)&bits[w8 + 4] = make_uint4(m4, m5, m6, m7);
    }
}

// ---------------- conversions / transposes ----------------
__global__ void k_f2h(const float* __restrict__ in, __half* __restrict__ out, int n4) {
    int i = blockIdx.x * 256 + threadIdx.x;
    if (i >= n4) return;
    float4 v = ((const float4*)in)[i];
    ((__half2*)out)[i * 2 + 0] = __floats2half2_rn(v.x, v.y);
    ((__half2*)out)[i * 2 + 1] = __floats2half2_rn(v.z, v.w);
}

__global__ void k_wth(const float* __restrict__ W, __half* __restrict__ Wt, int K, int N) {
    int i = blockIdx.x * 256 + threadIdx.x;
    if (i >= K * N) return;
    int k = i / N, n = i % N;
    Wt[(size_t)n * K + k] = __float2half(W[i]);
}

// half transpose: in[R][C] -> out[C][R]
__global__ void k_tr_h(const __half* __restrict__ in, __half* __restrict__ out,
                       int R, int C) {
    __shared__ __half tile[32][33];
    int c0 = blockIdx.x * 32, r0 = blockIdx.y * 32;
    int tx = threadIdx.x;
    for (int i = threadIdx.y; i < 32; i += 8)
        tile[i][tx] = in[(size_t)(r0 + i) * C + c0 + tx];
    __syncthreads();
    for (int i = threadIdx.y; i < 32; i += 8)
        out[(size_t)(c0 + i) * R + r0 + tx] = tile[tx][i];
}

// fp32 -> half transpose: in[R][C] float -> out[C][R] half
__global__ void k_trf_h(const float* __restrict__ in, __half* __restrict__ out,
                        int R, int C) {
    __shared__ __half tile[32][33];
    int c0 = blockIdx.x * 32, r0 = blockIdx.y * 32;
    int tx = threadIdx.x;
    for (int i = threadIdx.y; i < 32; i += 8)
        tile[i][tx] = __float2half(in[(size_t)(r0 + i) * C + c0 + tx]);
    __syncthreads();
    for (int i = threadIdx.y; i < 32; i += 8)
        out[(size_t)(c0 + i) * R + r0 + tx] = tile[tx][i];
}

// ---------------- fp16 tensor-core GEMM: C = A[MxK] @ Bt[NcxK]^T ----------------
__global__ __launch_bounds__(256)
void k_gemm_h(const __half* __restrict__ A, const __half* __restrict__ Bt,
              float* __restrict__ C, int Nc, int K) {
    extern __shared__ __half sg[];
    __half* As = sg;
    __half* Bs = sg + 2 * 128 * LDK;
    const int BUF = 128 * LDK;
    const int tid = threadIdx.x;
    const int lane = tid & 31, warp = tid >> 5;
    const int wm = warp >> 1, wn = warp & 1;
    const int r0 = blockIdx.x * 128, c0 = blockIdx.y * 128;

    const int mat = lane >> 3, r = lane & 7;
    unsigned int aB[2], bB[4];
    #pragma unroll
    for (int am = 0; am < 2; am++) {
        int row = wm * 32 + am * 16 + (mat & 1) * 8 + r;
        aB[am] = saddr(&As[row * LDK + (mat >> 1) * 8]);
    }
    #pragma unroll
    for (int p = 0; p < 4; p++) {
        int row = wn * 64 + p * 16 + (mat >> 1) * 8 + r;
        bB[p] = saddr(&Bs[row * LDK + (mat & 1) * 8]);
    }

    float acc[2][8][4] = {};
    const int nch = K / 64;

    #pragma unroll
    for (int i = 0; i < 4; i++) {
        int idx = tid + i * 256;
        int row = idx >> 3, c8 = (idx & 7) * 8;
        cpasync16(saddr(&As[row * LDK + c8]), &A[(size_t)(r0 + row) * K + c8]);
        cpasync16(saddr(&Bs[row * LDK + c8]), &Bt[(size_t)(c0 + row) * K + c8]);
    }
    cpcommit();

    for (int ch = 0; ch < nch; ch++) {
        int p = ch & 1;
        cpwait0();
        __syncthreads();
        if (ch + 1 < nch) {
            int np = 1 - p, k0g = (ch + 1) * 64;
            #pragma unroll
            for (int i = 0; i < 4; i++) {
                int idx = tid + i * 256;
                int row = idx >> 3, c8 = (idx & 7) * 8;
                cpasync16(saddr(&As[np * BUF + row * LDK + c8]),
                          &A[(size_t)(r0 + row) * K + k0g + c8]);
                cpasync16(saddr(&Bs[np * BUF + row * LDK + c8]),
                          &Bt[(size_t)(c0 + row) * K + k0g + c8]);
            }
            cpcommit();
        }
        const unsigned int bufOff = p * BUF * 2;
        #pragma unroll
        for (int k0 = 0; k0 < 64; k0 += 16) {
            unsigned int a[2][4], b[4][4];
            #pragma unroll
            for (int am = 0; am < 2; am++)
                asm volatile("ldmatrix.sync.aligned.m8n8.x4.shared.b16 {%0,%1,%2,%3}, [%4];"
                    : "=r"(a[am][0]), "=r"(a[am][1]), "=r"(a[am][2]), "=r"(a[am][3])
                    : "r"(aB[am] + bufOff + k0 * 2));
            #pragma unroll
            for (int q = 0; q < 4; q++)
                asm volatile("ldmatrix.sync.aligned.m8n8.x4.shared.b16 {%0,%1,%2,%3}, [%4];"
                    : "=r"(b[q][0]), "=r"(b[q][1]), "=r"(b[q][2]), "=r"(b[q][3])
                    : "r"(bB[q] + bufOff + k0 * 2));
            #pragma unroll
            for (int am = 0; am < 2; am++)
                #pragma unroll
                for (int an = 0; an < 8; an++) {
                    int q = an >> 1, s = (an & 1) * 2;
                    asm volatile(
                        "mma.sync.aligned.m16n8k16.row.col.f32.f16.f16.f32 "
                        "{%0,%1,%2,%3}, {%4,%5,%6,%7}, {%8,%9}, {%0,%1,%2,%3};"
                        : "+f"(acc[am][an][0]), "+f"(acc[am][an][1]),
                          "+f"(acc[am][an][2]), "+f"(acc[am][an][3])
                        : "r"(a[am][0]), "r"(a[am][1]), "r"(a[am][2]), "r"(a[am][3]),
                          "r"(b[q][s]), "r"(b[q][s + 1]));
                }
        }
        __syncthreads();
    }

    #pragma unroll
    for (int am = 0; am < 2; am++) {
        int row = r0 + wm * 32 + am * 16 + (lane >> 2);
        #pragma unroll
        for (int an = 0; an < 8; an++) {
            int col = c0 + wn * 64 + an * 8 + (lane & 3) * 2;
            *(float2*)&C[(size_t)row * Nc + col] =
                make_float2(acc[am][an][0], acc[am][an][1]);
            *(float2*)&C[(size_t)(row + 8) * Nc + col] =
                make_float2(acc[am][an][2], acc[am][an][3]);
        }
    }
}

// K-sliced fp16 GEMM with atomic fp32 accumulation: C += A[:,kslice] @ Bt[:,kslice]^T
__global__ __launch_bounds__(256)
void k_gemm_atb_h(const __half* __restrict__ A, const __half* __restrict__ Bt,
                  float* __restrict__ C, int Nc, int K, int kPerSlice) {
    extern __shared__ __half sg[];
    __half* As = sg;
    __half* Bs = sg + 2 * 128 * LDK;
    const int BUF = 128 * LDK;
    const int tid = threadIdx.x;
    const int lane = tid & 31, warp = tid >> 5;
    const int wm = warp >> 1, wn = warp & 1;
    const int r0 = blockIdx.x * 128, c0 = blockIdx.y * 128;
    const int kOff = blockIdx.z * kPerSlice;

    const int mat = lane >> 3, r = lane & 7;
    unsigned int aB[2], bB[4];
    #pragma unroll
    for (int am = 0; am < 2; am++) {
        int row = wm * 32 + am * 16 + (mat & 1) * 8 + r;
        aB[am] = saddr(&As[row * LDK + (mat >> 1) * 8]);
    }
    #pragma unroll
    for (int p = 0; p < 4; p++) {
        int row = wn * 64 + p * 16 + (mat >> 1) * 8 + r;
        bB[p] = saddr(&Bs[row * LDK + (mat & 1) * 8]);
    }

    float acc[2][8][4] = {};
    const int nch = kPerSlice / 64;

    #pragma unroll
    for (int i = 0; i < 4; i++) {
        int idx = tid + i * 256;
        int row = idx >> 3, c8 = (idx & 7) * 8;
        cpasync16(saddr(&As[row * LDK + c8]), &A[(size_t)(r0 + row) * K + kOff + c8]);
        cpasync16(saddr(&Bs[row * LDK + c8]), &Bt[(size_t)(c0 + row) * K + kOff + c8]);
    }
    cpcommit();

    for (int ch = 0; ch < nch; ch++) {
        int p = ch & 1;
        cpwait0();
        __syncthreads();
        if (ch + 1 < nch) {
            int np = 1 - p, k0g = kOff + (ch + 1) * 64;
            #pragma unroll
            for (int i = 0; i < 4; i++) {
                int idx = tid + i * 256;
                int row = idx >> 3, c8 = (idx & 7) * 8;
                cpasync16(saddr(&As[np * BUF + row * LDK + c8]),
                          &A[(size_t)(r0 + row) * K + k0g + c8]);
                cpasync16(saddr(&Bs[np * BUF + row * LDK + c8]),
                          &Bt[(size_t)(c0 + row) * K + k0g + c8]);
            }
            cpcommit();
        }
        const unsigned int bufOff = p * BUF * 2;
        #pragma unroll
        for (int k0 = 0; k0 < 64; k0 += 16) {
            unsigned int a[2][4], b[4][4];
            #pragma unroll
            for (int am = 0; am < 2; am++)
                asm volatile("ldmatrix.sync.aligned.m8n8.x4.shared.b16 {%0,%1,%2,%3}, [%4];"
                    : "=r"(a[am][0]), "=r"(a[am][1]), "=r"(a[am][2]), "=r"(a[am][3])
                    : "r"(aB[am] + bufOff + k0 * 2));
            #pragma unroll
            for (int q = 0; q < 4; q++)
                asm volatile("ldmatrix.sync.aligned.m8n8.x4.shared.b16 {%0,%1,%2,%3}, [%4];"
                    : "=r"(b[q][0]), "=r"(b[q][1]), "=r"(b[q][2]), "=r"(b[q][3])
                    : "r"(bB[q] + bufOff + k0 * 2));
            #pragma unroll
            for (int am = 0; am < 2; am++)
                #pragma unroll
                for (int an = 0; an < 8; an++) {
                    int q = an >> 1, s = (an & 1) * 2;
                    asm volatile(
                        "mma.sync.aligned.m16n8k16.row.col.f32.f16.f16.f32 "
                        "{%0,%1,%2,%3}, {%4,%5,%6,%7}, {%8,%9}, {%0,%1,%2,%3};"
                        : "+f"(acc[am][an][0]), "+f"(acc[am][an][1]),
                          "+f"(acc[am][an][2]), "+f"(acc[am][an][3])
                        : "r"(a[am][0]), "r"(a[am][1]), "r"(a[am][2]), "r"(a[am][3]),
                          "r"(b[q][s]), "r"(b[q][s + 1]));
                }
        }
        __syncthreads();
    }

    #pragma unroll
    for (int am = 0; am < 2; am++) {
        int row = r0 + wm * 32 + am * 16 + (lane >> 2);
        #pragma unroll
        for (int an = 0; an < 8; an++) {
            int col = c0 + wn * 64 + an * 8 + (lane & 3) * 2;
            atomicAdd(&C[(size_t)row * Nc + col],     acc[am][an][0]);
            atomicAdd(&C[(size_t)row * Nc + col + 1], acc[am][an][1]);
            atomicAdd(&C[(size_t)(row + 8) * Nc + col],     acc[am][an][2]);
            atomicAdd(&C[(size_t)(row + 8) * Nc + col + 1], acc[am][an][3]);
        }
    }
}

// ---------------- symmetric contrastive loss, 16 warps, resident-A + dbl-buffered B ----------------
__global__ __launch_bounds__(512)
void k_loss_sym(const __half* __restrict__ Zh, const unsigned* __restrict__ bits,
                float* __restrict__ sumG, float* __restrict__ posG) {
    const int x = blockIdx.x, s = blockIdx.y;
    const int tmax = (x < 32) ? 33 : 32;
    const int tBeg = (s == 0) ? 0 : 17;
    const int tEnd = (s == 0) ? 17 : tmax;
    const int r0 = x * 128;

    extern __shared__ __half sh[];
    __half* As = sh;
    __half* Bs = sh + 128 * LDH;
    unsigned* bitsS = (unsigned*)(sh + 3 * 128 * LDH);
    const unsigned int BUFB = 128 * LDH * 2;

    const int tid = threadIdx.x;
    const int lane = tid & 31, warp = tid >> 5;
    const int wm = warp >> 2, wn = warp & 3;

    for (int t = tid; t < 4096; t += 512) {
        int row = t >> 5, c8 = (t & 31) * 8;
        *(float4*)&As[row * LDH + c8] =
            *(const float4*)&Zh[(size_t)(r0 + row) * Dout + c8];
    }

    const int mat = lane >> 3, r = lane & 7;
    unsigned int aBase[2], bBase[2];
    #pragma unroll
    for (int am = 0; am < 2; am++) {
        int row = wm * 32 + am * 16 + (mat & 1) * 8 + r;
        aBase[am] = saddr(&As[row * LDH + (mat >> 1) * 8]);
    }
    #pragma unroll
    for (int p = 0; p < 2; p++) {
        int row = wn * 32 + p * 16 + (mat >> 1) * 8 + r;
        bBase[p] = saddr(&Bs[row * LDH + (mat & 1) * 8]);
    }

    {
        int j = (x + tBeg) & 63;
        int c0 = j * 128;
        #pragma unroll
        for (int i = 0; i < 8; i++) {
            int idx = tid + i * 512;
            int row = idx >> 5, c8 = (idx & 31) * 8;
            cpasync16(saddr(&Bs[row * LDH + c8]),
                      &Zh[(size_t)(c0 + row) * Dout + c8]);
        }
        cpcommit();
        if (tid < 128)
            *(uint4*)&bitsS[tid * 4] =
                *(const uint4*)&bits[(size_t)(c0 + tid) * NW + (r0 >> 5)];
    }

    float rs[4] = {}, rp[4] = {};
    const int bitPos = (lane & 3) * 2;
    int pbuf = 0;

    for (int t = tBeg; t < tEnd; t++) {
        const int j = (x + t) & 63;
        const int c0 = j * 128;
        cpwait0();
        __syncthreads();
        if (t + 1 < tEnd) {
            int np = 1 - pbuf;
            int jn = (x + t + 1) & 63;
            int c0n = jn * 128;
            #pragma unroll
            for (int i = 0; i < 8; i++) {
                int idx = tid + i * 512;
                int row = idx >> 5, c8 = (idx & 31) * 8;
                cpasync16(saddr(&Bs[np * 128 * LDH + row * LDH + c8]),
                          &Zh[(size_t)(c0n + row) * Dout + c8]);
            }
            cpcommit();
            if (tid < 128)
                *(uint4*)&bitsS[np * 512 + tid * 4] =
                    *(const uint4*)&bits[(size_t)(c0n + tid) * NW + (r0 >> 5)];
        }
        const unsigned int bOff = pbuf * BUFB;

        float acc[2][4][4] = {};
        #pragma unroll
        for (int k0 = 0; k0 < Dout; k0 += 16) {
            unsigned int a[2][4], b[2][4];
            #pragma unroll
            for (int am = 0; am < 2; am++)
                asm volatile("ldmatrix.sync.aligned.m8n8.x4.shared.b16 {%0,%1,%2,%3}, [%4];"
                    : "=r"(a[am][0]), "=r"(a[am][1]), "=r"(a[am][2]), "=r"(a[am][3])
                    : "r"(aBase[am] + k0 * 2));
            #pragma unroll
            for (int p = 0; p < 2; p++)
                asm volatile("ldmatrix.sync.aligned.m8n8.x4.shared.b16 {%0,%1,%2,%3}, [%4];"
                    : "=r"(b[p][0]), "=r"(b[p][1]), "=r"(b[p][2]), "=r"(b[p][3])
                    : "r"(bBase[p] + bOff + k0 * 2));
            #pragma unroll
            for (int am = 0; am < 2; am++)
                #pragma unroll
                for (int an = 0; an < 4; an++) {
                    int q = an >> 1, sx = (an & 1) * 2;
                    asm volatile(
                        "mma.sync.aligned.m16n8k16.row.col.f32.f16.f16.f32 "
                        "{%0,%1,%2,%3}, {%4,%5,%6,%7}, {%8,%9}, {%0,%1,%2,%3};"
                        : "+f"(acc[am][an][0]), "+f"(acc[am][an][1]),
                          "+f"(acc[am][an][2]), "+f"(acc[am][an][3])
                        : "r"(a[am][0]), "r"(a[am][1]), "r"(a[am][2]), "r"(a[am][3]),
                          "r"(b[q][sx]), "r"(b[q][sx + 1]));
                }
        }

        const bool doCol = (t != 0);
        const int wbase = (c0 >> 5) + wn;
        float cs[4][2] = {}, cp[4][2] = {};
        #pragma unroll
        for (int am = 0; am < 2; am++) {
            int baseRow = wm * 32 + am * 16;
            int row0 = r0 + baseRow + (lane >> 2);
            unsigned wA = bits[(size_t)row0 * NW + wbase];
            unsigned wB = bits[(size_t)(row0 + 8) * NW + wbase];
            int wi = baseRow >> 5;
            int bp0 = (baseRow & 31) + (lane >> 2);
            #pragma unroll
            for (int an = 0; an < 4; an++) {
                int pos = an * 8 + bitPos;
                float e0 = __expf(acc[am][an][0]);
                float e1 = __expf(acc[am][an][1]);
                float e2 = __expf(acc[am][an][2]);
                float e3 = __expf(acc[am][an][3]);
                rs[am * 2 + 0] += e0 + e1;
                rs[am * 2 + 1] += e2 + e3;
                if ((wA >> pos) & 1u)       rp[am * 2 + 0] += e0;
                if ((wA >> (pos + 1)) & 1u) rp[am * 2 + 0] += e1;
                if ((wB >> pos) & 1u)       rp[am * 2 + 1] += e2;
                if ((wB >> (pos + 1)) & 1u) rp[am * 2 + 1] += e3;
                if (doCol) {
                    int colLoc = wn * 32 + an * 8 + (lane & 3) * 2;
                    unsigned w0 = bitsS[pbuf * 512 + colLoc * 4 + wi];
                    unsigned w1 = bitsS[pbuf * 512 + (colLoc + 1) * 4 + wi];
                    cs[an][0] += e0 + e2;
                    cs[an][1] += e1 + e3;
                    if ((w0 >> bp0) & 1u)       cp[an][0] += e0;
                    if ((w0 >> (bp0 + 8)) & 1u) cp[an][0] += e2;
                    if ((w1 >> bp0) & 1u)       cp[an][1] += e1;
                    if ((w1 >> (bp0 + 8)) & 1u) cp[an][1] += e3;
                }
            }
        }
        if (doCol) {
            #pragma unroll
            for (int an = 0; an < 4; an++) {
                #pragma unroll
                for (int jj = 0; jj < 2; jj++) {
                    float v = cs[an][jj], p = cp[an][jj];
                    v += __shfl_xor_sync(0xffffffffu, v, 4);
                    v += __shfl_xor_sync(0xffffffffu, v, 8);
                    v += __shfl_xor_sync(0xffffffffu, v, 16);
                    p += __shfl_xor_sync(0xffffffffu, p, 4);
                    p += __shfl_xor_sync(0xffffffffu, p, 8);
                    p += __shfl_xor_sync(0xffffffffu, p, 16);
                    if (lane < 4) {
                        int col = c0 + wn * 32 + an * 8 + lane * 2 + jj;
                        atomicAdd(&sumG[col], v);
                        atomicAdd(&posG[col], p);
                    }
                }
            }
        }
        pbuf ^= 1;
    }

    #pragma unroll
    for (int q = 0; q < 4; q++) {
        float v = rs[q], p = rp[q];
        v += __shfl_xor_sync(0xffffffffu, v, 1);
        v += __shfl_xor_sync(0xffffffffu, v, 2);
        p += __shfl_xor_sync(0xffffffffu, p, 1);
        p += __shfl_xor_sync(0xffffffffu, p, 2);
        if ((lane & 3) == 0) {
            int row = r0 + wm * 32 + (q >> 1) * 16 + (q & 1) * 8 + (lane >> 2);
            atomicAdd(&sumG[row], v);
            atomicAdd(&posG[row], p);
        }
    }
}

// ---------------- fp16 dim-label loss: refl = exp(Zfh @ CnH^T), mask = fbits ----------------
__global__ __launch_bounds__(512)
void k_loss_dim_h(const __half* __restrict__ Zh, const __half* __restrict__ CnH,
                  const unsigned* __restrict__ fbits,
                  float* __restrict__ sumG, float* __restrict__ posG) {
    const int r0 = blockIdx.x * 128;
    const int c0 = blockIdx.y * 128;

    extern __shared__ __half sh[];
    __half* As = sh;                 // [128][LDH]
    __half* Bs = sh + 128 * LDH;     // [128][LDH]

    const int tid = threadIdx.x;
    const int lane = tid & 31, warp = tid >> 5;
    const int wm = warp >> 2, wn = warp & 3;

    for (int t = tid; t < 4096; t += 512) {
        int row = t >> 5, c8 = (t & 31) * 8;
        *(float4*)&As[row * LDH + c8] =
            *(const float4*)&Zh[(size_t)(r0 + row) * Dout + c8];
        *(float4*)&Bs[row * LDH + c8] =
            *(const float4*)&CnH[(size_t)(c0 + row) * Dout + c8];
    }
    __syncthreads();

    const int mat = lane >> 3, r = lane & 7;
    unsigned int aBase[2], bBase[2];
    #pragma unroll
    for (int am = 0; am < 2; am++) {
        int row = wm * 32 + am * 16 + (mat & 1) * 8 + r;
        aBase[am] = saddr(&As[row * LDH + (mat >> 1) * 8]);
    }
    #pragma unroll
    for (int p = 0; p < 2; p++) {
        int row = wn * 32 + p * 16 + (mat >> 1) * 8 + r;
        bBase[p] = saddr(&Bs[row * LDH + (mat & 1) * 8]);
    }

    float acc[2][4][4] = {};
    #pragma unroll
    for (int k0 = 0; k0 < Dout; k0 += 16) {
        unsigned int a[2][4], b[2][4];
        #pragma unroll
        for (int am = 0; am < 2; am++)
            asm volatile("ldmatrix.sync.aligned.m8n8.x4.shared.b16 {%0,%1,%2,%3}, [%4];"
                : "=r"(a[am][0]), "=r"(a[am][1]), "=r"(a[am][2]), "=r"(a[am][3])
                : "r"(aBase[am] + k0 * 2));
        #pragma unroll
        for (int p = 0; p < 2; p++)
            asm volatile("ldmatrix.sync.aligned.m8n8.x4.shared.b16 {%0,%1,%2,%3}, [%4];"
                : "=r"(b[p][0]), "=r"(b[p][1]), "=r"(b[p][2]), "=r"(b[p][3])
                : "r"(bBase[p] + k0 * 2));
        #pragma unroll
        for (int am = 0; am < 2; am++)
            #pragma unroll
            for (int an = 0; an < 4; an++) {
                int q = an >> 1, sx = (an & 1) * 2;
                asm volatile(
                    "mma.sync.aligned.m16n8k16.row.col.f32.f16.f16.f32 "
                    "{%0,%1,%2,%3}, {%4,%5,%6,%7}, {%8,%9}, {%0,%1,%2,%3};"
                    : "+f"(acc[am][an][0]), "+f"(acc[am][an][1]),
                      "+f"(acc[am][an][2]), "+f"(acc[am][an][3])
                    : "r"(a[am][0]), "r"(a[am][1]), "r"(a[am][2]), "r"(a[am][3]),
                      "r"(b[q][sx]), "r"(b[q][sx + 1]));
            }
    }

    float rs[4] = {}, rp[4] = {};
    const int bitPos = (lane & 3) * 2;
    const int wbase = (c0 >> 5) + wn;      // word index within fbits row
    #pragma unroll
    for (int am = 0; am < 2; am++) {
        int baseRow = wm * 32 + am * 16;
        int row0 = r0 + baseRow + (lane >> 2);
        unsigned wA = fbits[(size_t)row0 * NWF + wbase];
        unsigned wB = fbits[(size_t)(row0 + 8) * NWF + wbase];
        #pragma unroll
        for (int an = 0; an < 4; an++) {
            int pos = an * 8 + bitPos;
            float e0 = __expf(acc[am][an][0]);
            float e1 = __expf(acc[am][an][1]);
            float e2 = __expf(acc[am][an][2]);
            float e3 = __expf(acc[am][an][3]);
            rs[am * 2 + 0] += e0 + e1;
            rs[am * 2 + 1] += e2 + e3;
            if ((wA >> pos) & 1u)       rp[am * 2 + 0] += e0;
            if ((wA >> (pos + 1)) & 1u) rp[am * 2 + 0] += e1;
            if ((wB >> pos) & 1u)       rp[am * 2 + 1] += e2;
            if ((wB >> (pos + 1)) & 1u) rp[am * 2 + 1] += e3;
        }
    }
    #pragma unroll
    for (int q = 0; q < 4; q++) {
        float v = rs[q], p = rp[q];
        v += __shfl_xor_sync(0xffffffffu, v, 1);
        v += __shfl_xor_sync(0xffffffffu, v, 2);
        p += __shfl_xor_sync(0xffffffffu, p, 1);
        p += __shfl_xor_sync(0xffffffffu, p, 2);
        if ((lane & 3) == 0) {
            int row = r0 + wm * 32 + (q >> 1) * 16 + (q & 1) * 8 + (lane >> 2);
            atomicAdd(&sumG[row], v);
            atomicAdd(&posG[row], p);
        }
    }
}

__global__ void k_rowloss(const float* __restrict__ sumG, const float* __restrict__ posG,
                          float* loss, int mode) {
    __shared__ float red[256];
    int t = blockIdx.x * 256 + threadIdx.x;
    float term = 0.f;
    if (t < Nn) {
        float pos = posG[t], tot = sumG[t];
        float neg = tot - pos;
        if (mode == 0) term = -logf((pos + 1e-10f) / (neg + 1e-10f));
        else           term = -logf((pos + 1e-10f) / neg + 1e-5f);
    }
    red[threadIdx.x] = term;
    __syncthreads();
    for (int s = 128; s; s >>= 1) {
        if (threadIdx.x < s) red[threadIdx.x] += red[threadIdx.x + s];
        __syncthreads();
    }
    if (threadIdx.x == 0) atomicAdd(loss, red[0]);
}

// ---------------- attention fuse + norms + centers ----------------
__global__ void k_attention(const float* __restrict__ Wp1, const float* __restrict__ bp1,
                            const float* __restrict__ wp2) {
    int nid = blockIdx.x * 256 + threadIdx.x;
    if (nid >= Nn) return;
    const float* hx = g_Hx + (size_t)nid * Dout;
    const float* ha = g_Hadj + (size_t)nid * Dout;
    float accx[AH], acca[AH];
    #pragma unroll
    for (int h = 0; h < AH; h++) { accx[h] = bp1[h]; acca[h] = bp1[h]; }
    for (int d = 0; d < Dout; d++) {
        float vx = hx[d], va = ha[d];
        #pragma unroll
        for (int h = 0; h < AH; h++) {
            float w = Wp1[d * AH + h];
            accx[h] += vx * w; acca[h] += va * w;
        }
    }
    float wx = 0.f, wa = 0.f;
    #pragma unroll
    for (int h = 0; h < AH; h++) {
        wx += tanhf(accx[h]) * wp2[h];
        wa += tanhf(acca[h]) * wp2[h];
    }
    float m = fmaxf(wx, wa);
    float ex = __expf(wx - m), ea = __expf(wa - m);
    float inv = 1.f / (ex + ea);
    float bx = ex * inv, ba = ea * inv;
    float* out = g_Hf + (size_t)nid * Dout;
    for (int d = 0; d < Dout; d++) out[d] = bx * hx[d] + ba * ha[d];
}

__global__ void k_l2norm(const float* __restrict__ in, __half* __restrict__ outH,
                         int rows, int cols) {
    int w = (blockIdx.x * blockDim.x + threadIdx.x) >> 5;
    int lane = threadIdx.x & 31;
    if (w >= rows) return;
    const float* r = in + (size_t)w * cols;
    float ss = 0.f;
    for (int c = lane; c < cols; c += 32) { float v = r[c]; ss += v * v; }
    for (int o = 16; o; o >>= 1) ss += __shfl_xor_sync(0xffffffffu, ss, o);
    float inv = 1.f / fmaxf(sqrtf(ss), 1e-12f);
    __half* wh = outH + (size_t)w * cols;
    for (int c = lane; c < cols; c += 32)
        wh[c] = __float2half(r[c] * inv);
}

__global__ void k_colsum(const float* __restrict__ feat) {
    int c = blockIdx.x * 256 + threadIdx.x;
    int rbeg = blockIdx.y * 128;
    float s = 0.f;
    for (int i = rbeg; i < rbeg + 128; i++) s += feat[(size_t)i * Din + c];
    atomicAdd(&g_colsum[c], s);
}

__global__ void k_center() {
    int w = (blockIdx.x * blockDim.x + threadIdx.x) >> 5;
    int lane = threadIdx.x & 31;
    if (w >= Din) return;
    float s = g_colsum[w] + 1e-5f;
    float inv_s = 1.f / s;
    float v[8]; float ss = 0.f;
    #pragma unroll
    for (int i = 0; i < 8; i++) {
        v[i] = g_dcraw[(size_t)w * Dout + lane + 32 * i] * inv_s;
        ss += v[i] * v[i];
    }
    for (int o = 16; o; o >>= 1) ss += __shfl_xor_sync(0xffffffffu, ss, o);
    float inv = 1.f / fmaxf(sqrtf(ss), 1e-12f);
    #pragma unroll
    for (int i = 0; i < 8; i++) g_Cn[(size_t)w * Dout + lane + 32 * i] = v[i] * inv;
}

__global__ void k_final(float* out) {
    out[0] = (0.5f * (g_loss[0] + g_loss[1]) + 0.1f * g_loss[2] + g_loss[3]) * (1.0f / Nn);
}

// ---------------- host ----------------
extern "C" void kernel_launch(void* const* d_in, const int* in_sizes, int n_in,
                              void* d_out, int out_size) {
    const float* feat = (const float*)d_in[0];
    const float* adjL = (const float*)d_in[1];
    const float* adjX = (const float*)d_in[2];
    const float* adjR = (const float*)d_in[3];

    const int *eA, *eX; int pb;
    if (in_sizes[5] == 262144) { eA = (const int*)d_in[4]; eX = (const int*)d_in[5]; pb = 6; }
    else                       { pb = 4; eA = (const int*)d_in[15]; eX = (const int*)d_in[16]; }

    const float* W0a = (const float*)d_in[pb + 0];
    const float* b0a = (const float*)d_in[pb + 1];
    const float* W1a = (const float*)d_in[pb + 2];
    const float* b1a = (const float*)d_in[pb + 3];
    const float* W0x = (const float*)d_in[pb + 4];
    const float* b0x = (const float*)d_in[pb + 5];
    const float* W1x = (const float*)d_in[pb + 6];
    const float* b1x = (const float*)d_in[pb + 7];
    const float* Wp1 = (const float*)d_in[pb + 8];
    const float* bp1 = (const float*)d_in[pb + 9];
    const float* wp2 = (const float*)d_in[pb + 10];

    const int LOSS_SMEM = 3 * 128 * LDH * (int)sizeof(__half) + 4096;  // 206848
    const int LDIM_SMEM = 2 * 128 * LDH * (int)sizeof(__half);         // 135168
    const int GEMM_SMEM = 4 * 128 * LDK * (int)sizeof(__half);

    static int inited = 0;
    static cudaStream_t s1, s2, s3;
    static cudaEvent_t eStart, eConv, ePrep, ePrepX, eMset, ePack, eZero, eF2h, eFT,
                       eHadj, eZxh, eZf, eL1, eL2, eL3;
    if (!inited) {
        cudaFuncSetAttribute(k_loss_sym, cudaFuncAttributeMaxDynamicSharedMemorySize, LOSS_SMEM);
        cudaFuncSetAttribute(k_loss_dim_h, cudaFuncAttributeMaxDynamicSharedMemorySize, LDIM_SMEM);
        cudaFuncSetAttribute(k_gemm_h, cudaFuncAttributeMaxDynamicSharedMemorySize, GEMM_SMEM);
        cudaFuncSetAttribute(k_gemm_atb_h, cudaFuncAttributeMaxDynamicSharedMemorySize, GEMM_SMEM);
        cudaStreamCreateWithFlags(&s1, cudaStreamNonBlocking);
        cudaStreamCreateWithFlags(&s2, cudaStreamNonBlocking);
        cudaStreamCreateWithFlags(&s3, cudaStreamNonBlocking);
        cudaEventCreateWithFlags(&eStart, cudaEventDisableTiming);
        cudaEventCreateWithFlags(&eConv,  cudaEventDisableTiming);
        cudaEventCreateWithFlags(&ePrep,  cudaEventDisableTiming);
        cudaEventCreateWithFlags(&ePrepX, cudaEventDisableTiming);
        cudaEventCreateWithFlags(&eMset,  cudaEventDisableTiming);
        cudaEventCreateWithFlags(&ePack,  cudaEventDisableTiming);
        cudaEventCreateWithFlags(&eZero,  cudaEventDisableTiming);
        cudaEventCreateWithFlags(&eF2h,   cudaEventDisableTiming);
        cudaEventCreateWithFlags(&eFT,    cudaEventDisableTiming);
        cudaEventCreateWithFlags(&eHadj,  cudaEventDisableTiming);
        cudaEventCreateWithFlags(&eZxh,   cudaEventDisableTiming);
        cudaEventCreateWithFlags(&eZf,    cudaEventDisableTiming);
        cudaEventCreateWithFlags(&eL1,    cudaEventDisableTiming);
        cudaEventCreateWithFlags(&eL2,    cudaEventDisableTiming);
        cudaEventCreateWithFlags(&eL3,    cudaEventDisableTiming);
        inited = 1;
    }

    void *pY, *pY2, *pHadj, *pHx, *pHf, *pFH, *pFT, *pHfT, *pH1h, *pH1h2;
    void *pZah, *pZxh, *pZfh, *pCnH, *pWt;
    void *pDeg, *pNrm, *pOff, *pCur, *pEidx, *pBits, *pFbits;
    void *pDc, *pCn, *pCs, *pSum, *pPos, *pLoss;
    cudaGetSymbolAddress(&pY, g_Y);       cudaGetSymbolAddress(&pY2, g_Y2);
    cudaGetSymbolAddress(&pHadj, g_Hadj); cudaGetSymbolAddress(&pHx, g_Hx);
    cudaGetSymbolAddress(&pHf, g_Hf);
    cudaGetSymbolAddress(&pFH, g_featH);  cudaGetSymbolAddress(&pFT, g_featTh);
    cudaGetSymbolAddress(&pHfT, g_HfTh);
    cudaGetSymbolAddress(&pH1h, g_H1h);   cudaGetSymbolAddress(&pH1h2, g_H1h2);
    cudaGetSymbolAddress(&pZah, g_Zah);   cudaGetSymbolAddress(&pZxh, g_Zxh);
    cudaGetSymbolAddress(&pZfh, g_Zfh);   cudaGetSymbolAddress(&pCnH, g_CnH);
    cudaGetSymbolAddress(&pWt, g_Wt);
    cudaGetSymbolAddress(&pDeg, g_deg);   cudaGetSymbolAddress(&pNrm, g_nrm);
    cudaGetSymbolAddress(&pOff, g_off);   cudaGetSymbolAddress(&pCur, g_cursor);
    cudaGetSymbolAddress(&pEidx, g_eidx); cudaGetSymbolAddress(&pBits, g_bits);
    cudaGetSymbolAddress(&pFbits, g_fbits);
    cudaGetSymbolAddress(&pDc, g_dcraw);  cudaGetSymbolAddress(&pCn, g_Cn);
    cudaGetSymbolAddress(&pCs, g_colsum); cudaGetSymbolAddress(&pSum, g_sum);
    cudaGetSymbolAddress(&pPos, g_pos);   cudaGetSymbolAddress(&pLoss, g_loss);

    float* deg = (float*)pDeg;
    float* nrm = (float*)pNrm;
    float* nsA = nrm;           float* ndA = nrm + Nn;
    float* nsX = nrm + 2 * Nn;  float* ndX = nrm + 3 * Nn;
    int* offA = (int*)pOff;     int* offX = offA + (Nn + 1);
    int* eidxA = (int*)pEidx;   int* eidxX = eidxA + Ne;
    unsigned* bitsL = (unsigned*)pBits;
    unsigned* bitsX = bitsL + (size_t)Nn * NW;
    unsigned* bitsR = bitsX + (size_t)Nn * NW;
    unsigned* fbits = (unsigned*)pFbits;
    __half* featH = (__half*)pFH;
    __half* featTh = (__half*)pFT;
    __half* HfTh = (__half*)pHfT;
    __half* H1h = (__half*)pH1h;
    __half* H1h2 = (__half*)pH1h2;
    __half* CnH = (__half*)pCnH;
    __half* W0aT = (__half*)pWt;
    __half* W1aT = W0aT + Din * Din;
    __half* W0xT = W1aT + Din * Dout;
    __half* W1xT = W0xT + Din * Din;
    float* sum = (float*)pSum;  float* pos = (float*)pPos;
    float* loss = (float*)pLoss;
    const int packBlocks = (Nn * NW) / 64;
    const int packBlocksF = (Nn * NWF) / 64;

    // ---- fork ----
    cudaEventRecord(eStart, 0);
    cudaStreamWaitEvent(s1, eStart, 0);
    cudaStreamWaitEvent(s2, eStart, 0);
    cudaStreamWaitEvent(s3, eStart, 0);

    // ---- s2: zeroing + colsum + packs + featT transpose ----
    cudaMemsetAsync(pCs, 0, Din * sizeof(float), s2);
    cudaMemsetAsync(pDc, 0, (size_t)Din * Dout * sizeof(float), s2);
    cudaMemsetAsync(pSum, 0, 4 * Nn * sizeof(float), s2);
    cudaMemsetAsync(pPos, 0, 4 * Nn * sizeof(float), s2);
    cudaMemsetAsync(pLoss, 0, 4 * sizeof(float), s2);
    k_colsum<<<dim3(2, 64), 256, 0, s2>>>(feat);
    cudaEventRecord(eZero, s2);
    k_pack<<<packBlocks, 256, 0, s2>>>(adjL, bitsL);
    k_pack<<<packBlocks, 256, 0, s2>>>(adjX, bitsX);
    k_pack<<<packBlocks, 256, 0, s2>>>(adjR, bitsR);
    k_packp<<<packBlocksF, 256, 0, s2>>>(feat, fbits);
    cudaEventRecord(ePack, s2);

    // ---- s1: conversions + branch A start ----
    k_f2h<<<(Nn * Din / 4 + 255) / 256, 256, 0, s1>>>(feat, featH, Nn * Din / 4);
    cudaEventRecord(eF2h, s1);
    k_wth<<<(Din * Din + 255) / 256, 256, 0, s1>>>(W0a, W0aT, Din, Din);
    k_wth<<<(Din * Dout + 255) / 256, 256, 0, s1>>>(W1a, W1aT, Din, Dout);
    k_wth<<<(Din * Din + 255) / 256, 256, 0, s1>>>(W0x, W0xT, Din, Din);
    k_wth<<<(Din * Dout + 255) / 256, 256, 0, s1>>>(W1x, W1xT, Din, Dout);
    cudaEventRecord(eConv, s1);
    k_gemm_h<<<dim3(Nn / 128, Din / 128), 256, GEMM_SMEM, s1>>>(featH, W0aT, (float*)pY, Din, Din);

    // s2 continues: transpose featH (needs eF2h)
    cudaStreamWaitEvent(s2, eF2h, 0);
    k_tr_h<<<dim3(Din / 32, Nn / 32), dim3(32, 8), 0, s2>>>(featH, featTh, Nn, Din);
    cudaEventRecord(eFT, s2);

    // ---- s0: A-graph prep ----
    cudaMemsetAsync(pDeg, 0, 4 * Nn * sizeof(float), 0);
    cudaMemsetAsync(pCur, 0, 2 * Nn * sizeof(int), 0);
    cudaEventRecord(eMset, 0);
    k_degree<<<(Ne + 255) / 256, 256>>>(eA, eA + Ne, deg, deg + Nn);
    k_norm<<<(2 * Nn) / 256, 256>>>(0, 2 * Nn);
    k_scan<<<1, 1024>>>(deg + Nn, offA);
    k_bucket<<<(Ne + 255) / 256, 256>>>(eA, eA + Ne, offA, (int*)pCur, eidxA);
    cudaEventRecord(ePrep, 0);

    // ---- s3: X-graph prep (parallel) ----
    cudaStreamWaitEvent(s3, eMset, 0);
    k_degree<<<(Ne + 255) / 256, 256, 0, s3>>>(eX, eX + Ne, deg + 2 * Nn, deg + 3 * Nn);
    k_norm<<<(2 * Nn) / 256, 256, 0, s3>>>(2 * Nn, 2 * Nn);
    k_scan<<<1, 1024, 0, s3>>>(deg + 3 * Nn, offX);
    k_bucket<<<(Ne + 255) / 256, 256, 0, s3>>>(eX, eX + Ne, offX, (int*)pCur + Nn, eidxX);
    cudaEventRecord(ePrepX, s3);

    // ---- s1: branch A finish + loss A ----
    cudaStreamWaitEvent(s1, ePrep, 0);
    k_gather_h<<<Nn, Din / 4, 0, s1>>>(offA, eidxA, (float*)pY, nsA, ndA, b0a, H1h, Din / 4);
    k_gemm_h<<<dim3(Nn / 128, Dout / 128), 256, GEMM_SMEM, s1>>>(H1h, W1aT, (float*)pY, Dout, Din);
    k_gather<<<Nn, Dout / 4, 0, s1>>>(offA, eidxA, (float*)pY, nsA, ndA, b1a, (float*)pHadj, Dout / 4);
    cudaEventRecord(eHadj, s1);
    k_l2norm<<<Nn / 8, 256, 0, s1>>>((float*)pHadj, (__half*)pZah, Nn, Dout);
    cudaStreamWaitEvent(s1, ePack, 0);
    k_loss_sym<<<dim3(64, 2), 512, LOSS_SMEM, s1>>>((const __half*)pZah, bitsL, sum, pos);
    k_rowloss<<<Nn / 256, 256, 0, s1>>>(sum, pos, loss + 0, 0);
    cudaEventRecord(eL1, s1);

    // ---- s0: branch X ----
    cudaStreamWaitEvent(0, eConv, 0);
    cudaStreamWaitEvent(0, ePrepX, 0);
    k_gemm_h<<<dim3(Nn / 128, Din / 128), 256, GEMM_SMEM>>>(featH, W0xT, (float*)pY2, Din, Din);
    k_gather_h<<<Nn, Din / 4>>>(offX, eidxX, (float*)pY2, nsX, ndX, b0x, H1h2, Din / 4);
    k_gemm_h<<<dim3(Nn / 128, Dout / 128), 256, GEMM_SMEM>>>(H1h2, W1xT, (float*)pY2, Dout, Din);
    k_gather<<<Nn, Dout / 4>>>(offX, eidxX, (float*)pY2, nsX, ndX, b1x, (float*)pHx, Dout / 4);
    k_l2norm<<<Nn / 8, 256>>>((float*)pHx, (__half*)pZxh, Nn, Dout);
    cudaEventRecord(eZxh, 0);

    // ---- s3: loss X ----
    cudaStreamWaitEvent(s3, eZxh, 0);
    cudaStreamWaitEvent(s3, ePack, 0);
    k_loss_sym<<<dim3(64, 2), 512, LOSS_SMEM, s3>>>((const __half*)pZxh, bitsX, sum + Nn, pos + Nn);
    k_rowloss<<<Nn / 256, 256, 0, s3>>>(sum + Nn, pos + Nn, loss + 1, 0);
    cudaEventRecord(eL2, s3);

    // ---- s0: attention + fused embedding ----
    cudaStreamWaitEvent(0, eHadj, 0);
    k_attention<<<Nn / 256, 256>>>(Wp1, bp1, wp2);
    k_l2norm<<<Nn / 8, 256>>>((float*)pHf, (__half*)pZfh, Nn, Dout);
    cudaEventRecord(eZf, 0);

    // ---- s2: loss R ----
    cudaStreamWaitEvent(s2, eZf, 0);
    k_loss_sym<<<dim3(64, 2), 512, LOSS_SMEM, s2>>>((const __half*)pZfh, bitsR, sum + 3 * Nn, pos + 3 * Nn);
    k_rowloss<<<Nn / 256, 256, 0, s2>>>(sum + 3 * Nn, pos + 3 * Nn, loss + 3, 0);
    cudaEventRecord(eL3, s2);

    // ---- s0: dim_center (fp16 path) + dim loss ----
    cudaStreamWaitEvent(0, eZero, 0);
    cudaStreamWaitEvent(0, eFT, 0);
    k_trf_h<<<dim3(Dout / 32, Nn / 32), dim3(32, 8)>>>((float*)pHf, HfTh, Nn, Dout);
    k_gemm_atb_h<<<dim3(Din / 128, Dout / 128, 16), 256, GEMM_SMEM>>>(
        featTh, HfTh, (float*)pDc, Dout, Nn, Nn / 16);
    k_center<<<Din / 8, 256>>>();
    k_f2h<<<(Din * Dout / 4 + 255) / 256, 256>>>((float*)pCn, CnH, Din * Dout / 4);
    cudaStreamWaitEvent(0, ePack, 0);
    k_loss_dim_h<<<dim3(Nn / 128, Din / 128), 512, LDIM_SMEM>>>(
        (const __half*)pZfh, CnH, fbits, sum + 2 * Nn, pos + 2 * Nn);
    k_rowloss<<<Nn / 256, 256>>>(sum + 2 * Nn, pos + 2 * Nn, loss + 2, 1);

    // ---- join + final ----
    cudaStreamWaitEvent(0, eL1, 0);
    cudaStreamWaitEvent(0, eL2, 0);
    cudaStreamWaitEvent(0, eL3, 0);
    k_final<<<1, 1>>>((float*)d_out);
}